// round 11
// baseline (speedup 1.0000x reference)
#include <cuda_runtime.h>
#include <math.h>
#include <stdint.h>

#define BSZ 2
#define TT 1024
#define DM 1024
#define DI 2048
#define DS 128
#define NH 32
#define HDS 64
#define NHA 16
#define HDA 64
#define FFND 4096
#define ZXB 4384
#define XBCD 2304
#define QKVD 1152
#define BT (BSZ*TT)

// ---------------- scratch (device globals; no allocations allowed) ----------------
__device__ float g_h[BT*DM];
__device__ float g_zxb[BT*ZXB];
__device__ float g_xBC[BT*XBCD];
__device__ float g_dt[BT*NH];
__device__ float g_dA[BT*NH];
__device__ float g_yp[2*BT*DI];
__device__ float g_y2[BT*DI];
__device__ float g_x2[BT*DM];
__device__ float g_qkv[BT*QKVD];
__device__ float g_qc[BT*DM];
__device__ float g_kc[BT*HDA];
__device__ float g_vc[BT*HDA];
__device__ float g_att[BT*DM];
__device__ float g_x3[BT*DM];
__device__ float g_xk[BT*DM];
__device__ float g_xr[BT*DM];
__device__ float g_kf[BT*FFND];
__device__ float g_kv[BT*DM];
__device__ float g_wt[18251776];   // tf32-rounded TRANSPOSED weights [N][K] (73MB)

// weight offsets in g_wt
#define OW_IN    0
#define OW_OUT   4489216
#define OW_QKV   6586368
#define OW_CPROJ 7766016
#define OW_KEY   8814592
#define OW_VAL   13008896
#define OW_REC   17203200

// ---------------- helpers ----------------
__device__ __forceinline__ uint32_t f2tf32(float x) {
    uint32_t r; asm("cvt.rna.tf32.f32 %0, %1;" : "=r"(r) : "f"(x)); return r;
}
__device__ __forceinline__ float tf32r(float x) { return __uint_as_float(f2tf32(x)); }

__device__ __forceinline__ float block_sum(float v) {
    __shared__ float red[32];
    int lane = threadIdx.x & 31, w = threadIdx.x >> 5;
    #pragma unroll
    for (int o = 16; o; o >>= 1) v += __shfl_xor_sync(0xffffffffu, v, o);
    if (lane == 0) red[w] = v;
    __syncthreads();
    int nw = blockDim.x >> 5;
    float r = (threadIdx.x < nw) ? red[threadIdx.x] : 0.f;
    if (w == 0) {
        #pragma unroll
        for (int o = 16; o; o >>= 1) r += __shfl_xor_sync(0xffffffffu, r, o);
        if (lane == 0) red[0] = r;
    }
    __syncthreads();
    return red[0];
}

__global__ void rmsnorm_k(const float* __restrict__ x, float* __restrict__ o, float eps, int rnd) {
    int row = blockIdx.x;
    const float* xr = x + (size_t)row * DM;
    float ss = 0.f;
    for (int c = threadIdx.x; c < DM; c += blockDim.x) { float v = xr[c]; ss = fmaf(v, v, ss); }
    ss = block_sum(ss);
    float sc = rsqrtf(ss / (float)DM + eps);
    float* orow = o + (size_t)row * DM;
    if (rnd) for (int c = threadIdx.x; c < DM; c += blockDim.x) orow[c] = tf32r(xr[c] * sc);
    else     for (int c = threadIdx.x; c < DM; c += blockDim.x) orow[c] = xr[c] * sc;
}

// ---------------- fused rmsnorm + token-shift (channel mix) ----------------
__global__ void rmsshift_k(const float* __restrict__ x3,
                           const float* __restrict__ tmk, const float* __restrict__ tmr,
                           float* __restrict__ xk, float* __restrict__ xr) {
    int bt = blockIdx.x; int t = bt & 1023;
    const float* cur = x3 + (size_t)bt * DM;
    const float* prv = x3 + (size_t)(bt - 1) * DM;
    float sa = 0.f, sb = 0.f;
    for (int c = threadIdx.x; c < DM; c += blockDim.x) {
        float v = cur[c]; sa = fmaf(v, v, sa);
        float p = t ? prv[c] : 0.f; sb = fmaf(p, p, sb);
    }
    float ra = block_sum(sa);
    __syncthreads();
    float rb = block_sum(sb);
    float scc = rsqrtf(ra / (float)DM + 1e-6f);
    float scp = rsqrtf(rb / (float)DM + 1e-6f);
    for (int c = threadIdx.x; c < DM; c += blockDim.x) {
        float h = cur[c] * scc;
        float hp = t ? prv[c] * scp : 0.f;
        float dd = hp - h;
        xk[(size_t)bt * DM + c] = tf32r(fmaf(dd, tmk[c], h));
        xr[(size_t)bt * DM + c] = tf32r(fmaf(dd, tmr[c], h));
    }
}

// ---------------- merged weight tf32 round + transpose (all 7 weights, one launch) ----
struct WTab {
    const float* src[7];
    int off[7];
    int K[7], N[7];
    int tstart[8];
};
__global__ void cvtall_k(WTab wt) {
    __shared__ float t[32][33];
    int bidx = blockIdx.x;
    int w = 0;
    #pragma unroll
    for (int i = 1; i < 7; i++) if (bidx >= wt.tstart[i]) w = i;
    int tloc = bidx - wt.tstart[w];
    int K = wt.K[w], N = wt.N[w];
    int ntn = N >> 5;
    int k0 = (tloc / ntn) << 5, n0 = (tloc % ntn) << 5;
    const float* in = wt.src[w];
    float* out = g_wt + wt.off[w];
    int x = threadIdx.x, y = threadIdx.y;
    #pragma unroll
    for (int i = 0; i < 32; i += 8)
        t[y + i][x] = tf32r(in[(size_t)(k0 + y + i) * N + n0 + x]);
    __syncthreads();
    #pragma unroll
    for (int i = 0; i < 32; i += 8)
        out[(size_t)(n0 + y + i) * K + k0 + x] = t[x][y + i];
}

// ================= tf32 mma.sync GEMM (ldmatrix, 3-stage pipeline, templated BM) =====
#define CP_ASYNC16(dst, src, sz) \
    asm volatile("cp.async.cg.shared.global [%0], [%1], 16, %2;" :: "r"(dst), "l"(src), "r"(sz) : "memory")
#define CP_COMMIT() asm volatile("cp.async.commit_group;" ::: "memory")
#define CP_WAIT1()  asm volatile("cp.async.wait_group 1;" ::: "memory")
#define MMA_TF32(d, a, b) \
    asm volatile("mma.sync.aligned.m16n8k8.row.col.f32.tf32.tf32.f32 " \
        "{%0,%1,%2,%3}, {%4,%5,%6,%7}, {%8,%9}, {%0,%1,%2,%3};" \
        : "+f"((d)[0]), "+f"((d)[1]), "+f"((d)[2]), "+f"((d)[3]) \
        : "r"((a)[0]), "r"((a)[1]), "r"((a)[2]), "r"((a)[3]), "r"((b)[0]), "r"((b)[1]))
#define LDMX4(r0, r1, r2, r3, a) \
    asm volatile("ldmatrix.sync.aligned.m8n8.x4.shared.b16 {%0,%1,%2,%3}, [%4];" \
        : "=r"(r0), "=r"(r1), "=r"(r2), "=r"(r3) : "r"(a))

// C[M,N] = A[M,K] @ Bt[N,K]^T (+fused epilogue). A,Bt pre-rounded to tf32.
template<int BM>
__global__ void __launch_bounds__(256, 2) gemm_tc(const float* __restrict__ A, const float* __restrict__ Bt,
                                                  float* __restrict__ C, int M, int N, int K,
                                                  const float* __restrict__ res, const float* __restrict__ mul, int epi)
{
    constexpr int MI = BM / 32;            // per-warp m-tiles of 16 (2 or 4)
    extern __shared__ float gs[];
    float (*As)[36] = (float(*)[36])gs;                // [3*BM][36]
    float (*Bs)[36] = (float(*)[36])(gs + 3*BM*36);    // [3*128][36] (n-major)
    int tid = threadIdx.x;
    int m0 = blockIdx.y * BM, n0 = blockIdx.x * 128;
    int w = tid >> 5, lane = tid & 31;
    int wm = (w >> 2) * (BM / 2);
    int wn = (w & 3) * 32;

    float acc[MI][4][4];
    #pragma unroll
    for (int mi = 0; mi < MI; mi++)
        #pragma unroll
        for (int ni = 0; ni < 4; ni++)
            #pragma unroll
            for (int e = 0; e < 4; e++) acc[mi][ni][e] = 0.f;

    const int NC = K >> 5;

    auto fill = [&](int buf, int k0) {
        #pragma unroll
        for (int i = 0; i < BM / 32; i++) {
            int task = tid + i * 256;
            int r = task >> 3, q = (task & 7) * 4;
            const float* src = A + (size_t)(m0 + r) * K + k0 + q;
            uint32_t dst = (uint32_t)__cvta_generic_to_shared(&As[buf * BM + r][q]);
            CP_ASYNC16(dst, src, 16);
        }
        #pragma unroll
        for (int i = 0; i < 4; i++) {
            int task = tid + i * 256;
            int r = task >> 3, q = (task & 7) * 4;
            int ok = (n0 + r) < N;
            const float* src = Bt + (size_t)(n0 + r) * K + k0 + q;
            uint32_t dst = (uint32_t)__cvta_generic_to_shared(&Bs[buf * 128 + r][q]);
            CP_ASYNC16(dst, src, ok ? 16 : 0);
        }
    };

    fill(0, 0);  CP_COMMIT();
    fill(1, 32); CP_COMMIT();     // all GEMMs have K >= 1024

    int g = lane >> 3, lr8 = lane & 7;
    int arow_l = wm + (g & 1) * 8 + lr8;
    int acol_l = (g >> 1) * 4;
    int brow_l = wn + (g >> 1) * 8 + lr8;
    int bcol_l = (g & 1) * 4;

    int buf = 0;
    for (int ct = 0; ct < NC; ct++) {
        CP_WAIT1();
        __syncthreads();

        const float (*as)[36] = &As[buf * BM];
        const float (*bs)[36] = &Bs[buf * 128];
        #pragma unroll
        for (int ks = 0; ks < 4; ks++) {
            int kb = ks * 8;
            uint32_t af[MI][4];
            #pragma unroll
            for (int mi = 0; mi < MI; mi++) {
                uint32_t a = (uint32_t)__cvta_generic_to_shared(&as[arow_l + mi * 16][acol_l + kb]);
                LDMX4(af[mi][0], af[mi][1], af[mi][2], af[mi][3], a);
            }
            uint32_t bf[4][2];
            #pragma unroll
            for (int p = 0; p < 2; p++) {
                uint32_t a = (uint32_t)__cvta_generic_to_shared(&bs[brow_l + p * 16][bcol_l + kb]);
                LDMX4(bf[2*p][0], bf[2*p][1], bf[2*p+1][0], bf[2*p+1][1], a);
            }
            #pragma unroll
            for (int mi = 0; mi < MI; mi++)
                #pragma unroll
                for (int ni = 0; ni < 4; ni++)
                    MMA_TF32(acc[mi][ni], af[mi], bf[ni]);
        }

        int nx = ct + 2;
        if (nx < NC) {
            int nslot = nx - (nx / 3) * 3;
            fill(nslot, nx * 32);
        }
        CP_COMMIT();
        if (++buf == 3) buf = 0;
    }

    #pragma unroll
    for (int mi = 0; mi < MI; mi++) {
        int r0 = m0 + wm + mi * 16 + (lane >> 2);
        #pragma unroll
        for (int ni = 0; ni < 4; ni++) {
            int c = n0 + wn + ni * 8 + (lane & 3) * 2;
            if (c < N) {
                #pragma unroll
                for (int half = 0; half < 2; half++) {
                    int r = r0 + half * 8;
                    size_t idx = (size_t)r * N + c;
                    float v0 = acc[mi][ni][half * 2 + 0];
                    float v1 = acc[mi][ni][half * 2 + 1];
                    if (epi == 1) {
                        v0 += res[idx]; v1 += res[idx + 1];
                    } else if (epi == 2) {
                        v0 = fmaxf(v0, 0.f); v0 = tf32r(v0 * v0);
                        v1 = fmaxf(v1, 0.f); v1 = tf32r(v1 * v1);
                    } else if (epi == 3) {
                        v0 = res[idx]     + mul[idx]     / (1.f + expf(-v0));
                        v1 = res[idx + 1] + mul[idx + 1] / (1.f + expf(-v1));
                    }
                    C[idx] = v0; C[idx + 1] = v1;
                }
            }
        }
    }
}
#define GEMM_SMEM_128 110592
#define GEMM_SMEM_64  82944

// ---------------- xBC causal depthwise conv (K=4) + silu + fused dt/dA ----------------
// 8 timesteps per CTA, register ring buffer (4x less read traffic)
#define CTB 8
__global__ void conv_silu_k(const float* __restrict__ cw, const float* __restrict__ cb,
                            const float* __restrict__ dt_bias, const float* __restrict__ A_log) {
    int blk = blockIdx.x;
    int b = blk / (TT / CTB);
    int t0 = (blk % (TT / CTB)) * CTB;
    for (int c = threadIdx.x; c < XBCD; c += blockDim.x) {
        float w0 = cw[c*4], w1 = cw[c*4+1], w2 = cw[c*4+2], w3 = cw[c*4+3], bb = cb[c];
        float xm3 = (t0 >= 3) ? g_zxb[(size_t)(b * TT + t0 - 3) * ZXB + DI + c] : 0.f;
        float xm2 = (t0 >= 2) ? g_zxb[(size_t)(b * TT + t0 - 2) * ZXB + DI + c] : 0.f;
        float xm1 = (t0 >= 1) ? g_zxb[(size_t)(b * TT + t0 - 1) * ZXB + DI + c] : 0.f;
        #pragma unroll
        for (int j = 0; j < CTB; j++) {
            float x0 = g_zxb[(size_t)(b * TT + t0 + j) * ZXB + DI + c];
            float acc = bb;
            acc = fmaf(w0, xm3, acc); acc = fmaf(w1, xm2, acc);
            acc = fmaf(w2, xm1, acc); acc = fmaf(w3, x0, acc);
            acc = acc / (1.f + expf(-acc));
            g_xBC[(size_t)(b * TT + t0 + j) * XBCD + c] = acc;
            xm3 = xm2; xm2 = xm1; xm1 = x0;
        }
    }
    // fused dt/dA: 256 threads = 8 timesteps x 32 heads
    {
        int h = threadIdx.x & 31, j = threadIdx.x >> 5;
        int bt = b * TT + t0 + j;
        float v = g_zxb[(size_t)bt * ZXB + 4352 + h] + dt_bias[h];
        float sp = (v > 20.f) ? v : log1pf(expf(v));
        g_dt[bt * NH + h] = sp;
        g_dA[bt * NH + h] = expf(sp * (-expf(A_log[h])));
    }
}

// ---------------- SSM scan ----------------
__global__ void scan_k() {
    int bid = blockIdx.x;
    int ns = bid & 1; int bh = bid >> 1; int b = bh >> 5; int h = bh & 31;
    int tid = threadIdx.x;
    int p = tid >> 3;
    int ng = tid & 7;
    __shared__ float sB[16 * 64], sC[16 * 64], sX[16 * 64], sS[16];
    float s[8];
    #pragma unroll
    for (int j = 0; j < 8; j++) s[j] = 0.f;
    int nb = ns * 64;

    for (int ct = 0; ct < TT / 16; ct++) {
        int t0 = ct * 16;
        #pragma unroll
        for (int l = 0; l < 2; l++) {
            int e = tid + l * 512; int tt = e >> 6; int n = e & 63;
            int base = b * TT + t0 + tt;
            sB[e] = g_xBC[(size_t)base * XBCD + DI + nb + n];
            sC[e] = g_xBC[(size_t)base * XBCD + DI + DS + nb + n];
            sX[e] = g_xBC[(size_t)base * XBCD + h * 64 + n] * g_dt[base * NH + h];
        }
        if (tid < 16) sS[tid] = g_dA[(b * TT + t0 + tid) * NH + h];
        __syncthreads();
        for (int tt = 0; tt < 16; tt++) {
            float da = sS[tt];
            float dtx = sX[tt * 64 + p];
            float bb[8], cc[8];
            *(float4*)&bb[0] = *(float4*)&sB[tt * 64 + ng * 8];
            *(float4*)&bb[4] = *(float4*)&sB[tt * 64 + ng * 8 + 4];
            *(float4*)&cc[0] = *(float4*)&sC[tt * 64 + ng * 8];
            *(float4*)&cc[4] = *(float4*)&sC[tt * 64 + ng * 8 + 4];
            float acc = 0.f;
            #pragma unroll
            for (int j = 0; j < 8; j++) {
                s[j] = fmaf(s[j], da, dtx * bb[j]);
                acc = fmaf(s[j], cc[j], acc);
            }
            acc += __shfl_xor_sync(0xffffffffu, acc, 1);
            acc += __shfl_xor_sync(0xffffffffu, acc, 2);
            acc += __shfl_xor_sync(0xffffffffu, acc, 4);
            if (ng == 0)
                g_yp[(size_t)ns * (BT * DI) + (size_t)(b * TT + t0 + tt) * DI + h * 64 + p] = acc;
        }
        __syncthreads();
    }
}

__global__ void gate_k(const float* __restrict__ Dm, const float* __restrict__ mnw) {
    int bt = blockIdx.x;
    float ss = 0.f;
    for (int c = threadIdx.x; c < DI; c += blockDim.x) {
        float v = g_yp[(size_t)bt * DI + c] + g_yp[(size_t)BT * DI + (size_t)bt * DI + c]
                + g_xBC[(size_t)bt * XBCD + c] * Dm[c >> 6];
        float z = g_zxb[(size_t)bt * ZXB + c];
        v *= z / (1.f + expf(-z));
        g_y2[(size_t)bt * DI + c] = v;
        ss = fmaf(v, v, ss);
    }
    ss = block_sum(ss);
    float sc = rsqrtf(ss / (float)DI + 1e-5f);
    for (int c = threadIdx.x; c < DI; c += blockDim.x)
        g_y2[(size_t)bt * DI + c] = tf32r(g_y2[(size_t)bt * DI + c] * sc * mnw[c]);
}

// ---------------- q/k/v causal depthwise conv (K=3), 8 timesteps per CTA --------------
__global__ void convqkv_k(const float* __restrict__ qw, const float* __restrict__ qb,
                          const float* __restrict__ kw, const float* __restrict__ kb,
                          const float* __restrict__ vw, const float* __restrict__ vb) {
    int blk = blockIdx.x;
    int b = blk / (TT / CTB);
    int t0 = (blk % (TT / CTB)) * CTB;
    for (int c = threadIdx.x; c < QKVD; c += blockDim.x) {
        const float* w; const float* bias; int d;
        if (c < DM)            { d = c & 63;        w = qw; bias = qb; }
        else if (c < DM + 64)  { d = c - DM;        w = kw; bias = kb; }
        else                   { d = c - DM - 64;   w = vw; bias = vb; }
        float w0 = w[d*3], w1 = w[d*3+1], w2 = w[d*3+2], bb = bias[d];
        float xm2 = (t0 >= 2) ? g_qkv[(size_t)(b * TT + t0 - 2) * QKVD + c] : 0.f;
        float xm1 = (t0 >= 1) ? g_qkv[(size_t)(b * TT + t0 - 1) * QKVD + c] : 0.f;
        #pragma unroll
        for (int j = 0; j < CTB; j++) {
            int bt = b * TT + t0 + j;
            float x0 = g_qkv[(size_t)bt * QKVD + c];
            float acc = bb;
            acc = fmaf(w0, xm2, acc); acc = fmaf(w1, xm1, acc); acc = fmaf(w2, x0, acc);
            if (c < DM)           g_qc[(size_t)bt * DM + c] = acc;
            else if (c < DM + 64) g_kc[(size_t)bt * 64 + d] = acc;
            else                  g_vc[(size_t)bt * 64 + d] = acc;
            xm2 = xm1; xm1 = x0;
        }
    }
}

// ---------------- fused causal attention (tf32 mma, online softmax) ----------------
#define ATTN_SMEM 69632
__global__ void __launch_bounds__(128) attn_k() {
    extern __shared__ float sm[];
    float* qs = sm;              // [64][68] tf32, pre-scaled
    float* ks = sm + 4352;       // [64][68] tf32
    float* vT = sm + 8704;       // [64][68] tf32 (V transposed)
    float* ps = sm + 13056;      // [64][68] tf32 (P)
    int bid = blockIdx.x;
    int qb = bid & 15; int h = (bid >> 4) & 15; int b = bid >> 8;
    int tid = threadIdx.x;
    int w = tid >> 5, lane = tid & 31;
    int lr = lane >> 2, lc = lane & 3;

    {
        int r = tid >> 1, d0 = (tid & 1) * 32;
        const float* qp = &g_qc[(size_t)(b * TT + qb * 64 + r) * DM + h * 64 + d0];
        #pragma unroll
        for (int j = 0; j < 8; j++) {
            float4 v = *(const float4*)(qp + j * 4);
            *(float4*)&qs[r * 68 + d0 + j * 4] =
                make_float4(tf32r(v.x * 0.125f), tf32r(v.y * 0.125f),
                            tf32r(v.z * 0.125f), tf32r(v.w * 0.125f));
        }
    }

    float m[2] = {-1e30f, -1e30f}, l[2] = {0.f, 0.f};
    float o[8][4];
    #pragma unroll
    for (int ni = 0; ni < 8; ni++)
        #pragma unroll
        for (int e = 0; e < 4; e++) o[ni][e] = 0.f;

    for (int kb = 0; kb <= qb; kb++) {
        __syncthreads();
        {
            int r = tid >> 1, d0 = (tid & 1) * 32;
            const float* kp = &g_kc[(size_t)(b * TT + kb * 64 + r) * 64 + d0];
            const float* vp = &g_vc[(size_t)(b * TT + kb * 64 + r) * 64 + d0];
            #pragma unroll
            for (int j = 0; j < 8; j++) {
                float4 kv = *(const float4*)(kp + j * 4);
                *(float4*)&ks[r * 68 + d0 + j * 4] =
                    make_float4(tf32r(kv.x), tf32r(kv.y), tf32r(kv.z), tf32r(kv.w));
                float4 vv = *(const float4*)(vp + j * 4);
                int d = d0 + j * 4;
                vT[(d + 0) * 68 + r] = tf32r(vv.x); vT[(d + 1) * 68 + r] = tf32r(vv.y);
                vT[(d + 2) * 68 + r] = tf32r(vv.z); vT[(d + 3) * 68 + r] = tf32r(vv.w);
            }
        }
        __syncthreads();

        float sc[8][4];
        #pragma unroll
        for (int ni = 0; ni < 8; ni++)
            #pragma unroll
            for (int e = 0; e < 4; e++) sc[ni][e] = 0.f;
        #pragma unroll
        for (int ksx = 0; ksx < 8; ksx++) {
            int k8 = ksx * 8;
            int r = w * 16 + lr;
            uint32_t af[4];
            af[0] = __float_as_uint(qs[r * 68 + k8 + lc]);
            af[1] = __float_as_uint(qs[(r + 8) * 68 + k8 + lc]);
            af[2] = __float_as_uint(qs[r * 68 + k8 + lc + 4]);
            af[3] = __float_as_uint(qs[(r + 8) * 68 + k8 + lc + 4]);
            #pragma unroll
            for (int ni = 0; ni < 8; ni++) {
                int n = ni * 8 + lr;
                uint32_t bf[2];
                bf[0] = __float_as_uint(ks[n * 68 + k8 + lc]);
                bf[1] = __float_as_uint(ks[n * 68 + k8 + lc + 4]);
                MMA_TF32(sc[ni], af, bf);
            }
        }

        bool diag = (kb == qb);
        #pragma unroll
        for (int h2 = 0; h2 < 2; h2++) {
            int row = w * 16 + lr + h2 * 8;
            if (diag) {
                #pragma unroll
                for (int ni = 0; ni < 8; ni++) {
                    int c0 = ni * 8 + lc * 2;
                    if (c0 > row)     sc[ni][h2 * 2 + 0] = -1e30f;
                    if (c0 + 1 > row) sc[ni][h2 * 2 + 1] = -1e30f;
                }
            }
            float mx = -1e30f;
            #pragma unroll
            for (int ni = 0; ni < 8; ni++)
                mx = fmaxf(mx, fmaxf(sc[ni][h2 * 2], sc[ni][h2 * 2 + 1]));
            mx = fmaxf(mx, __shfl_xor_sync(0xffffffffu, mx, 1));
            mx = fmaxf(mx, __shfl_xor_sync(0xffffffffu, mx, 2));
            float mn = fmaxf(m[h2], mx);
            float alpha = __expf(m[h2] - mn);
            m[h2] = mn;
            float rs = 0.f;
            #pragma unroll
            for (int ni = 0; ni < 8; ni++) {
                float p0 = __expf(sc[ni][h2 * 2]     - mn);
                float p1 = __expf(sc[ni][h2 * 2 + 1] - mn);
                rs += p0 + p1;
                *(float2*)&ps[row * 68 + ni * 8 + lc * 2] = make_float2(tf32r(p0), tf32r(p1));
            }
            rs += __shfl_xor_sync(0xffffffffu, rs, 1);
            rs += __shfl_xor_sync(0xffffffffu, rs, 2);
            l[h2] = l[h2] * alpha + rs;
            #pragma unroll
            for (int ni = 0; ni < 8; ni++) {
                o[ni][h2 * 2]     *= alpha;
                o[ni][h2 * 2 + 1] *= alpha;
            }
        }
        __syncwarp();

        #pragma unroll
        for (int ksx = 0; ksx < 8; ksx++) {
            int k8 = ksx * 8;
            int r = w * 16 + lr;
            uint32_t af[4];
            af[0] = __float_as_uint(ps[r * 68 + k8 + lc]);
            af[1] = __float_as_uint(ps[(r + 8) * 68 + k8 + lc]);
            af[2] = __float_as_uint(ps[r * 68 + k8 + lc + 4]);
            af[3] = __float_as_uint(ps[(r + 8) * 68 + k8 + lc + 4]);
            #pragma unroll
            for (int ni = 0; ni < 8; ni++) {
                int n = ni * 8 + lr;
                uint32_t bf[2];
                bf[0] = __float_as_uint(vT[n * 68 + k8 + lc]);
                bf[1] = __float_as_uint(vT[n * 68 + k8 + lc + 4]);
                MMA_TF32(o[ni], af, bf);
            }
        }
    }

    #pragma unroll
    for (int h2 = 0; h2 < 2; h2++) {
        float inv = 1.f / l[h2];
        int r = qb * 64 + w * 16 + lr + h2 * 8;
        #pragma unroll
        for (int ni = 0; ni < 8; ni++) {
            float2 v = make_float2(tf32r(o[ni][h2 * 2] * inv), tf32r(o[ni][h2 * 2 + 1] * inv));
            *(float2*)&g_att[(size_t)(b * TT + r) * DM + h * 64 + ni * 8 + lc * 2] = v;
        }
    }
}

// ---------------- host launch ----------------
static void run_gemm(const float* A, const float* Wt, float* C, int M, int N, int K,
                     const float* res, const float* mul, int epi) {
    if (N <= 1536) {
        gemm_tc<64><<<dim3((N + 127) / 128, M / 64), 256, GEMM_SMEM_64>>>(A, Wt, C, M, N, K, res, mul, epi);
    } else {
        gemm_tc<128><<<dim3((N + 127) / 128, M / 128), 256, GEMM_SMEM_128>>>(A, Wt, C, M, N, K, res, mul, epi);
    }
}

extern "C" void kernel_launch(void* const* d_in, const int* in_sizes, int n_in,
                              void* d_out, int out_size) {
    const float* x       = (const float*)d_in[0];
    const float* W_in    = (const float*)d_in[1];
    const float* conv_w  = (const float*)d_in[2];
    const float* conv_b  = (const float*)d_in[3];
    const float* A_log   = (const float*)d_in[4];
    const float* Dm      = (const float*)d_in[5];
    const float* dt_bias = (const float*)d_in[6];
    const float* mnorm_w = (const float*)d_in[7];
    const float* W_out   = (const float*)d_in[8];
    const float* W_qkv   = (const float*)d_in[9];
    const float* W_cproj = (const float*)d_in[10];
    const float* qconv_w = (const float*)d_in[11];
    const float* qconv_b = (const float*)d_in[12];
    const float* kconv_w = (const float*)d_in[13];
    const float* kconv_b = (const float*)d_in[14];
    const float* vconv_w = (const float*)d_in[15];
    const float* vconv_b = (const float*)d_in[16];
    const float* tmk     = (const float*)d_in[17];
    const float* tmr     = (const float*)d_in[18];
    const float* W_key   = (const float*)d_in[19];
    const float* W_rec   = (const float*)d_in[20];
    const float* W_val   = (const float*)d_in[21];
    float* out = (float*)d_out;

    float *p_h, *p_zxb, *p_y2, *p_x2, *p_qkv, *p_att, *p_x3, *p_xk, *p_xr, *p_kf, *p_kv, *p_wt;
    cudaGetSymbolAddress((void**)&p_h, g_h);
    cudaGetSymbolAddress((void**)&p_zxb, g_zxb);
    cudaGetSymbolAddress((void**)&p_y2, g_y2);
    cudaGetSymbolAddress((void**)&p_x2, g_x2);
    cudaGetSymbolAddress((void**)&p_qkv, g_qkv);
    cudaGetSymbolAddress((void**)&p_att, g_att);
    cudaGetSymbolAddress((void**)&p_x3, g_x3);
    cudaGetSymbolAddress((void**)&p_xk, g_xk);
    cudaGetSymbolAddress((void**)&p_xr, g_xr);
    cudaGetSymbolAddress((void**)&p_kf, g_kf);
    cudaGetSymbolAddress((void**)&p_kv, g_kv);
    cudaGetSymbolAddress((void**)&p_wt, g_wt);

    cudaFuncSetAttribute(attn_k, cudaFuncAttributeMaxDynamicSharedMemorySize, ATTN_SMEM);
    cudaFuncSetAttribute(gemm_tc<128>, cudaFuncAttributeMaxDynamicSharedMemorySize, GEMM_SMEM_128);
    cudaFuncSetAttribute(gemm_tc<64>,  cudaFuncAttributeMaxDynamicSharedMemorySize, GEMM_SMEM_64);

    // ---- weight tf32 round + transpose, single launch ----
    {
        WTab wt;
        const float* srcs[7] = {W_in, W_out, W_qkv, W_cproj, W_key, W_val, W_rec};
        int offs[7] = {OW_IN, OW_OUT, OW_QKV, OW_CPROJ, OW_KEY, OW_VAL, OW_REC};
        int Ks[7]   = {DM, DI, DM, DM, DM, FFND, DM};
        int Ns[7]   = {ZXB, DM, QKVD, DM, FFND, DM, DM};
        int acc = 0;
        for (int i = 0; i < 7; i++) {
            wt.src[i] = srcs[i]; wt.off[i] = offs[i]; wt.K[i] = Ks[i]; wt.N[i] = Ns[i];
            wt.tstart[i] = acc;
            acc += (Ks[i] >> 5) * (Ns[i] >> 5);
        }
        wt.tstart[7] = acc;
        cvtall_k<<<acc, dim3(32, 8)>>>(wt);
    }

    // ---- Mamba2-style block ----
    rmsnorm_k<<<BT, 256>>>(x, p_h, 1e-6f, 1);
    run_gemm(p_h, p_wt + OW_IN, p_zxb, BT, ZXB, DM, nullptr, nullptr, 0);
    conv_silu_k<<<BT / CTB, 256>>>(conv_w, conv_b, dt_bias, A_log);
    scan_k<<<128, 512>>>();
    gate_k<<<BT, 256>>>(Dm, mnorm_w);
    run_gemm(p_y2, p_wt + OW_OUT, p_x2, BT, DM, DI, x, nullptr, 1);

    // ---- attention block ----
    rmsnorm_k<<<BT, 256>>>(p_x2, p_h, 1e-6f, 1);
    run_gemm(p_h, p_wt + OW_QKV, p_qkv, BT, QKVD, DM, nullptr, nullptr, 0);
    convqkv_k<<<BT / CTB, 256>>>(qconv_w, qconv_b, kconv_w, kconv_b, vconv_w, vconv_b);
    attn_k<<<BSZ * NHA * (TT / 64), 128, ATTN_SMEM>>>();
    run_gemm(p_att, p_wt + OW_CPROJ, p_x3, BT, DM, DM, p_x2, nullptr, 1);

    // ---- channel mix ----
    rmsshift_k<<<BT, 256>>>(p_x3, tmk, tmr, p_xk, p_xr);
    run_gemm(p_xk, p_wt + OW_KEY, p_kf, BT, FFND, DM, nullptr, nullptr, 2);
    run_gemm(p_kf, p_wt + OW_VAL, p_kv, BT, DM, FFND, nullptr, nullptr, 0);
    run_gemm(p_xr, p_wt + OW_REC, out, BT, DM, DM, p_x3, p_kv, 3);
}

// round 12
// speedup vs baseline: 1.0179x; 1.0179x over previous
#include <cuda_runtime.h>
#include <math.h>
#include <stdint.h>

#define BSZ 2
#define TT 1024
#define DM 1024
#define DI 2048
#define DS 128
#define NH 32
#define HDS 64
#define NHA 16
#define HDA 64
#define FFND 4096
#define ZXB 4384
#define XBCD 2304
#define QKVD 1152
#define BT (BSZ*TT)

// ---------------- scratch (device globals; no allocations allowed) ----------------
__device__ float g_h[BT*DM];
__device__ float g_zxb[BT*ZXB];
__device__ float g_xBC[BT*XBCD];
__device__ float g_dt[BT*NH];
__device__ float g_dA[BT*NH];
__device__ float g_yp[2*BT*DI];
__device__ float g_y2[BT*DI];
__device__ float g_x2[BT*DM];
__device__ float g_qkv[BT*QKVD];
__device__ float g_qc[BT*DM];
__device__ float g_kc[BT*HDA];
__device__ float g_vc[BT*HDA];
__device__ float g_att[BT*DM];
__device__ float g_x3[BT*DM];
__device__ float g_xk[BT*DM];
__device__ float g_xr[BT*DM];
__device__ float g_kf[BT*FFND];
__device__ float g_kv[BT*DM];
__device__ float g_wt[18251776];   // tf32-rounded TRANSPOSED weights [N][K] (73MB)

// weight offsets in g_wt
#define OW_IN    0
#define OW_OUT   4489216
#define OW_QKV   6586368
#define OW_CPROJ 7766016
#define OW_KEY   8814592
#define OW_VAL   13008896
#define OW_REC   17203200

// ---------------- helpers ----------------
__device__ __forceinline__ uint32_t f2tf32(float x) {
    uint32_t r; asm("cvt.rna.tf32.f32 %0, %1;" : "=r"(r) : "f"(x)); return r;
}
__device__ __forceinline__ float tf32r(float x) { return __uint_as_float(f2tf32(x)); }

__device__ __forceinline__ float block_sum(float v) {
    __shared__ float red[32];
    int lane = threadIdx.x & 31, w = threadIdx.x >> 5;
    #pragma unroll
    for (int o = 16; o; o >>= 1) v += __shfl_xor_sync(0xffffffffu, v, o);
    if (lane == 0) red[w] = v;
    __syncthreads();
    int nw = blockDim.x >> 5;
    float r = (threadIdx.x < nw) ? red[threadIdx.x] : 0.f;
    if (w == 0) {
        #pragma unroll
        for (int o = 16; o; o >>= 1) r += __shfl_xor_sync(0xffffffffu, r, o);
        if (lane == 0) red[0] = r;
    }
    __syncthreads();
    return red[0];
}

__global__ void rmsnorm_k(const float* __restrict__ x, float* __restrict__ o, float eps, int rnd) {
    int row = blockIdx.x;
    const float* xr = x + (size_t)row * DM;
    float ss = 0.f;
    for (int c = threadIdx.x; c < DM; c += blockDim.x) { float v = xr[c]; ss = fmaf(v, v, ss); }
    ss = block_sum(ss);
    float sc = rsqrtf(ss / (float)DM + eps);
    float* orow = o + (size_t)row * DM;
    if (rnd) for (int c = threadIdx.x; c < DM; c += blockDim.x) orow[c] = tf32r(xr[c] * sc);
    else     for (int c = threadIdx.x; c < DM; c += blockDim.x) orow[c] = xr[c] * sc;
}

// ---------------- fused rmsnorm + token-shift (channel mix) ----------------
__global__ void rmsshift_k(const float* __restrict__ x3,
                           const float* __restrict__ tmk, const float* __restrict__ tmr,
                           float* __restrict__ xk, float* __restrict__ xr) {
    int bt = blockIdx.x; int t = bt & 1023;
    const float* cur = x3 + (size_t)bt * DM;
    const float* prv = x3 + (size_t)(bt - 1) * DM;
    float sa = 0.f, sb = 0.f;
    for (int c = threadIdx.x; c < DM; c += blockDim.x) {
        float v = cur[c]; sa = fmaf(v, v, sa);
        float p = t ? prv[c] : 0.f; sb = fmaf(p, p, sb);
    }
    float ra = block_sum(sa);
    __syncthreads();
    float rb = block_sum(sb);
    float scc = rsqrtf(ra / (float)DM + 1e-6f);
    float scp = rsqrtf(rb / (float)DM + 1e-6f);
    for (int c = threadIdx.x; c < DM; c += blockDim.x) {
        float h = cur[c] * scc;
        float hp = t ? prv[c] * scp : 0.f;
        float dd = hp - h;
        xk[(size_t)bt * DM + c] = tf32r(fmaf(dd, tmk[c], h));
        xr[(size_t)bt * DM + c] = tf32r(fmaf(dd, tmr[c], h));
    }
}

// ---------------- merged weight tf32 round + transpose (all 7 weights, one launch) ----
struct WTab {
    const float* src[7];
    int off[7];
    int K[7], N[7];
    int tstart[8];
};
__global__ void cvtall_k(WTab wt) {
    __shared__ float t[32][33];
    int bidx = blockIdx.x;
    int w = 0;
    #pragma unroll
    for (int i = 1; i < 7; i++) if (bidx >= wt.tstart[i]) w = i;
    int tloc = bidx - wt.tstart[w];
    int K = wt.K[w], N = wt.N[w];
    int ntn = N >> 5;
    int k0 = (tloc / ntn) << 5, n0 = (tloc % ntn) << 5;
    const float* in = wt.src[w];
    float* out = g_wt + wt.off[w];
    int x = threadIdx.x, y = threadIdx.y;
    #pragma unroll
    for (int i = 0; i < 32; i += 8)
        t[y + i][x] = tf32r(in[(size_t)(k0 + y + i) * N + n0 + x]);
    __syncthreads();
    #pragma unroll
    for (int i = 0; i < 32; i += 8)
        out[(size_t)(n0 + y + i) * K + k0 + x] = t[x][y + i];
}

// ================= tf32 mma.sync GEMM (ldmatrix, 3-stage pipeline, templated BM) =====
#define CP_ASYNC16(dst, src, sz) \
    asm volatile("cp.async.cg.shared.global [%0], [%1], 16, %2;" :: "r"(dst), "l"(src), "r"(sz) : "memory")
#define CP_COMMIT() asm volatile("cp.async.commit_group;" ::: "memory")
#define CP_WAIT1()  asm volatile("cp.async.wait_group 1;" ::: "memory")
#define MMA_TF32(d, a, b) \
    asm volatile("mma.sync.aligned.m16n8k8.row.col.f32.tf32.tf32.f32 " \
        "{%0,%1,%2,%3}, {%4,%5,%6,%7}, {%8,%9}, {%0,%1,%2,%3};" \
        : "+f"((d)[0]), "+f"((d)[1]), "+f"((d)[2]), "+f"((d)[3]) \
        : "r"((a)[0]), "r"((a)[1]), "r"((a)[2]), "r"((a)[3]), "r"((b)[0]), "r"((b)[1]))
#define LDMX4(r0, r1, r2, r3, a) \
    asm volatile("ldmatrix.sync.aligned.m8n8.x4.shared.b16 {%0,%1,%2,%3}, [%4];" \
        : "=r"(r0), "=r"(r1), "=r"(r2), "=r"(r3) : "r"(a))

// C[M,N] = A[M,K] @ Bt[N,K]^T (+fused epilogue). A,Bt pre-rounded to tf32.
template<int BM>
__global__ void __launch_bounds__(256, 2) gemm_tc(const float* __restrict__ A, const float* __restrict__ Bt,
                                                  float* __restrict__ C, int M, int N, int K,
                                                  const float* __restrict__ res, const float* __restrict__ mul, int epi)
{
    constexpr int MI = BM / 32;            // per-warp m-tiles of 16 (2 or 4)
    extern __shared__ float gs[];
    float (*As)[36] = (float(*)[36])gs;                // [3*BM][36]
    float (*Bs)[36] = (float(*)[36])(gs + 3*BM*36);    // [3*128][36] (n-major)
    int tid = threadIdx.x;
    int m0 = blockIdx.y * BM, n0 = blockIdx.x * 128;
    int w = tid >> 5, lane = tid & 31;
    int wm = (w >> 2) * (BM / 2);
    int wn = (w & 3) * 32;

    float acc[MI][4][4];
    #pragma unroll
    for (int mi = 0; mi < MI; mi++)
        #pragma unroll
        for (int ni = 0; ni < 4; ni++)
            #pragma unroll
            for (int e = 0; e < 4; e++) acc[mi][ni][e] = 0.f;

    const int NC = K >> 5;

    auto fill = [&](int buf, int k0) {
        #pragma unroll
        for (int i = 0; i < BM / 32; i++) {
            int task = tid + i * 256;
            int r = task >> 3, q = (task & 7) * 4;
            const float* src = A + (size_t)(m0 + r) * K + k0 + q;
            uint32_t dst = (uint32_t)__cvta_generic_to_shared(&As[buf * BM + r][q]);
            CP_ASYNC16(dst, src, 16);
        }
        #pragma unroll
        for (int i = 0; i < 4; i++) {
            int task = tid + i * 256;
            int r = task >> 3, q = (task & 7) * 4;
            int ok = (n0 + r) < N;
            const float* src = Bt + (size_t)(n0 + r) * K + k0 + q;
            uint32_t dst = (uint32_t)__cvta_generic_to_shared(&Bs[buf * 128 + r][q]);
            CP_ASYNC16(dst, src, ok ? 16 : 0);
        }
    };

    fill(0, 0);  CP_COMMIT();
    fill(1, 32); CP_COMMIT();     // all GEMMs have K >= 1024

    int g = lane >> 3, lr8 = lane & 7;
    int arow_l = wm + (g & 1) * 8 + lr8;
    int acol_l = (g >> 1) * 4;
    int brow_l = wn + (g >> 1) * 8 + lr8;
    int bcol_l = (g & 1) * 4;

    int buf = 0;
    for (int ct = 0; ct < NC; ct++) {
        CP_WAIT1();
        __syncthreads();

        const float (*as)[36] = &As[buf * BM];
        const float (*bs)[36] = &Bs[buf * 128];
        #pragma unroll
        for (int ks = 0; ks < 4; ks++) {
            int kb = ks * 8;
            uint32_t af[MI][4];
            #pragma unroll
            for (int mi = 0; mi < MI; mi++) {
                uint32_t a = (uint32_t)__cvta_generic_to_shared(&as[arow_l + mi * 16][acol_l + kb]);
                LDMX4(af[mi][0], af[mi][1], af[mi][2], af[mi][3], a);
            }
            uint32_t bf[4][2];
            #pragma unroll
            for (int p = 0; p < 2; p++) {
                uint32_t a = (uint32_t)__cvta_generic_to_shared(&bs[brow_l + p * 16][bcol_l + kb]);
                LDMX4(bf[2*p][0], bf[2*p][1], bf[2*p+1][0], bf[2*p+1][1], a);
            }
            #pragma unroll
            for (int mi = 0; mi < MI; mi++)
                #pragma unroll
                for (int ni = 0; ni < 4; ni++)
                    MMA_TF32(acc[mi][ni], af[mi], bf[ni]);
        }

        int nx = ct + 2;
        if (nx < NC) {
            int nslot = nx - (nx / 3) * 3;
            fill(nslot, nx * 32);
        }
        CP_COMMIT();
        if (++buf == 3) buf = 0;
    }

    #pragma unroll
    for (int mi = 0; mi < MI; mi++) {
        int r0 = m0 + wm + mi * 16 + (lane >> 2);
        #pragma unroll
        for (int ni = 0; ni < 4; ni++) {
            int c = n0 + wn + ni * 8 + (lane & 3) * 2;
            if (c < N) {
                #pragma unroll
                for (int half = 0; half < 2; half++) {
                    int r = r0 + half * 8;
                    size_t idx = (size_t)r * N + c;
                    float v0 = acc[mi][ni][half * 2 + 0];
                    float v1 = acc[mi][ni][half * 2 + 1];
                    if (epi == 1) {
                        v0 += res[idx]; v1 += res[idx + 1];
                    } else if (epi == 2) {
                        v0 = fmaxf(v0, 0.f); v0 = tf32r(v0 * v0);
                        v1 = fmaxf(v1, 0.f); v1 = tf32r(v1 * v1);
                    } else if (epi == 3) {
                        v0 = res[idx]     + mul[idx]     / (1.f + expf(-v0));
                        v1 = res[idx + 1] + mul[idx + 1] / (1.f + expf(-v1));
                    }
                    C[idx] = v0; C[idx + 1] = v1;
                }
            }
        }
    }
}
#define GEMM_SMEM_128 110592
#define GEMM_SMEM_64  82944

// ---------------- xBC causal depthwise conv (K=4) + silu + fused dt/dA ----------------
// CTA = (batch, 8-timestep block, 256-channel slab): full occupancy AND 4x traffic cut.
#define CTB 8
__global__ void conv_silu_k(const float* __restrict__ cw, const float* __restrict__ cb,
                            const float* __restrict__ dt_bias, const float* __restrict__ A_log) {
    int blk = blockIdx.x;
    int cblk = blk % (XBCD / 256);          // 9 slabs
    int tb = blk / (XBCD / 256);
    int b = tb / (TT / CTB);
    int t0 = (tb % (TT / CTB)) * CTB;
    int c = cblk * 256 + threadIdx.x;

    float w0 = cw[c*4], w1 = cw[c*4+1], w2 = cw[c*4+2], w3 = cw[c*4+3], bb = cb[c];
    float xm3 = (t0 >= 3) ? g_zxb[(size_t)(b * TT + t0 - 3) * ZXB + DI + c] : 0.f;
    float xm2 = (t0 >= 2) ? g_zxb[(size_t)(b * TT + t0 - 2) * ZXB + DI + c] : 0.f;
    float xm1 = (t0 >= 1) ? g_zxb[(size_t)(b * TT + t0 - 1) * ZXB + DI + c] : 0.f;
    #pragma unroll
    for (int j = 0; j < CTB; j++) {
        float x0 = g_zxb[(size_t)(b * TT + t0 + j) * ZXB + DI + c];
        float acc = bb;
        acc = fmaf(w0, xm3, acc); acc = fmaf(w1, xm2, acc);
        acc = fmaf(w2, xm1, acc); acc = fmaf(w3, x0, acc);
        acc = acc / (1.f + expf(-acc));
        g_xBC[(size_t)(b * TT + t0 + j) * XBCD + c] = acc;
        xm3 = xm2; xm2 = xm1; xm1 = x0;
    }
    // fused dt/dA: only slab 0; 256 threads = 8 timesteps x 32 heads
    if (cblk == 0) {
        int h = threadIdx.x & 31, j = threadIdx.x >> 5;
        int bt = b * TT + t0 + j;
        float v = g_zxb[(size_t)bt * ZXB + 4352 + h] + dt_bias[h];
        float sp = (v > 20.f) ? v : log1pf(expf(v));
        g_dt[bt * NH + h] = sp;
        g_dA[bt * NH + h] = expf(sp * (-expf(A_log[h])));
    }
}

// ---------------- SSM scan ----------------
__global__ void scan_k() {
    int bid = blockIdx.x;
    int ns = bid & 1; int bh = bid >> 1; int b = bh >> 5; int h = bh & 31;
    int tid = threadIdx.x;
    int p = tid >> 3;
    int ng = tid & 7;
    __shared__ float sB[16 * 64], sC[16 * 64], sX[16 * 64], sS[16];
    float s[8];
    #pragma unroll
    for (int j = 0; j < 8; j++) s[j] = 0.f;
    int nb = ns * 64;

    for (int ct = 0; ct < TT / 16; ct++) {
        int t0 = ct * 16;
        #pragma unroll
        for (int l = 0; l < 2; l++) {
            int e = tid + l * 512; int tt = e >> 6; int n = e & 63;
            int base = b * TT + t0 + tt;
            sB[e] = g_xBC[(size_t)base * XBCD + DI + nb + n];
            sC[e] = g_xBC[(size_t)base * XBCD + DI + DS + nb + n];
            sX[e] = g_xBC[(size_t)base * XBCD + h * 64 + n] * g_dt[base * NH + h];
        }
        if (tid < 16) sS[tid] = g_dA[(b * TT + t0 + tid) * NH + h];
        __syncthreads();
        for (int tt = 0; tt < 16; tt++) {
            float da = sS[tt];
            float dtx = sX[tt * 64 + p];
            float bb[8], cc[8];
            *(float4*)&bb[0] = *(float4*)&sB[tt * 64 + ng * 8];
            *(float4*)&bb[4] = *(float4*)&sB[tt * 64 + ng * 8 + 4];
            *(float4*)&cc[0] = *(float4*)&sC[tt * 64 + ng * 8];
            *(float4*)&cc[4] = *(float4*)&sC[tt * 64 + ng * 8 + 4];
            float acc = 0.f;
            #pragma unroll
            for (int j = 0; j < 8; j++) {
                s[j] = fmaf(s[j], da, dtx * bb[j]);
                acc = fmaf(s[j], cc[j], acc);
            }
            acc += __shfl_xor_sync(0xffffffffu, acc, 1);
            acc += __shfl_xor_sync(0xffffffffu, acc, 2);
            acc += __shfl_xor_sync(0xffffffffu, acc, 4);
            if (ng == 0)
                g_yp[(size_t)ns * (BT * DI) + (size_t)(b * TT + t0 + tt) * DI + h * 64 + p] = acc;
        }
        __syncthreads();
    }
}

__global__ void gate_k(const float* __restrict__ Dm, const float* __restrict__ mnw) {
    int bt = blockIdx.x;
    float ss = 0.f;
    for (int c = threadIdx.x; c < DI; c += blockDim.x) {
        float v = g_yp[(size_t)bt * DI + c] + g_yp[(size_t)BT * DI + (size_t)bt * DI + c]
                + g_xBC[(size_t)bt * XBCD + c] * Dm[c >> 6];
        float z = g_zxb[(size_t)bt * ZXB + c];
        v *= z / (1.f + expf(-z));
        g_y2[(size_t)bt * DI + c] = v;
        ss = fmaf(v, v, ss);
    }
    ss = block_sum(ss);
    float sc = rsqrtf(ss / (float)DI + 1e-5f);
    for (int c = threadIdx.x; c < DI; c += blockDim.x)
        g_y2[(size_t)bt * DI + c] = tf32r(g_y2[(size_t)bt * DI + c] * sc * mnw[c]);
}

// ---------------- q/k/v causal depthwise conv (K=3), channel-slab blocking -----------
__global__ void convqkv_k(const float* __restrict__ qw, const float* __restrict__ qb,
                          const float* __restrict__ kw, const float* __restrict__ kb,
                          const float* __restrict__ vw, const float* __restrict__ vb) {
    int blk = blockIdx.x;
    int cblk = blk % 5;                     // 5 slabs of 256 (last partial: 1152-1024=128)
    int tb = blk / 5;
    int b = tb / (TT / CTB);
    int t0 = (tb % (TT / CTB)) * CTB;
    int c = cblk * 256 + threadIdx.x;
    if (c >= QKVD) return;

    const float* w; const float* bias; int d;
    if (c < DM)            { d = c & 63;        w = qw; bias = qb; }
    else if (c < DM + 64)  { d = c - DM;        w = kw; bias = kb; }
    else                   { d = c - DM - 64;   w = vw; bias = vb; }
    float w0 = w[d*3], w1 = w[d*3+1], w2 = w[d*3+2], bb = bias[d];
    float xm2 = (t0 >= 2) ? g_qkv[(size_t)(b * TT + t0 - 2) * QKVD + c] : 0.f;
    float xm1 = (t0 >= 1) ? g_qkv[(size_t)(b * TT + t0 - 1) * QKVD + c] : 0.f;
    #pragma unroll
    for (int j = 0; j < CTB; j++) {
        int bt = b * TT + t0 + j;
        float x0 = g_qkv[(size_t)bt * QKVD + c];
        float acc = bb;
        acc = fmaf(w0, xm2, acc); acc = fmaf(w1, xm1, acc); acc = fmaf(w2, x0, acc);
        if (c < DM)           g_qc[(size_t)bt * DM + c] = acc;
        else if (c < DM + 64) g_kc[(size_t)bt * 64 + d] = acc;
        else                  g_vc[(size_t)bt * 64 + d] = acc;
        xm2 = xm1; xm1 = x0;
    }
}

// ---------------- fused causal attention (tf32 mma, online softmax) ----------------
#define ATTN_SMEM 69632
__global__ void __launch_bounds__(128) attn_k() {
    extern __shared__ float sm[];
    float* qs = sm;              // [64][68] tf32, pre-scaled
    float* ks = sm + 4352;       // [64][68] tf32
    float* vT = sm + 8704;       // [64][68] tf32 (V transposed)
    float* ps = sm + 13056;      // [64][68] tf32 (P)
    int bid = blockIdx.x;
    int qb = bid & 15; int h = (bid >> 4) & 15; int b = bid >> 8;
    int tid = threadIdx.x;
    int w = tid >> 5, lane = tid & 31;
    int lr = lane >> 2, lc = lane & 3;

    {
        int r = tid >> 1, d0 = (tid & 1) * 32;
        const float* qp = &g_qc[(size_t)(b * TT + qb * 64 + r) * DM + h * 64 + d0];
        #pragma unroll
        for (int j = 0; j < 8; j++) {
            float4 v = *(const float4*)(qp + j * 4);
            *(float4*)&qs[r * 68 + d0 + j * 4] =
                make_float4(tf32r(v.x * 0.125f), tf32r(v.y * 0.125f),
                            tf32r(v.z * 0.125f), tf32r(v.w * 0.125f));
        }
    }

    float m[2] = {-1e30f, -1e30f}, l[2] = {0.f, 0.f};
    float o[8][4];
    #pragma unroll
    for (int ni = 0; ni < 8; ni++)
        #pragma unroll
        for (int e = 0; e < 4; e++) o[ni][e] = 0.f;

    for (int kb = 0; kb <= qb; kb++) {
        __syncthreads();
        {
            int r = tid >> 1, d0 = (tid & 1) * 32;
            const float* kp = &g_kc[(size_t)(b * TT + kb * 64 + r) * 64 + d0];
            const float* vp = &g_vc[(size_t)(b * TT + kb * 64 + r) * 64 + d0];
            #pragma unroll
            for (int j = 0; j < 8; j++) {
                float4 kv = *(const float4*)(kp + j * 4);
                *(float4*)&ks[r * 68 + d0 + j * 4] =
                    make_float4(tf32r(kv.x), tf32r(kv.y), tf32r(kv.z), tf32r(kv.w));
                float4 vv = *(const float4*)(vp + j * 4);
                int d = d0 + j * 4;
                vT[(d + 0) * 68 + r] = tf32r(vv.x); vT[(d + 1) * 68 + r] = tf32r(vv.y);
                vT[(d + 2) * 68 + r] = tf32r(vv.z); vT[(d + 3) * 68 + r] = tf32r(vv.w);
            }
        }
        __syncthreads();

        float sc[8][4];
        #pragma unroll
        for (int ni = 0; ni < 8; ni++)
            #pragma unroll
            for (int e = 0; e < 4; e++) sc[ni][e] = 0.f;
        #pragma unroll
        for (int ksx = 0; ksx < 8; ksx++) {
            int k8 = ksx * 8;
            int r = w * 16 + lr;
            uint32_t af[4];
            af[0] = __float_as_uint(qs[r * 68 + k8 + lc]);
            af[1] = __float_as_uint(qs[(r + 8) * 68 + k8 + lc]);
            af[2] = __float_as_uint(qs[r * 68 + k8 + lc + 4]);
            af[3] = __float_as_uint(qs[(r + 8) * 68 + k8 + lc + 4]);
            #pragma unroll
            for (int ni = 0; ni < 8; ni++) {
                int n = ni * 8 + lr;
                uint32_t bf[2];
                bf[0] = __float_as_uint(ks[n * 68 + k8 + lc]);
                bf[1] = __float_as_uint(ks[n * 68 + k8 + lc + 4]);
                MMA_TF32(sc[ni], af, bf);
            }
        }

        bool diag = (kb == qb);
        #pragma unroll
        for (int h2 = 0; h2 < 2; h2++) {
            int row = w * 16 + lr + h2 * 8;
            if (diag) {
                #pragma unroll
                for (int ni = 0; ni < 8; ni++) {
                    int c0 = ni * 8 + lc * 2;
                    if (c0 > row)     sc[ni][h2 * 2 + 0] = -1e30f;
                    if (c0 + 1 > row) sc[ni][h2 * 2 + 1] = -1e30f;
                }
            }
            float mx = -1e30f;
            #pragma unroll
            for (int ni = 0; ni < 8; ni++)
                mx = fmaxf(mx, fmaxf(sc[ni][h2 * 2], sc[ni][h2 * 2 + 1]));
            mx = fmaxf(mx, __shfl_xor_sync(0xffffffffu, mx, 1));
            mx = fmaxf(mx, __shfl_xor_sync(0xffffffffu, mx, 2));
            float mn = fmaxf(m[h2], mx);
            float alpha = __expf(m[h2] - mn);
            m[h2] = mn;
            float rs = 0.f;
            #pragma unroll
            for (int ni = 0; ni < 8; ni++) {
                float p0 = __expf(sc[ni][h2 * 2]     - mn);
                float p1 = __expf(sc[ni][h2 * 2 + 1] - mn);
                rs += p0 + p1;
                *(float2*)&ps[row * 68 + ni * 8 + lc * 2] = make_float2(tf32r(p0), tf32r(p1));
            }
            rs += __shfl_xor_sync(0xffffffffu, rs, 1);
            rs += __shfl_xor_sync(0xffffffffu, rs, 2);
            l[h2] = l[h2] * alpha + rs;
            #pragma unroll
            for (int ni = 0; ni < 8; ni++) {
                o[ni][h2 * 2]     *= alpha;
                o[ni][h2 * 2 + 1] *= alpha;
            }
        }
        __syncwarp();

        #pragma unroll
        for (int ksx = 0; ksx < 8; ksx++) {
            int k8 = ksx * 8;
            int r = w * 16 + lr;
            uint32_t af[4];
            af[0] = __float_as_uint(ps[r * 68 + k8 + lc]);
            af[1] = __float_as_uint(ps[(r + 8) * 68 + k8 + lc]);
            af[2] = __float_as_uint(ps[r * 68 + k8 + lc + 4]);
            af[3] = __float_as_uint(ps[(r + 8) * 68 + k8 + lc + 4]);
            #pragma unroll
            for (int ni = 0; ni < 8; ni++) {
                int n = ni * 8 + lr;
                uint32_t bf[2];
                bf[0] = __float_as_uint(vT[n * 68 + k8 + lc]);
                bf[1] = __float_as_uint(vT[n * 68 + k8 + lc + 4]);
                MMA_TF32(o[ni], af, bf);
            }
        }
    }

    #pragma unroll
    for (int h2 = 0; h2 < 2; h2++) {
        float inv = 1.f / l[h2];
        int r = qb * 64 + w * 16 + lr + h2 * 8;
        #pragma unroll
        for (int ni = 0; ni < 8; ni++) {
            float2 v = make_float2(tf32r(o[ni][h2 * 2] * inv), tf32r(o[ni][h2 * 2 + 1] * inv));
            *(float2*)&g_att[(size_t)(b * TT + r) * DM + h * 64 + ni * 8 + lc * 2] = v;
        }
    }
}

// ---------------- host launch ----------------
static void run_gemm(const float* A, const float* Wt, float* C, int M, int N, int K,
                     const float* res, const float* mul, int epi) {
    if (N <= 1536) {
        gemm_tc<64><<<dim3((N + 127) / 128, M / 64), 256, GEMM_SMEM_64>>>(A, Wt, C, M, N, K, res, mul, epi);
    } else {
        gemm_tc<128><<<dim3((N + 127) / 128, M / 128), 256, GEMM_SMEM_128>>>(A, Wt, C, M, N, K, res, mul, epi);
    }
}

extern "C" void kernel_launch(void* const* d_in, const int* in_sizes, int n_in,
                              void* d_out, int out_size) {
    const float* x       = (const float*)d_in[0];
    const float* W_in    = (const float*)d_in[1];
    const float* conv_w  = (const float*)d_in[2];
    const float* conv_b  = (const float*)d_in[3];
    const float* A_log   = (const float*)d_in[4];
    const float* Dm      = (const float*)d_in[5];
    const float* dt_bias = (const float*)d_in[6];
    const float* mnorm_w = (const float*)d_in[7];
    const float* W_out   = (const float*)d_in[8];
    const float* W_qkv   = (const float*)d_in[9];
    const float* W_cproj = (const float*)d_in[10];
    const float* qconv_w = (const float*)d_in[11];
    const float* qconv_b = (const float*)d_in[12];
    const float* kconv_w = (const float*)d_in[13];
    const float* kconv_b = (const float*)d_in[14];
    const float* vconv_w = (const float*)d_in[15];
    const float* vconv_b = (const float*)d_in[16];
    const float* tmk     = (const float*)d_in[17];
    const float* tmr     = (const float*)d_in[18];
    const float* W_key   = (const float*)d_in[19];
    const float* W_rec   = (const float*)d_in[20];
    const float* W_val   = (const float*)d_in[21];
    float* out = (float*)d_out;

    float *p_h, *p_zxb, *p_y2, *p_x2, *p_qkv, *p_att, *p_x3, *p_xk, *p_xr, *p_kf, *p_kv, *p_wt;
    cudaGetSymbolAddress((void**)&p_h, g_h);
    cudaGetSymbolAddress((void**)&p_zxb, g_zxb);
    cudaGetSymbolAddress((void**)&p_y2, g_y2);
    cudaGetSymbolAddress((void**)&p_x2, g_x2);
    cudaGetSymbolAddress((void**)&p_qkv, g_qkv);
    cudaGetSymbolAddress((void**)&p_att, g_att);
    cudaGetSymbolAddress((void**)&p_x3, g_x3);
    cudaGetSymbolAddress((void**)&p_xk, g_xk);
    cudaGetSymbolAddress((void**)&p_xr, g_xr);
    cudaGetSymbolAddress((void**)&p_kf, g_kf);
    cudaGetSymbolAddress((void**)&p_kv, g_kv);
    cudaGetSymbolAddress((void**)&p_wt, g_wt);

    cudaFuncSetAttribute(attn_k, cudaFuncAttributeMaxDynamicSharedMemorySize, ATTN_SMEM);
    cudaFuncSetAttribute(gemm_tc<128>, cudaFuncAttributeMaxDynamicSharedMemorySize, GEMM_SMEM_128);
    cudaFuncSetAttribute(gemm_tc<64>,  cudaFuncAttributeMaxDynamicSharedMemorySize, GEMM_SMEM_64);

    // ---- weight tf32 round + transpose, single launch ----
    {
        WTab wt;
        const float* srcs[7] = {W_in, W_out, W_qkv, W_cproj, W_key, W_val, W_rec};
        int offs[7] = {OW_IN, OW_OUT, OW_QKV, OW_CPROJ, OW_KEY, OW_VAL, OW_REC};
        int Ks[7]   = {DM, DI, DM, DM, DM, FFND, DM};
        int Ns[7]   = {ZXB, DM, QKVD, DM, FFND, DM, DM};
        int acc = 0;
        for (int i = 0; i < 7; i++) {
            wt.src[i] = srcs[i]; wt.off[i] = offs[i]; wt.K[i] = Ks[i]; wt.N[i] = Ns[i];
            wt.tstart[i] = acc;
            acc += (Ks[i] >> 5) * (Ns[i] >> 5);
        }
        wt.tstart[7] = acc;
        cvtall_k<<<acc, dim3(32, 8)>>>(wt);
    }

    // ---- Mamba2-style block ----
    rmsnorm_k<<<BT, 256>>>(x, p_h, 1e-6f, 1);
    run_gemm(p_h, p_wt + OW_IN, p_zxb, BT, ZXB, DM, nullptr, nullptr, 0);
    conv_silu_k<<<(BT / CTB) * (XBCD / 256), 256>>>(conv_w, conv_b, dt_bias, A_log);
    scan_k<<<128, 512>>>();
    gate_k<<<BT, 256>>>(Dm, mnorm_w);
    run_gemm(p_y2, p_wt + OW_OUT, p_x2, BT, DM, DI, x, nullptr, 1);

    // ---- attention block ----
    rmsnorm_k<<<BT, 256>>>(p_x2, p_h, 1e-6f, 1);
    run_gemm(p_h, p_wt + OW_QKV, p_qkv, BT, QKVD, DM, nullptr, nullptr, 0);
    convqkv_k<<<(BT / CTB) * 5, 256>>>(qconv_w, qconv_b, kconv_w, kconv_b, vconv_w, vconv_b);
    attn_k<<<BSZ * NHA * (TT / 64), 128, ATTN_SMEM>>>();
    run_gemm(p_att, p_wt + OW_CPROJ, p_x3, BT, DM, DM, p_x2, nullptr, 1);

    // ---- channel mix ----
    rmsshift_k<<<BT, 256>>>(p_x3, tmk, tmr, p_xk, p_xr);
    run_gemm(p_xk, p_wt + OW_KEY, p_kf, BT, FFND, DM, nullptr, nullptr, 2);
    run_gemm(p_kf, p_wt + OW_VAL, p_kv, BT, DM, FFND, nullptr, nullptr, 0);
    run_gemm(p_xr, p_wt + OW_REC, out, BT, DM, DM, p_x3, p_kv, 3);
}

// round 13
// speedup vs baseline: 1.0394x; 1.0211x over previous
#include <cuda_runtime.h>
#include <math.h>
#include <stdint.h>

#define BSZ 2
#define TT 1024
#define DM 1024
#define DI 2048
#define DS 128
#define NH 32
#define HDS 64
#define NHA 16
#define HDA 64
#define FFND 4096
#define ZXB 4384
#define XBCD 2304
#define QKVD 1152
#define BT (BSZ*TT)

// ---------------- scratch (device globals; no allocations allowed) ----------------
__device__ float g_h[BT*DM];
__device__ float g_zxb[BT*ZXB];
__device__ float g_xBC[BT*XBCD];
__device__ float g_dt[BT*NH];
__device__ float g_dA[BT*NH];
__device__ float g_yp[2*BT*DI];
__device__ float g_y2[BT*DI];
__device__ float g_x2[BT*DM];
__device__ float g_qkv[BT*QKVD];
__device__ float g_qc[BT*DM];
__device__ float g_kc[BT*HDA];
__device__ float g_vc[BT*HDA];
__device__ float g_att[BT*DM];
__device__ float g_x3[BT*DM];
__device__ float g_xk[BT*DM];
__device__ float g_xr[BT*DM];
__device__ float g_kf[BT*FFND];
__device__ float g_kv[BT*DM];
__device__ float g_wt[18251776];   // tf32-rounded TRANSPOSED weights [N][K] (73MB)

// weight offsets in g_wt
#define OW_IN    0
#define OW_OUT   4489216
#define OW_QKV   6586368
#define OW_CPROJ 7766016
#define OW_KEY   8814592
#define OW_VAL   13008896
#define OW_REC   17203200

// ---------------- helpers ----------------
__device__ __forceinline__ uint32_t f2tf32(float x) {
    uint32_t r; asm("cvt.rna.tf32.f32 %0, %1;" : "=r"(r) : "f"(x)); return r;
}
__device__ __forceinline__ float tf32r(float x) { return __uint_as_float(f2tf32(x)); }

__device__ __forceinline__ float block_sum(float v) {
    __shared__ float red[32];
    int lane = threadIdx.x & 31, w = threadIdx.x >> 5;
    #pragma unroll
    for (int o = 16; o; o >>= 1) v += __shfl_xor_sync(0xffffffffu, v, o);
    if (lane == 0) red[w] = v;
    __syncthreads();
    int nw = blockDim.x >> 5;
    float r = (threadIdx.x < nw) ? red[threadIdx.x] : 0.f;
    if (w == 0) {
        #pragma unroll
        for (int o = 16; o; o >>= 1) r += __shfl_xor_sync(0xffffffffu, r, o);
        if (lane == 0) red[0] = r;
    }
    __syncthreads();
    return red[0];
}

__global__ void rmsnorm_k(const float* __restrict__ x, float* __restrict__ o, float eps, int rnd) {
    int row = blockIdx.x;
    const float* xr = x + (size_t)row * DM;
    float ss = 0.f;
    for (int c = threadIdx.x; c < DM; c += blockDim.x) { float v = xr[c]; ss = fmaf(v, v, ss); }
    ss = block_sum(ss);
    float sc = rsqrtf(ss / (float)DM + eps);
    float* orow = o + (size_t)row * DM;
    if (rnd) for (int c = threadIdx.x; c < DM; c += blockDim.x) orow[c] = tf32r(xr[c] * sc);
    else     for (int c = threadIdx.x; c < DM; c += blockDim.x) orow[c] = xr[c] * sc;
}

// ---------------- fused rmsnorm + token-shift (channel mix) ----------------
__global__ void rmsshift_k(const float* __restrict__ x3,
                           const float* __restrict__ tmk, const float* __restrict__ tmr,
                           float* __restrict__ xk, float* __restrict__ xr) {
    int bt = blockIdx.x; int t = bt & 1023;
    const float* cur = x3 + (size_t)bt * DM;
    const float* prv = x3 + (size_t)(bt - 1) * DM;
    float sa = 0.f, sb = 0.f;
    for (int c = threadIdx.x; c < DM; c += blockDim.x) {
        float v = cur[c]; sa = fmaf(v, v, sa);
        float p = t ? prv[c] : 0.f; sb = fmaf(p, p, sb);
    }
    float ra = block_sum(sa);
    __syncthreads();
    float rb = block_sum(sb);
    float scc = rsqrtf(ra / (float)DM + 1e-6f);
    float scp = rsqrtf(rb / (float)DM + 1e-6f);
    for (int c = threadIdx.x; c < DM; c += blockDim.x) {
        float h = cur[c] * scc;
        float hp = t ? prv[c] * scp : 0.f;
        float dd = hp - h;
        xk[(size_t)bt * DM + c] = tf32r(fmaf(dd, tmk[c], h));
        xr[(size_t)bt * DM + c] = tf32r(fmaf(dd, tmr[c], h));
    }
}

// ---------------- merged weight tf32 round + transpose (all 7 weights, one launch) ----
struct WTab {
    const float* src[7];
    int off[7];
    int K[7], N[7];
    int tstart[8];
};
__global__ void cvtall_k(WTab wt) {
    __shared__ float t[32][33];
    int bidx = blockIdx.x;
    int w = 0;
    #pragma unroll
    for (int i = 1; i < 7; i++) if (bidx >= wt.tstart[i]) w = i;
    int tloc = bidx - wt.tstart[w];
    int K = wt.K[w], N = wt.N[w];
    int ntn = N >> 5;
    int k0 = (tloc / ntn) << 5, n0 = (tloc % ntn) << 5;
    const float* in = wt.src[w];
    float* out = g_wt + wt.off[w];
    int x = threadIdx.x, y = threadIdx.y;
    #pragma unroll
    for (int i = 0; i < 32; i += 8)
        t[y + i][x] = tf32r(in[(size_t)(k0 + y + i) * N + n0 + x]);
    __syncthreads();
    #pragma unroll
    for (int i = 0; i < 32; i += 8)
        out[(size_t)(n0 + y + i) * K + k0 + x] = t[x][y + i];
}

// ================= tf32 mma.sync GEMM (ldmatrix, templated pipeline depth) ===========
#define CP_ASYNC16(dst, src, sz) \
    asm volatile("cp.async.cg.shared.global [%0], [%1], 16, %2;" :: "r"(dst), "l"(src), "r"(sz) : "memory")
#define CP_COMMIT() asm volatile("cp.async.commit_group;" ::: "memory")
#define CP_WAIT_N(n) asm volatile("cp.async.wait_group %0;" :: "n"(n) : "memory")
#define MMA_TF32(d, a, b) \
    asm volatile("mma.sync.aligned.m16n8k8.row.col.f32.tf32.tf32.f32 " \
        "{%0,%1,%2,%3}, {%4,%5,%6,%7}, {%8,%9}, {%0,%1,%2,%3};" \
        : "+f"((d)[0]), "+f"((d)[1]), "+f"((d)[2]), "+f"((d)[3]) \
        : "r"((a)[0]), "r"((a)[1]), "r"((a)[2]), "r"((a)[3]), "r"((b)[0]), "r"((b)[1]))
#define LDMX4(r0, r1, r2, r3, a) \
    asm volatile("ldmatrix.sync.aligned.m8n8.x4.shared.b16 {%0,%1,%2,%3}, [%4];" \
        : "=r"(r0), "=r"(r1), "=r"(r2), "=r"(r3) : "r"(a))

// C[M,N] = A[M,K] @ Bt[N,K]^T (+fused epilogue). A,Bt pre-rounded to tf32.
// 128x128 tiles. STAGES=3 + 2 CTA/SM for wide-N (occupancy-hidden);
// STAGES=5 + 1 CTA/SM for small-N (prefetch-hidden).
template<int STAGES, int MINCTA>
__global__ void __launch_bounds__(256, MINCTA) gemm_tc(const float* __restrict__ A, const float* __restrict__ Bt,
                                                       float* __restrict__ C, int M, int N, int K,
                                                       const float* __restrict__ res, const float* __restrict__ mul, int epi)
{
    extern __shared__ float gs[];
    float (*As)[36] = (float(*)[36])gs;                    // [STAGES*128][36]
    float (*Bs)[36] = (float(*)[36])(gs + STAGES*128*36);  // [STAGES*128][36] (n-major)
    int tid = threadIdx.x;
    int m0 = blockIdx.y * 128, n0 = blockIdx.x * 128;
    int w = tid >> 5, lane = tid & 31;
    int wm = (w >> 2) * 64;
    int wn = (w & 3) * 32;

    float acc[4][4][4];
    #pragma unroll
    for (int mi = 0; mi < 4; mi++)
        #pragma unroll
        for (int ni = 0; ni < 4; ni++)
            #pragma unroll
            for (int e = 0; e < 4; e++) acc[mi][ni][e] = 0.f;

    const int NC = K >> 5;

    auto fill = [&](int buf, int k0) {
        #pragma unroll
        for (int i = 0; i < 4; i++) {
            int task = tid + i * 256;
            int r = task >> 3, q = (task & 7) * 4;
            const float* src = A + (size_t)(m0 + r) * K + k0 + q;
            uint32_t dst = (uint32_t)__cvta_generic_to_shared(&As[buf * 128 + r][q]);
            CP_ASYNC16(dst, src, 16);
        }
        #pragma unroll
        for (int i = 0; i < 4; i++) {
            int task = tid + i * 256;
            int r = task >> 3, q = (task & 7) * 4;
            int ok = (n0 + r) < N;
            const float* src = Bt + (size_t)(n0 + r) * K + k0 + q;
            uint32_t dst = (uint32_t)__cvta_generic_to_shared(&Bs[buf * 128 + r][q]);
            CP_ASYNC16(dst, src, ok ? 16 : 0);
        }
    };

    // prologue: STAGES-1 chunks in flight (all GEMMs have K >= 1024 -> NC >= 32)
    #pragma unroll
    for (int i = 0; i < STAGES - 1; i++) { fill(i, i * 32); CP_COMMIT(); }

    int g = lane >> 3, lr8 = lane & 7;
    int arow_l = wm + (g & 1) * 8 + lr8;
    int acol_l = (g >> 1) * 4;
    int brow_l = wn + (g >> 1) * 8 + lr8;
    int bcol_l = (g & 1) * 4;

    int buf = 0;
    for (int ct = 0; ct < NC; ct++) {
        CP_WAIT_N(STAGES - 2);
        __syncthreads();

        const float (*as)[36] = &As[buf * 128];
        const float (*bs)[36] = &Bs[buf * 128];
        #pragma unroll
        for (int ks = 0; ks < 4; ks++) {
            int kb = ks * 8;
            uint32_t af[4][4];
            #pragma unroll
            for (int mi = 0; mi < 4; mi++) {
                uint32_t a = (uint32_t)__cvta_generic_to_shared(&as[arow_l + mi * 16][acol_l + kb]);
                LDMX4(af[mi][0], af[mi][1], af[mi][2], af[mi][3], a);
            }
            uint32_t bf[4][2];
            #pragma unroll
            for (int p = 0; p < 2; p++) {
                uint32_t a = (uint32_t)__cvta_generic_to_shared(&bs[brow_l + p * 16][bcol_l + kb]);
                LDMX4(bf[2*p][0], bf[2*p][1], bf[2*p+1][0], bf[2*p+1][1], a);
            }
            #pragma unroll
            for (int mi = 0; mi < 4; mi++)
                #pragma unroll
                for (int ni = 0; ni < 4; ni++)
                    MMA_TF32(acc[mi][ni], af[mi], bf[ni]);
        }

        int nx = ct + STAGES - 1;
        if (nx < NC) {
            fill(nx % STAGES, nx * 32);
        }
        CP_COMMIT();
        if (++buf == STAGES) buf = 0;
    }

    #pragma unroll
    for (int mi = 0; mi < 4; mi++) {
        int r0 = m0 + wm + mi * 16 + (lane >> 2);
        #pragma unroll
        for (int ni = 0; ni < 4; ni++) {
            int c = n0 + wn + ni * 8 + (lane & 3) * 2;
            if (c < N) {
                #pragma unroll
                for (int half = 0; half < 2; half++) {
                    int r = r0 + half * 8;
                    size_t idx = (size_t)r * N + c;
                    float v0 = acc[mi][ni][half * 2 + 0];
                    float v1 = acc[mi][ni][half * 2 + 1];
                    if (epi == 1) {
                        v0 += res[idx]; v1 += res[idx + 1];
                    } else if (epi == 2) {
                        v0 = fmaxf(v0, 0.f); v0 = tf32r(v0 * v0);
                        v1 = fmaxf(v1, 0.f); v1 = tf32r(v1 * v1);
                    } else if (epi == 3) {
                        v0 = res[idx]     + mul[idx]     / (1.f + expf(-v0));
                        v1 = res[idx + 1] + mul[idx + 1] / (1.f + expf(-v1));
                    }
                    C[idx] = v0; C[idx + 1] = v1;
                }
            }
        }
    }
}
#define GEMM_SMEM_S3 110592
#define GEMM_SMEM_S5 184320

// ---------------- xBC causal depthwise conv (K=4) + silu + fused dt/dA ----------------
// CTA = (batch, 8-timestep block, 256-channel slab): full occupancy AND 4x traffic cut.
#define CTB 8
__global__ void conv_silu_k(const float* __restrict__ cw, const float* __restrict__ cb,
                            const float* __restrict__ dt_bias, const float* __restrict__ A_log) {
    int blk = blockIdx.x;
    int cblk = blk % (XBCD / 256);          // 9 slabs
    int tb = blk / (XBCD / 256);
    int b = tb / (TT / CTB);
    int t0 = (tb % (TT / CTB)) * CTB;
    int c = cblk * 256 + threadIdx.x;

    float w0 = cw[c*4], w1 = cw[c*4+1], w2 = cw[c*4+2], w3 = cw[c*4+3], bb = cb[c];
    float xm3 = (t0 >= 3) ? g_zxb[(size_t)(b * TT + t0 - 3) * ZXB + DI + c] : 0.f;
    float xm2 = (t0 >= 2) ? g_zxb[(size_t)(b * TT + t0 - 2) * ZXB + DI + c] : 0.f;
    float xm1 = (t0 >= 1) ? g_zxb[(size_t)(b * TT + t0 - 1) * ZXB + DI + c] : 0.f;
    #pragma unroll
    for (int j = 0; j < CTB; j++) {
        float x0 = g_zxb[(size_t)(b * TT + t0 + j) * ZXB + DI + c];
        float acc = bb;
        acc = fmaf(w0, xm3, acc); acc = fmaf(w1, xm2, acc);
        acc = fmaf(w2, xm1, acc); acc = fmaf(w3, x0, acc);
        acc = acc / (1.f + expf(-acc));
        g_xBC[(size_t)(b * TT + t0 + j) * XBCD + c] = acc;
        xm3 = xm2; xm2 = xm1; xm1 = x0;
    }
    // fused dt/dA: only slab 0; 256 threads = 8 timesteps x 32 heads
    if (cblk == 0) {
        int h = threadIdx.x & 31, j = threadIdx.x >> 5;
        int bt = b * TT + t0 + j;
        float v = g_zxb[(size_t)bt * ZXB + 4352 + h] + dt_bias[h];
        float sp = (v > 20.f) ? v : log1pf(expf(v));
        g_dt[bt * NH + h] = sp;
        g_dA[bt * NH + h] = expf(sp * (-expf(A_log[h])));
    }
}

// ---------------- SSM scan ----------------
__global__ void scan_k() {
    int bid = blockIdx.x;
    int ns = bid & 1; int bh = bid >> 1; int b = bh >> 5; int h = bh & 31;
    int tid = threadIdx.x;
    int p = tid >> 3;
    int ng = tid & 7;
    __shared__ float sB[16 * 64], sC[16 * 64], sX[16 * 64], sS[16];
    float s[8];
    #pragma unroll
    for (int j = 0; j < 8; j++) s[j] = 0.f;
    int nb = ns * 64;

    for (int ct = 0; ct < TT / 16; ct++) {
        int t0 = ct * 16;
        #pragma unroll
        for (int l = 0; l < 2; l++) {
            int e = tid + l * 512; int tt = e >> 6; int n = e & 63;
            int base = b * TT + t0 + tt;
            sB[e] = g_xBC[(size_t)base * XBCD + DI + nb + n];
            sC[e] = g_xBC[(size_t)base * XBCD + DI + DS + nb + n];
            sX[e] = g_xBC[(size_t)base * XBCD + h * 64 + n] * g_dt[base * NH + h];
        }
        if (tid < 16) sS[tid] = g_dA[(b * TT + t0 + tid) * NH + h];
        __syncthreads();
        for (int tt = 0; tt < 16; tt++) {
            float da = sS[tt];
            float dtx = sX[tt * 64 + p];
            float bb[8], cc[8];
            *(float4*)&bb[0] = *(float4*)&sB[tt * 64 + ng * 8];
            *(float4*)&bb[4] = *(float4*)&sB[tt * 64 + ng * 8 + 4];
            *(float4*)&cc[0] = *(float4*)&sC[tt * 64 + ng * 8];
            *(float4*)&cc[4] = *(float4*)&sC[tt * 64 + ng * 8 + 4];
            float acc = 0.f;
            #pragma unroll
            for (int j = 0; j < 8; j++) {
                s[j] = fmaf(s[j], da, dtx * bb[j]);
                acc = fmaf(s[j], cc[j], acc);
            }
            acc += __shfl_xor_sync(0xffffffffu, acc, 1);
            acc += __shfl_xor_sync(0xffffffffu, acc, 2);
            acc += __shfl_xor_sync(0xffffffffu, acc, 4);
            if (ng == 0)
                g_yp[(size_t)ns * (BT * DI) + (size_t)(b * TT + t0 + tt) * DI + h * 64 + p] = acc;
        }
        __syncthreads();
    }
}

__global__ void gate_k(const float* __restrict__ Dm, const float* __restrict__ mnw) {
    int bt = blockIdx.x;
    float ss = 0.f;
    for (int c = threadIdx.x; c < DI; c += blockDim.x) {
        float v = g_yp[(size_t)bt * DI + c] + g_yp[(size_t)BT * DI + (size_t)bt * DI + c]
                + g_xBC[(size_t)bt * XBCD + c] * Dm[c >> 6];
        float z = g_zxb[(size_t)bt * ZXB + c];
        v *= z / (1.f + expf(-z));
        g_y2[(size_t)bt * DI + c] = v;
        ss = fmaf(v, v, ss);
    }
    ss = block_sum(ss);
    float sc = rsqrtf(ss / (float)DI + 1e-5f);
    for (int c = threadIdx.x; c < DI; c += blockDim.x)
        g_y2[(size_t)bt * DI + c] = tf32r(g_y2[(size_t)bt * DI + c] * sc * mnw[c]);
}

// ---------------- q/k/v causal depthwise conv (K=3), channel-slab blocking -----------
__global__ void convqkv_k(const float* __restrict__ qw, const float* __restrict__ qb,
                          const float* __restrict__ kw, const float* __restrict__ kb,
                          const float* __restrict__ vw, const float* __restrict__ vb) {
    int blk = blockIdx.x;
    int cblk = blk % 5;                     // 5 slabs of 256 (last partial: 1152-1024=128)
    int tb = blk / 5;
    int b = tb / (TT / CTB);
    int t0 = (tb % (TT / CTB)) * CTB;
    int c = cblk * 256 + threadIdx.x;
    if (c >= QKVD) return;

    const float* w; const float* bias; int d;
    if (c < DM)            { d = c & 63;        w = qw; bias = qb; }
    else if (c < DM + 64)  { d = c - DM;        w = kw; bias = kb; }
    else                   { d = c - DM - 64;   w = vw; bias = vb; }
    float w0 = w[d*3], w1 = w[d*3+1], w2 = w[d*3+2], bb = bias[d];
    float xm2 = (t0 >= 2) ? g_qkv[(size_t)(b * TT + t0 - 2) * QKVD + c] : 0.f;
    float xm1 = (t0 >= 1) ? g_qkv[(size_t)(b * TT + t0 - 1) * QKVD + c] : 0.f;
    #pragma unroll
    for (int j = 0; j < CTB; j++) {
        int bt = b * TT + t0 + j;
        float x0 = g_qkv[(size_t)bt * QKVD + c];
        float acc = bb;
        acc = fmaf(w0, xm2, acc); acc = fmaf(w1, xm1, acc); acc = fmaf(w2, x0, acc);
        if (c < DM)           g_qc[(size_t)bt * DM + c] = acc;
        else if (c < DM + 64) g_kc[(size_t)bt * 64 + d] = acc;
        else                  g_vc[(size_t)bt * 64 + d] = acc;
        xm2 = xm1; xm1 = x0;
    }
}

// ---------------- fused causal attention (tf32 mma, online softmax) ----------------
#define ATTN_SMEM 69632
__global__ void __launch_bounds__(128) attn_k() {
    extern __shared__ float sm[];
    float* qs = sm;              // [64][68] tf32, pre-scaled
    float* ks = sm + 4352;       // [64][68] tf32
    float* vT = sm + 8704;       // [64][68] tf32 (V transposed)
    float* ps = sm + 13056;      // [64][68] tf32 (P)
    int bid = blockIdx.x;
    int qb = bid & 15; int h = (bid >> 4) & 15; int b = bid >> 8;
    int tid = threadIdx.x;
    int w = tid >> 5, lane = tid & 31;
    int lr = lane >> 2, lc = lane & 3;

    {
        int r = tid >> 1, d0 = (tid & 1) * 32;
        const float* qp = &g_qc[(size_t)(b * TT + qb * 64 + r) * DM + h * 64 + d0];
        #pragma unroll
        for (int j = 0; j < 8; j++) {
            float4 v = *(const float4*)(qp + j * 4);
            *(float4*)&qs[r * 68 + d0 + j * 4] =
                make_float4(tf32r(v.x * 0.125f), tf32r(v.y * 0.125f),
                            tf32r(v.z * 0.125f), tf32r(v.w * 0.125f));
        }
    }

    float m[2] = {-1e30f, -1e30f}, l[2] = {0.f, 0.f};
    float o[8][4];
    #pragma unroll
    for (int ni = 0; ni < 8; ni++)
        #pragma unroll
        for (int e = 0; e < 4; e++) o[ni][e] = 0.f;

    for (int kb = 0; kb <= qb; kb++) {
        __syncthreads();
        {
            int r = tid >> 1, d0 = (tid & 1) * 32;
            const float* kp = &g_kc[(size_t)(b * TT + kb * 64 + r) * 64 + d0];
            const float* vp = &g_vc[(size_t)(b * TT + kb * 64 + r) * 64 + d0];
            #pragma unroll
            for (int j = 0; j < 8; j++) {
                float4 kv = *(const float4*)(kp + j * 4);
                *(float4*)&ks[r * 68 + d0 + j * 4] =
                    make_float4(tf32r(kv.x), tf32r(kv.y), tf32r(kv.z), tf32r(kv.w));
                float4 vv = *(const float4*)(vp + j * 4);
                int d = d0 + j * 4;
                vT[(d + 0) * 68 + r] = tf32r(vv.x); vT[(d + 1) * 68 + r] = tf32r(vv.y);
                vT[(d + 2) * 68 + r] = tf32r(vv.z); vT[(d + 3) * 68 + r] = tf32r(vv.w);
            }
        }
        __syncthreads();

        float sc[8][4];
        #pragma unroll
        for (int ni = 0; ni < 8; ni++)
            #pragma unroll
            for (int e = 0; e < 4; e++) sc[ni][e] = 0.f;
        #pragma unroll
        for (int ksx = 0; ksx < 8; ksx++) {
            int k8 = ksx * 8;
            int r = w * 16 + lr;
            uint32_t af[4];
            af[0] = __float_as_uint(qs[r * 68 + k8 + lc]);
            af[1] = __float_as_uint(qs[(r + 8) * 68 + k8 + lc]);
            af[2] = __float_as_uint(qs[r * 68 + k8 + lc + 4]);
            af[3] = __float_as_uint(qs[(r + 8) * 68 + k8 + lc + 4]);
            #pragma unroll
            for (int ni = 0; ni < 8; ni++) {
                int n = ni * 8 + lr;
                uint32_t bf[2];
                bf[0] = __float_as_uint(ks[n * 68 + k8 + lc]);
                bf[1] = __float_as_uint(ks[n * 68 + k8 + lc + 4]);
                MMA_TF32(sc[ni], af, bf);
            }
        }

        bool diag = (kb == qb);
        #pragma unroll
        for (int h2 = 0; h2 < 2; h2++) {
            int row = w * 16 + lr + h2 * 8;
            if (diag) {
                #pragma unroll
                for (int ni = 0; ni < 8; ni++) {
                    int c0 = ni * 8 + lc * 2;
                    if (c0 > row)     sc[ni][h2 * 2 + 0] = -1e30f;
                    if (c0 + 1 > row) sc[ni][h2 * 2 + 1] = -1e30f;
                }
            }
            float mx = -1e30f;
            #pragma unroll
            for (int ni = 0; ni < 8; ni++)
                mx = fmaxf(mx, fmaxf(sc[ni][h2 * 2], sc[ni][h2 * 2 + 1]));
            mx = fmaxf(mx, __shfl_xor_sync(0xffffffffu, mx, 1));
            mx = fmaxf(mx, __shfl_xor_sync(0xffffffffu, mx, 2));
            float mn = fmaxf(m[h2], mx);
            float alpha = __expf(m[h2] - mn);
            m[h2] = mn;
            float rs = 0.f;
            #pragma unroll
            for (int ni = 0; ni < 8; ni++) {
                float p0 = __expf(sc[ni][h2 * 2]     - mn);
                float p1 = __expf(sc[ni][h2 * 2 + 1] - mn);
                rs += p0 + p1;
                *(float2*)&ps[row * 68 + ni * 8 + lc * 2] = make_float2(tf32r(p0), tf32r(p1));
            }
            rs += __shfl_xor_sync(0xffffffffu, rs, 1);
            rs += __shfl_xor_sync(0xffffffffu, rs, 2);
            l[h2] = l[h2] * alpha + rs;
            #pragma unroll
            for (int ni = 0; ni < 8; ni++) {
                o[ni][h2 * 2]     *= alpha;
                o[ni][h2 * 2 + 1] *= alpha;
            }
        }
        __syncwarp();

        #pragma unroll
        for (int ksx = 0; ksx < 8; ksx++) {
            int k8 = ksx * 8;
            int r = w * 16 + lr;
            uint32_t af[4];
            af[0] = __float_as_uint(ps[r * 68 + k8 + lc]);
            af[1] = __float_as_uint(ps[(r + 8) * 68 + k8 + lc]);
            af[2] = __float_as_uint(ps[r * 68 + k8 + lc + 4]);
            af[3] = __float_as_uint(ps[(r + 8) * 68 + k8 + lc + 4]);
            #pragma unroll
            for (int ni = 0; ni < 8; ni++) {
                int n = ni * 8 + lr;
                uint32_t bf[2];
                bf[0] = __float_as_uint(vT[n * 68 + k8 + lc]);
                bf[1] = __float_as_uint(vT[n * 68 + k8 + lc + 4]);
                MMA_TF32(o[ni], af, bf);
            }
        }
    }

    #pragma unroll
    for (int h2 = 0; h2 < 2; h2++) {
        float inv = 1.f / l[h2];
        int r = qb * 64 + w * 16 + lr + h2 * 8;
        #pragma unroll
        for (int ni = 0; ni < 8; ni++) {
            float2 v = make_float2(tf32r(o[ni][h2 * 2] * inv), tf32r(o[ni][h2 * 2 + 1] * inv));
            *(float2*)&g_att[(size_t)(b * TT + r) * DM + h * 64 + ni * 8 + lc * 2] = v;
        }
    }
}

// ---------------- host launch ----------------
static void run_gemm(const float* A, const float* Wt, float* C, int M, int N, int K,
                     const float* res, const float* mul, int epi) {
    dim3 grid((N + 127) / 128, M / 128);
    if (N <= 1536) {
        gemm_tc<5, 1><<<grid, 256, GEMM_SMEM_S5>>>(A, Wt, C, M, N, K, res, mul, epi);
    } else {
        gemm_tc<3, 2><<<grid, 256, GEMM_SMEM_S3>>>(A, Wt, C, M, N, K, res, mul, epi);
    }
}

extern "C" void kernel_launch(void* const* d_in, const int* in_sizes, int n_in,
                              void* d_out, int out_size) {
    const float* x       = (const float*)d_in[0];
    const float* W_in    = (const float*)d_in[1];
    const float* conv_w  = (const float*)d_in[2];
    const float* conv_b  = (const float*)d_in[3];
    const float* A_log   = (const float*)d_in[4];
    const float* Dm      = (const float*)d_in[5];
    const float* dt_bias = (const float*)d_in[6];
    const float* mnorm_w = (const float*)d_in[7];
    const float* W_out   = (const float*)d_in[8];
    const float* W_qkv   = (const float*)d_in[9];
    const float* W_cproj = (const float*)d_in[10];
    const float* qconv_w = (const float*)d_in[11];
    const float* qconv_b = (const float*)d_in[12];
    const float* kconv_w = (const float*)d_in[13];
    const float* kconv_b = (const float*)d_in[14];
    const float* vconv_w = (const float*)d_in[15];
    const float* vconv_b = (const float*)d_in[16];
    const float* tmk     = (const float*)d_in[17];
    const float* tmr     = (const float*)d_in[18];
    const float* W_key   = (const float*)d_in[19];
    const float* W_rec   = (const float*)d_in[20];
    const float* W_val   = (const float*)d_in[21];
    float* out = (float*)d_out;

    float *p_h, *p_zxb, *p_y2, *p_x2, *p_qkv, *p_att, *p_x3, *p_xk, *p_xr, *p_kf, *p_kv, *p_wt;
    cudaGetSymbolAddress((void**)&p_h, g_h);
    cudaGetSymbolAddress((void**)&p_zxb, g_zxb);
    cudaGetSymbolAddress((void**)&p_y2, g_y2);
    cudaGetSymbolAddress((void**)&p_x2, g_x2);
    cudaGetSymbolAddress((void**)&p_qkv, g_qkv);
    cudaGetSymbolAddress((void**)&p_att, g_att);
    cudaGetSymbolAddress((void**)&p_x3, g_x3);
    cudaGetSymbolAddress((void**)&p_xk, g_xk);
    cudaGetSymbolAddress((void**)&p_xr, g_xr);
    cudaGetSymbolAddress((void**)&p_kf, g_kf);
    cudaGetSymbolAddress((void**)&p_kv, g_kv);
    cudaGetSymbolAddress((void**)&p_wt, g_wt);

    cudaFuncSetAttribute(attn_k, cudaFuncAttributeMaxDynamicSharedMemorySize, ATTN_SMEM);
    cudaFuncSetAttribute(gemm_tc<3, 2>, cudaFuncAttributeMaxDynamicSharedMemorySize, GEMM_SMEM_S3);
    cudaFuncSetAttribute(gemm_tc<5, 1>, cudaFuncAttributeMaxDynamicSharedMemorySize, GEMM_SMEM_S5);

    // ---- weight tf32 round + transpose, single launch ----
    {
        WTab wt;
        const float* srcs[7] = {W_in, W_out, W_qkv, W_cproj, W_key, W_val, W_rec};
        int offs[7] = {OW_IN, OW_OUT, OW_QKV, OW_CPROJ, OW_KEY, OW_VAL, OW_REC};
        int Ks[7]   = {DM, DI, DM, DM, DM, FFND, DM};
        int Ns[7]   = {ZXB, DM, QKVD, DM, FFND, DM, DM};
        int acc = 0;
        for (int i = 0; i < 7; i++) {
            wt.src[i] = srcs[i]; wt.off[i] = offs[i]; wt.K[i] = Ks[i]; wt.N[i] = Ns[i];
            wt.tstart[i] = acc;
            acc += (Ks[i] >> 5) * (Ns[i] >> 5);
        }
        wt.tstart[7] = acc;
        cvtall_k<<<acc, dim3(32, 8)>>>(wt);
    }

    // ---- Mamba2-style block ----
    rmsnorm_k<<<BT, 256>>>(x, p_h, 1e-6f, 1);
    run_gemm(p_h, p_wt + OW_IN, p_zxb, BT, ZXB, DM, nullptr, nullptr, 0);
    conv_silu_k<<<(BT / CTB) * (XBCD / 256), 256>>>(conv_w, conv_b, dt_bias, A_log);
    scan_k<<<128, 512>>>();
    gate_k<<<BT, 256>>>(Dm, mnorm_w);
    run_gemm(p_y2, p_wt + OW_OUT, p_x2, BT, DM, DI, x, nullptr, 1);

    // ---- attention block ----
    rmsnorm_k<<<BT, 256>>>(p_x2, p_h, 1e-6f, 1);
    run_gemm(p_h, p_wt + OW_QKV, p_qkv, BT, QKVD, DM, nullptr, nullptr, 0);
    convqkv_k<<<(BT / CTB) * 5, 256>>>(qconv_w, qconv_b, kconv_w, kconv_b, vconv_w, vconv_b);
    attn_k<<<BSZ * NHA * (TT / 64), 128, ATTN_SMEM>>>();
    run_gemm(p_att, p_wt + OW_CPROJ, p_x3, BT, DM, DM, p_x2, nullptr, 1);

    // ---- channel mix ----
    rmsshift_k<<<BT, 256>>>(p_x3, tmk, tmr, p_xk, p_xr);
    run_gemm(p_xk, p_wt + OW_KEY, p_kf, BT, FFND, DM, nullptr, nullptr, 2);
    run_gemm(p_kf, p_wt + OW_VAL, p_kv, BT, DM, FFND, nullptr, nullptr, 0);
    run_gemm(p_xr, p_wt + OW_REC, out, BT, DM, DM, p_x3, p_kv, 3);
}

// round 14
// speedup vs baseline: 1.0397x; 1.0003x over previous
#include <cuda_runtime.h>
#include <math.h>
#include <stdint.h>

#define BSZ 2
#define TT 1024
#define DM 1024
#define DI 2048
#define DS 128
#define NH 32
#define HDS 64
#define NHA 16
#define HDA 64
#define FFND 4096
#define ZXB 4384
#define XBCD 2304
#define QKVD 1152
#define BT (BSZ*TT)

// ---------------- scratch (device globals; no allocations allowed) ----------------
__device__ float g_h[BT*DM];
__device__ float g_zxb[BT*ZXB];
__device__ float g_xBC[BT*XBCD];
__device__ float g_dt[BT*NH];
__device__ float g_dA[BT*NH];
__device__ float g_yp[2*BT*DI];
__device__ float g_y2[BT*DI];
__device__ float g_x2[BT*DM];
__device__ float g_qkv[BT*QKVD];
__device__ float g_qc[BT*DM];
__device__ float g_kc[BT*HDA];
__device__ float g_vc[BT*HDA];
__device__ float g_att[BT*DM];
__device__ float g_x3[BT*DM];
__device__ float g_xk[BT*DM];
__device__ float g_xr[BT*DM];
__device__ float g_kf[BT*FFND];
__device__ float g_kv[BT*DM];
__device__ float g_wt[18251776];      // tf32-rounded TRANSPOSED weights [N][K] (73MB)
__device__ float g_sk[2*BT*QKVD];     // split-K partial sums (max N=1152, 18.9MB)

// weight offsets in g_wt
#define OW_IN    0
#define OW_OUT   4489216
#define OW_QKV   6586368
#define OW_CPROJ 7766016
#define OW_KEY   8814592
#define OW_VAL   13008896
#define OW_REC   17203200

// ---------------- helpers ----------------
__device__ __forceinline__ uint32_t f2tf32(float x) {
    uint32_t r; asm("cvt.rna.tf32.f32 %0, %1;" : "=r"(r) : "f"(x)); return r;
}
__device__ __forceinline__ float tf32r(float x) { return __uint_as_float(f2tf32(x)); }

__device__ __forceinline__ float block_sum(float v) {
    __shared__ float red[32];
    int lane = threadIdx.x & 31, w = threadIdx.x >> 5;
    #pragma unroll
    for (int o = 16; o; o >>= 1) v += __shfl_xor_sync(0xffffffffu, v, o);
    if (lane == 0) red[w] = v;
    __syncthreads();
    int nw = blockDim.x >> 5;
    float r = (threadIdx.x < nw) ? red[threadIdx.x] : 0.f;
    if (w == 0) {
        #pragma unroll
        for (int o = 16; o; o >>= 1) r += __shfl_xor_sync(0xffffffffu, r, o);
        if (lane == 0) red[0] = r;
    }
    __syncthreads();
    return red[0];
}

__global__ void rmsnorm_k(const float* __restrict__ x, float* __restrict__ o, float eps, int rnd) {
    int row = blockIdx.x;
    const float* xr = x + (size_t)row * DM;
    float ss = 0.f;
    for (int c = threadIdx.x; c < DM; c += blockDim.x) { float v = xr[c]; ss = fmaf(v, v, ss); }
    ss = block_sum(ss);
    float sc = rsqrtf(ss / (float)DM + eps);
    float* orow = o + (size_t)row * DM;
    if (rnd) for (int c = threadIdx.x; c < DM; c += blockDim.x) orow[c] = tf32r(xr[c] * sc);
    else     for (int c = threadIdx.x; c < DM; c += blockDim.x) orow[c] = xr[c] * sc;
}

// ---------------- fused rmsnorm + token-shift (channel mix) ----------------
__global__ void rmsshift_k(const float* __restrict__ x3,
                           const float* __restrict__ tmk, const float* __restrict__ tmr,
                           float* __restrict__ xk, float* __restrict__ xr) {
    int bt = blockIdx.x; int t = bt & 1023;
    const float* cur = x3 + (size_t)bt * DM;
    const float* prv = x3 + (size_t)(bt - 1) * DM;
    float sa = 0.f, sb = 0.f;
    for (int c = threadIdx.x; c < DM; c += blockDim.x) {
        float v = cur[c]; sa = fmaf(v, v, sa);
        float p = t ? prv[c] : 0.f; sb = fmaf(p, p, sb);
    }
    float ra = block_sum(sa);
    __syncthreads();
    float rb = block_sum(sb);
    float scc = rsqrtf(ra / (float)DM + 1e-6f);
    float scp = rsqrtf(rb / (float)DM + 1e-6f);
    for (int c = threadIdx.x; c < DM; c += blockDim.x) {
        float h = cur[c] * scc;
        float hp = t ? prv[c] * scp : 0.f;
        float dd = hp - h;
        xk[(size_t)bt * DM + c] = tf32r(fmaf(dd, tmk[c], h));
        xr[(size_t)bt * DM + c] = tf32r(fmaf(dd, tmr[c], h));
    }
}

// ---------------- merged weight tf32 round + transpose (all 7 weights, one launch) ----
struct WTab {
    const float* src[7];
    int off[7];
    int K[7], N[7];
    int tstart[8];
};
__global__ void cvtall_k(WTab wt) {
    __shared__ float t[32][33];
    int bidx = blockIdx.x;
    int w = 0;
    #pragma unroll
    for (int i = 1; i < 7; i++) if (bidx >= wt.tstart[i]) w = i;
    int tloc = bidx - wt.tstart[w];
    int K = wt.K[w], N = wt.N[w];
    int ntn = N >> 5;
    int k0 = (tloc / ntn) << 5, n0 = (tloc % ntn) << 5;
    const float* in = wt.src[w];
    float* out = g_wt + wt.off[w];
    int x = threadIdx.x, y = threadIdx.y;
    #pragma unroll
    for (int i = 0; i < 32; i += 8)
        t[y + i][x] = tf32r(in[(size_t)(k0 + y + i) * N + n0 + x]);
    __syncthreads();
    #pragma unroll
    for (int i = 0; i < 32; i += 8)
        out[(size_t)(n0 + y + i) * K + k0 + x] = t[x][y + i];
}

// ================= tf32 mma.sync GEMM (ldmatrix, 3-stage pipeline, optional split-K) =
#define CP_ASYNC16(dst, src, sz) \
    asm volatile("cp.async.cg.shared.global [%0], [%1], 16, %2;" :: "r"(dst), "l"(src), "r"(sz) : "memory")
#define CP_COMMIT() asm volatile("cp.async.commit_group;" ::: "memory")
#define CP_WAIT_N(n) asm volatile("cp.async.wait_group %0;" :: "n"(n) : "memory")
#define MMA_TF32(d, a, b) \
    asm volatile("mma.sync.aligned.m16n8k8.row.col.f32.tf32.tf32.f32 " \
        "{%0,%1,%2,%3}, {%4,%5,%6,%7}, {%8,%9}, {%0,%1,%2,%3};" \
        : "+f"((d)[0]), "+f"((d)[1]), "+f"((d)[2]), "+f"((d)[3]) \
        : "r"((a)[0]), "r"((a)[1]), "r"((a)[2]), "r"((a)[3]), "r"((b)[0]), "r"((b)[1]))
#define LDMX4(r0, r1, r2, r3, a) \
    asm volatile("ldmatrix.sync.aligned.m8n8.x4.shared.b16 {%0,%1,%2,%3}, [%4];" \
        : "=r"(r0), "=r"(r1), "=r"(r2), "=r"(r3) : "r"(a))

// C[M,N] = A[M,K] @ Bt[N,K]^T. SPLITK: blockIdx.z halves the K range; raw partials out.
template<bool SPLITK>
__global__ void __launch_bounds__(256, 2) gemm_tc(const float* __restrict__ A, const float* __restrict__ Bt,
                                                  float* __restrict__ C, int M, int N, int K,
                                                  const float* __restrict__ res, const float* __restrict__ mul, int epi)
{
    extern __shared__ float gs[];
    float (*As)[36] = (float(*)[36])gs;               // [3*128][36]
    float (*Bs)[36] = (float(*)[36])(gs + 3*128*36);  // [3*128][36] (n-major)
    int tid = threadIdx.x;
    int m0 = blockIdx.y * 128, n0 = blockIdx.x * 128;
    int kz = SPLITK ? blockIdx.z : 0;
    int Keff = SPLITK ? (K >> 1) : K;
    int kzoff = kz * Keff;
    int w = tid >> 5, lane = tid & 31;
    int wm = (w >> 2) * 64;
    int wn = (w & 3) * 32;

    float acc[4][4][4];
    #pragma unroll
    for (int mi = 0; mi < 4; mi++)
        #pragma unroll
        for (int ni = 0; ni < 4; ni++)
            #pragma unroll
            for (int e = 0; e < 4; e++) acc[mi][ni][e] = 0.f;

    const int NC = Keff >> 5;

    auto fill = [&](int buf, int k0) {
        #pragma unroll
        for (int i = 0; i < 4; i++) {
            int task = tid + i * 256;
            int r = task >> 3, q = (task & 7) * 4;
            const float* src = A + (size_t)(m0 + r) * K + k0 + q;
            uint32_t dst = (uint32_t)__cvta_generic_to_shared(&As[buf * 128 + r][q]);
            CP_ASYNC16(dst, src, 16);
        }
        #pragma unroll
        for (int i = 0; i < 4; i++) {
            int task = tid + i * 256;
            int r = task >> 3, q = (task & 7) * 4;
            int ok = (n0 + r) < N;
            const float* src = Bt + (size_t)(n0 + r) * K + k0 + q;
            uint32_t dst = (uint32_t)__cvta_generic_to_shared(&Bs[buf * 128 + r][q]);
            CP_ASYNC16(dst, src, ok ? 16 : 0);
        }
    };

    fill(0, kzoff);      CP_COMMIT();
    fill(1, kzoff + 32); CP_COMMIT();   // NC >= 16 always

    int g = lane >> 3, lr8 = lane & 7;
    int arow_l = wm + (g & 1) * 8 + lr8;
    int acol_l = (g >> 1) * 4;
    int brow_l = wn + (g >> 1) * 8 + lr8;
    int bcol_l = (g & 1) * 4;

    int buf = 0;
    for (int ct = 0; ct < NC; ct++) {
        CP_WAIT_N(1);
        __syncthreads();

        const float (*as)[36] = &As[buf * 128];
        const float (*bs)[36] = &Bs[buf * 128];
        #pragma unroll
        for (int ks = 0; ks < 4; ks++) {
            int kb = ks * 8;
            uint32_t af[4][4];
            #pragma unroll
            for (int mi = 0; mi < 4; mi++) {
                uint32_t a = (uint32_t)__cvta_generic_to_shared(&as[arow_l + mi * 16][acol_l + kb]);
                LDMX4(af[mi][0], af[mi][1], af[mi][2], af[mi][3], a);
            }
            uint32_t bf[4][2];
            #pragma unroll
            for (int p = 0; p < 2; p++) {
                uint32_t a = (uint32_t)__cvta_generic_to_shared(&bs[brow_l + p * 16][bcol_l + kb]);
                LDMX4(bf[2*p][0], bf[2*p][1], bf[2*p+1][0], bf[2*p+1][1], a);
            }
            #pragma unroll
            for (int mi = 0; mi < 4; mi++)
                #pragma unroll
                for (int ni = 0; ni < 4; ni++)
                    MMA_TF32(acc[mi][ni], af[mi], bf[ni]);
        }

        int nx = ct + 2;
        if (nx < NC) fill(nx % 3, kzoff + nx * 32);
        CP_COMMIT();
        if (++buf == 3) buf = 0;
    }

    float* Co = SPLITK ? (C + (size_t)kz * M * N) : C;
    #pragma unroll
    for (int mi = 0; mi < 4; mi++) {
        int r0 = m0 + wm + mi * 16 + (lane >> 2);
        #pragma unroll
        for (int ni = 0; ni < 4; ni++) {
            int c = n0 + wn + ni * 8 + (lane & 3) * 2;
            if (c < N) {
                #pragma unroll
                for (int half = 0; half < 2; half++) {
                    int r = r0 + half * 8;
                    size_t idx = (size_t)r * N + c;
                    float v0 = acc[mi][ni][half * 2 + 0];
                    float v1 = acc[mi][ni][half * 2 + 1];
                    if (!SPLITK) {
                        if (epi == 1) {
                            v0 += res[idx]; v1 += res[idx + 1];
                        } else if (epi == 2) {
                            v0 = fmaxf(v0, 0.f); v0 = tf32r(v0 * v0);
                            v1 = fmaxf(v1, 0.f); v1 = tf32r(v1 * v1);
                        } else if (epi == 3) {
                            v0 = res[idx]     + mul[idx]     / (1.f + expf(-v0));
                            v1 = res[idx + 1] + mul[idx + 1] / (1.f + expf(-v1));
                        }
                    }
                    Co[idx] = v0; Co[idx + 1] = v1;
                }
            }
        }
    }
}
#define GEMM_SMEM_S3 110592

// ---------------- split-K combine + fused epilogue ----------------
__global__ void combine_k(const float* __restrict__ p, float* __restrict__ C,
                          const float* __restrict__ res, const float* __restrict__ mul,
                          int epi, int MN) {
    int i = (blockIdx.x * blockDim.x + threadIdx.x) * 2;
    if (i >= MN) return;
    float2 a = *(const float2*)(p + i);
    float2 b = *(const float2*)(p + MN + i);
    float v0 = a.x + b.x, v1 = a.y + b.y;
    if (epi == 1) {
        v0 += res[i]; v1 += res[i + 1];
    } else if (epi == 3) {
        v0 = res[i]     + mul[i]     / (1.f + expf(-v0));
        v1 = res[i + 1] + mul[i + 1] / (1.f + expf(-v1));
    }
    *(float2*)(C + i) = make_float2(v0, v1);
}

// ---------------- xBC causal depthwise conv (K=4) + silu + fused dt/dA ----------------
#define CTB 8
__global__ void conv_silu_k(const float* __restrict__ cw, const float* __restrict__ cb,
                            const float* __restrict__ dt_bias, const float* __restrict__ A_log) {
    int blk = blockIdx.x;
    int cblk = blk % (XBCD / 256);          // 9 slabs
    int tb = blk / (XBCD / 256);
    int b = tb / (TT / CTB);
    int t0 = (tb % (TT / CTB)) * CTB;
    int c = cblk * 256 + threadIdx.x;

    float w0 = cw[c*4], w1 = cw[c*4+1], w2 = cw[c*4+2], w3 = cw[c*4+3], bb = cb[c];
    float xm3 = (t0 >= 3) ? g_zxb[(size_t)(b * TT + t0 - 3) * ZXB + DI + c] : 0.f;
    float xm2 = (t0 >= 2) ? g_zxb[(size_t)(b * TT + t0 - 2) * ZXB + DI + c] : 0.f;
    float xm1 = (t0 >= 1) ? g_zxb[(size_t)(b * TT + t0 - 1) * ZXB + DI + c] : 0.f;
    #pragma unroll
    for (int j = 0; j < CTB; j++) {
        float x0 = g_zxb[(size_t)(b * TT + t0 + j) * ZXB + DI + c];
        float acc = bb;
        acc = fmaf(w0, xm3, acc); acc = fmaf(w1, xm2, acc);
        acc = fmaf(w2, xm1, acc); acc = fmaf(w3, x0, acc);
        acc = acc / (1.f + expf(-acc));
        g_xBC[(size_t)(b * TT + t0 + j) * XBCD + c] = acc;
        xm3 = xm2; xm2 = xm1; xm1 = x0;
    }
    if (cblk == 0) {
        int h = threadIdx.x & 31, j = threadIdx.x >> 5;
        int bt = b * TT + t0 + j;
        float v = g_zxb[(size_t)bt * ZXB + 4352 + h] + dt_bias[h];
        float sp = (v > 20.f) ? v : log1pf(expf(v));
        g_dt[bt * NH + h] = sp;
        g_dA[bt * NH + h] = expf(sp * (-expf(A_log[h])));
    }
}

// ---------------- SSM scan ----------------
__global__ void scan_k() {
    int bid = blockIdx.x;
    int ns = bid & 1; int bh = bid >> 1; int b = bh >> 5; int h = bh & 31;
    int tid = threadIdx.x;
    int p = tid >> 3;
    int ng = tid & 7;
    __shared__ float sB[16 * 64], sC[16 * 64], sX[16 * 64], sS[16];
    float s[8];
    #pragma unroll
    for (int j = 0; j < 8; j++) s[j] = 0.f;
    int nb = ns * 64;

    for (int ct = 0; ct < TT / 16; ct++) {
        int t0 = ct * 16;
        #pragma unroll
        for (int l = 0; l < 2; l++) {
            int e = tid + l * 512; int tt = e >> 6; int n = e & 63;
            int base = b * TT + t0 + tt;
            sB[e] = g_xBC[(size_t)base * XBCD + DI + nb + n];
            sC[e] = g_xBC[(size_t)base * XBCD + DI + DS + nb + n];
            sX[e] = g_xBC[(size_t)base * XBCD + h * 64 + n] * g_dt[base * NH + h];
        }
        if (tid < 16) sS[tid] = g_dA[(b * TT + t0 + tid) * NH + h];
        __syncthreads();
        for (int tt = 0; tt < 16; tt++) {
            float da = sS[tt];
            float dtx = sX[tt * 64 + p];
            float bb[8], cc[8];
            *(float4*)&bb[0] = *(float4*)&sB[tt * 64 + ng * 8];
            *(float4*)&bb[4] = *(float4*)&sB[tt * 64 + ng * 8 + 4];
            *(float4*)&cc[0] = *(float4*)&sC[tt * 64 + ng * 8];
            *(float4*)&cc[4] = *(float4*)&sC[tt * 64 + ng * 8 + 4];
            float acc = 0.f;
            #pragma unroll
            for (int j = 0; j < 8; j++) {
                s[j] = fmaf(s[j], da, dtx * bb[j]);
                acc = fmaf(s[j], cc[j], acc);
            }
            acc += __shfl_xor_sync(0xffffffffu, acc, 1);
            acc += __shfl_xor_sync(0xffffffffu, acc, 2);
            acc += __shfl_xor_sync(0xffffffffu, acc, 4);
            if (ng == 0)
                g_yp[(size_t)ns * (BT * DI) + (size_t)(b * TT + t0 + tt) * DI + h * 64 + p] = acc;
        }
        __syncthreads();
    }
}

__global__ void gate_k(const float* __restrict__ Dm, const float* __restrict__ mnw) {
    int bt = blockIdx.x;
    float ss = 0.f;
    for (int c = threadIdx.x; c < DI; c += blockDim.x) {
        float v = g_yp[(size_t)bt * DI + c] + g_yp[(size_t)BT * DI + (size_t)bt * DI + c]
                + g_xBC[(size_t)bt * XBCD + c] * Dm[c >> 6];
        float z = g_zxb[(size_t)bt * ZXB + c];
        v *= z / (1.f + expf(-z));
        g_y2[(size_t)bt * DI + c] = v;
        ss = fmaf(v, v, ss);
    }
    ss = block_sum(ss);
    float sc = rsqrtf(ss / (float)DI + 1e-5f);
    for (int c = threadIdx.x; c < DI; c += blockDim.x)
        g_y2[(size_t)bt * DI + c] = tf32r(g_y2[(size_t)bt * DI + c] * sc * mnw[c]);
}

// ---------------- q/k/v causal depthwise conv (K=3), channel-slab blocking -----------
__global__ void convqkv_k(const float* __restrict__ qw, const float* __restrict__ qb,
                          const float* __restrict__ kw, const float* __restrict__ kb,
                          const float* __restrict__ vw, const float* __restrict__ vb) {
    int blk = blockIdx.x;
    int cblk = blk % 5;
    int tb = blk / 5;
    int b = tb / (TT / CTB);
    int t0 = (tb % (TT / CTB)) * CTB;
    int c = cblk * 256 + threadIdx.x;
    if (c >= QKVD) return;

    const float* w; const float* bias; int d;
    if (c < DM)            { d = c & 63;        w = qw; bias = qb; }
    else if (c < DM + 64)  { d = c - DM;        w = kw; bias = kb; }
    else                   { d = c - DM - 64;   w = vw; bias = vb; }
    float w0 = w[d*3], w1 = w[d*3+1], w2 = w[d*3+2], bb = bias[d];
    float xm2 = (t0 >= 2) ? g_qkv[(size_t)(b * TT + t0 - 2) * QKVD + c] : 0.f;
    float xm1 = (t0 >= 1) ? g_qkv[(size_t)(b * TT + t0 - 1) * QKVD + c] : 0.f;
    #pragma unroll
    for (int j = 0; j < CTB; j++) {
        int bt = b * TT + t0 + j;
        float x0 = g_qkv[(size_t)bt * QKVD + c];
        float acc = bb;
        acc = fmaf(w0, xm2, acc); acc = fmaf(w1, xm1, acc); acc = fmaf(w2, x0, acc);
        if (c < DM)           g_qc[(size_t)bt * DM + c] = acc;
        else if (c < DM + 64) g_kc[(size_t)bt * 64 + d] = acc;
        else                  g_vc[(size_t)bt * 64 + d] = acc;
        xm2 = xm1; xm1 = x0;
    }
}

// ---------------- fused causal attention (tf32 mma, online softmax) ----------------
// qb reversed so longest CTAs launch first (load balance).
#define ATTN_SMEM 69632
__global__ void __launch_bounds__(128) attn_k() {
    extern __shared__ float sm[];
    float* qs = sm;              // [64][68] tf32, pre-scaled
    float* ks = sm + 4352;       // [64][68] tf32
    float* vT = sm + 8704;       // [64][68] tf32 (V transposed)
    float* ps = sm + 13056;      // [64][68] tf32 (P)
    int bid = blockIdx.x;
    int qb = 15 - (bid & 15); int h = (bid >> 4) & 15; int b = bid >> 8;
    int tid = threadIdx.x;
    int w = tid >> 5, lane = tid & 31;
    int lr = lane >> 2, lc = lane & 3;

    {
        int r = tid >> 1, d0 = (tid & 1) * 32;
        const float* qp = &g_qc[(size_t)(b * TT + qb * 64 + r) * DM + h * 64 + d0];
        #pragma unroll
        for (int j = 0; j < 8; j++) {
            float4 v = *(const float4*)(qp + j * 4);
            *(float4*)&qs[r * 68 + d0 + j * 4] =
                make_float4(tf32r(v.x * 0.125f), tf32r(v.y * 0.125f),
                            tf32r(v.z * 0.125f), tf32r(v.w * 0.125f));
        }
    }

    float m[2] = {-1e30f, -1e30f}, l[2] = {0.f, 0.f};
    float o[8][4];
    #pragma unroll
    for (int ni = 0; ni < 8; ni++)
        #pragma unroll
        for (int e = 0; e < 4; e++) o[ni][e] = 0.f;

    for (int kb = 0; kb <= qb; kb++) {
        __syncthreads();
        {
            int r = tid >> 1, d0 = (tid & 1) * 32;
            const float* kp = &g_kc[(size_t)(b * TT + kb * 64 + r) * 64 + d0];
            const float* vp = &g_vc[(size_t)(b * TT + kb * 64 + r) * 64 + d0];
            #pragma unroll
            for (int j = 0; j < 8; j++) {
                float4 kv = *(const float4*)(kp + j * 4);
                *(float4*)&ks[r * 68 + d0 + j * 4] =
                    make_float4(tf32r(kv.x), tf32r(kv.y), tf32r(kv.z), tf32r(kv.w));
                float4 vv = *(const float4*)(vp + j * 4);
                int d = d0 + j * 4;
                vT[(d + 0) * 68 + r] = tf32r(vv.x); vT[(d + 1) * 68 + r] = tf32r(vv.y);
                vT[(d + 2) * 68 + r] = tf32r(vv.z); vT[(d + 3) * 68 + r] = tf32r(vv.w);
            }
        }
        __syncthreads();

        float sc[8][4];
        #pragma unroll
        for (int ni = 0; ni < 8; ni++)
            #pragma unroll
            for (int e = 0; e < 4; e++) sc[ni][e] = 0.f;
        #pragma unroll
        for (int ksx = 0; ksx < 8; ksx++) {
            int k8 = ksx * 8;
            int r = w * 16 + lr;
            uint32_t af[4];
            af[0] = __float_as_uint(qs[r * 68 + k8 + lc]);
            af[1] = __float_as_uint(qs[(r + 8) * 68 + k8 + lc]);
            af[2] = __float_as_uint(qs[r * 68 + k8 + lc + 4]);
            af[3] = __float_as_uint(qs[(r + 8) * 68 + k8 + lc + 4]);
            #pragma unroll
            for (int ni = 0; ni < 8; ni++) {
                int n = ni * 8 + lr;
                uint32_t bf[2];
                bf[0] = __float_as_uint(ks[n * 68 + k8 + lc]);
                bf[1] = __float_as_uint(ks[n * 68 + k8 + lc + 4]);
                MMA_TF32(sc[ni], af, bf);
            }
        }

        bool diag = (kb == qb);
        #pragma unroll
        for (int h2 = 0; h2 < 2; h2++) {
            int row = w * 16 + lr + h2 * 8;
            if (diag) {
                #pragma unroll
                for (int ni = 0; ni < 8; ni++) {
                    int c0 = ni * 8 + lc * 2;
                    if (c0 > row)     sc[ni][h2 * 2 + 0] = -1e30f;
                    if (c0 + 1 > row) sc[ni][h2 * 2 + 1] = -1e30f;
                }
            }
            float mx = -1e30f;
            #pragma unroll
            for (int ni = 0; ni < 8; ni++)
                mx = fmaxf(mx, fmaxf(sc[ni][h2 * 2], sc[ni][h2 * 2 + 1]));
            mx = fmaxf(mx, __shfl_xor_sync(0xffffffffu, mx, 1));
            mx = fmaxf(mx, __shfl_xor_sync(0xffffffffu, mx, 2));
            float mn = fmaxf(m[h2], mx);
            float alpha = __expf(m[h2] - mn);
            m[h2] = mn;
            float rs = 0.f;
            #pragma unroll
            for (int ni = 0; ni < 8; ni++) {
                float p0 = __expf(sc[ni][h2 * 2]     - mn);
                float p1 = __expf(sc[ni][h2 * 2 + 1] - mn);
                rs += p0 + p1;
                *(float2*)&ps[row * 68 + ni * 8 + lc * 2] = make_float2(tf32r(p0), tf32r(p1));
            }
            rs += __shfl_xor_sync(0xffffffffu, rs, 1);
            rs += __shfl_xor_sync(0xffffffffu, rs, 2);
            l[h2] = l[h2] * alpha + rs;
            #pragma unroll
            for (int ni = 0; ni < 8; ni++) {
                o[ni][h2 * 2]     *= alpha;
                o[ni][h2 * 2 + 1] *= alpha;
            }
        }
        __syncwarp();

        #pragma unroll
        for (int ksx = 0; ksx < 8; ksx++) {
            int k8 = ksx * 8;
            int r = w * 16 + lr;
            uint32_t af[4];
            af[0] = __float_as_uint(ps[r * 68 + k8 + lc]);
            af[1] = __float_as_uint(ps[(r + 8) * 68 + k8 + lc]);
            af[2] = __float_as_uint(ps[r * 68 + k8 + lc + 4]);
            af[3] = __float_as_uint(ps[(r + 8) * 68 + k8 + lc + 4]);
            #pragma unroll
            for (int ni = 0; ni < 8; ni++) {
                int n = ni * 8 + lr;
                uint32_t bf[2];
                bf[0] = __float_as_uint(vT[n * 68 + k8 + lc]);
                bf[1] = __float_as_uint(vT[n * 68 + k8 + lc + 4]);
                MMA_TF32(o[ni], af, bf);
            }
        }
    }

    #pragma unroll
    for (int h2 = 0; h2 < 2; h2++) {
        float inv = 1.f / l[h2];
        int r = qb * 64 + w * 16 + lr + h2 * 8;
        #pragma unroll
        for (int ni = 0; ni < 8; ni++) {
            float2 v = make_float2(tf32r(o[ni][h2 * 2] * inv), tf32r(o[ni][h2 * 2 + 1] * inv));
            *(float2*)&g_att[(size_t)(b * TT + r) * DM + h * 64 + ni * 8 + lc * 2] = v;
        }
    }
}

// ---------------- host launch ----------------
static void run_gemm(const float* A, const float* Wt, float* C, int M, int N, int K,
                     const float* res, const float* mul, int epi, float* skbuf) {
    if (N <= 1536) {
        dim3 grid((N + 127) / 128, M / 128, 2);
        gemm_tc<true><<<grid, 256, GEMM_SMEM_S3>>>(A, Wt, skbuf, M, N, K, nullptr, nullptr, 0);
        int MN = M * N;
        combine_k<<<(MN / 2 + 255) / 256, 256>>>(skbuf, C, res, mul, epi, MN);
    } else {
        dim3 grid((N + 127) / 128, M / 128);
        gemm_tc<false><<<grid, 256, GEMM_SMEM_S3>>>(A, Wt, C, M, N, K, res, mul, epi);
    }
}

extern "C" void kernel_launch(void* const* d_in, const int* in_sizes, int n_in,
                              void* d_out, int out_size) {
    const float* x       = (const float*)d_in[0];
    const float* W_in    = (const float*)d_in[1];
    const float* conv_w  = (const float*)d_in[2];
    const float* conv_b  = (const float*)d_in[3];
    const float* A_log   = (const float*)d_in[4];
    const float* Dm      = (const float*)d_in[5];
    const float* dt_bias = (const float*)d_in[6];
    const float* mnorm_w = (const float*)d_in[7];
    const float* W_out   = (const float*)d_in[8];
    const float* W_qkv   = (const float*)d_in[9];
    const float* W_cproj = (const float*)d_in[10];
    const float* qconv_w = (const float*)d_in[11];
    const float* qconv_b = (const float*)d_in[12];
    const float* kconv_w = (const float*)d_in[13];
    const float* kconv_b = (const float*)d_in[14];
    const float* vconv_w = (const float*)d_in[15];
    const float* vconv_b = (const float*)d_in[16];
    const float* tmk     = (const float*)d_in[17];
    const float* tmr     = (const float*)d_in[18];
    const float* W_key   = (const float*)d_in[19];
    const float* W_rec   = (const float*)d_in[20];
    const float* W_val   = (const float*)d_in[21];
    float* out = (float*)d_out;

    float *p_h, *p_zxb, *p_y2, *p_x2, *p_qkv, *p_att, *p_x3, *p_xk, *p_xr, *p_kf, *p_kv, *p_wt, *p_sk;
    cudaGetSymbolAddress((void**)&p_h, g_h);
    cudaGetSymbolAddress((void**)&p_zxb, g_zxb);
    cudaGetSymbolAddress((void**)&p_y2, g_y2);
    cudaGetSymbolAddress((void**)&p_x2, g_x2);
    cudaGetSymbolAddress((void**)&p_qkv, g_qkv);
    cudaGetSymbolAddress((void**)&p_att, g_att);
    cudaGetSymbolAddress((void**)&p_x3, g_x3);
    cudaGetSymbolAddress((void**)&p_xk, g_xk);
    cudaGetSymbolAddress((void**)&p_xr, g_xr);
    cudaGetSymbolAddress((void**)&p_kf, g_kf);
    cudaGetSymbolAddress((void**)&p_kv, g_kv);
    cudaGetSymbolAddress((void**)&p_wt, g_wt);
    cudaGetSymbolAddress((void**)&p_sk, g_sk);

    cudaFuncSetAttribute(attn_k, cudaFuncAttributeMaxDynamicSharedMemorySize, ATTN_SMEM);
    cudaFuncSetAttribute(gemm_tc<true>,  cudaFuncAttributeMaxDynamicSharedMemorySize, GEMM_SMEM_S3);
    cudaFuncSetAttribute(gemm_tc<false>, cudaFuncAttributeMaxDynamicSharedMemorySize, GEMM_SMEM_S3);

    // ---- weight tf32 round + transpose, single launch ----
    {
        WTab wt;
        const float* srcs[7] = {W_in, W_out, W_qkv, W_cproj, W_key, W_val, W_rec};
        int offs[7] = {OW_IN, OW_OUT, OW_QKV, OW_CPROJ, OW_KEY, OW_VAL, OW_REC};
        int Ks[7]   = {DM, DI, DM, DM, DM, FFND, DM};
        int Ns[7]   = {ZXB, DM, QKVD, DM, FFND, DM, DM};
        int acc = 0;
        for (int i = 0; i < 7; i++) {
            wt.src[i] = srcs[i]; wt.off[i] = offs[i]; wt.K[i] = Ks[i]; wt.N[i] = Ns[i];
            wt.tstart[i] = acc;
            acc += (Ks[i] >> 5) * (Ns[i] >> 5);
        }
        wt.tstart[7] = acc;
        cvtall_k<<<acc, dim3(32, 8)>>>(wt);
    }

    // ---- Mamba2-style block ----
    rmsnorm_k<<<BT, 256>>>(x, p_h, 1e-6f, 1);
    run_gemm(p_h, p_wt + OW_IN, p_zxb, BT, ZXB, DM, nullptr, nullptr, 0, p_sk);
    conv_silu_k<<<(BT / CTB) * (XBCD / 256), 256>>>(conv_w, conv_b, dt_bias, A_log);
    scan_k<<<128, 512>>>();
    gate_k<<<BT, 256>>>(Dm, mnorm_w);
    run_gemm(p_y2, p_wt + OW_OUT, p_x2, BT, DM, DI, x, nullptr, 1, p_sk);

    // ---- attention block ----
    rmsnorm_k<<<BT, 256>>>(p_x2, p_h, 1e-6f, 1);
    run_gemm(p_h, p_wt + OW_QKV, p_qkv, BT, QKVD, DM, nullptr, nullptr, 0, p_sk);
    convqkv_k<<<(BT / CTB) * 5, 256>>>(qconv_w, qconv_b, kconv_w, kconv_b, vconv_w, vconv_b);
    attn_k<<<BSZ * NHA * (TT / 64), 128, ATTN_SMEM>>>();
    run_gemm(p_att, p_wt + OW_CPROJ, p_x3, BT, DM, DM, p_x2, nullptr, 1, p_sk);

    // ---- channel mix ----
    rmsshift_k<<<BT, 256>>>(p_x3, tmk, tmr, p_xk, p_xr);
    run_gemm(p_xk, p_wt + OW_KEY, p_kf, BT, FFND, DM, nullptr, nullptr, 2, p_sk);
    run_gemm(p_kf, p_wt + OW_VAL, p_kv, BT, DM, FFND, nullptr, nullptr, 0, p_sk);
    run_gemm(p_xr, p_wt + OW_REC, out, BT, DM, DM, p_x3, p_kv, 3, p_sk);
}

// round 15
// speedup vs baseline: 1.1024x; 1.0603x over previous
#include <cuda_runtime.h>
#include <cuda_bf16.h>
#include <math.h>
#include <stdint.h>

#define BSZ 2
#define TT 1024
#define DM 1024
#define DI 2048
#define DS 128
#define NH 32
#define HDS 64
#define NHA 16
#define HDA 64
#define FFND 4096
#define ZXB 4384
#define XBCD 2304
#define QKVD 1152
#define BT (BSZ*TT)

// ---------------- scratch (device globals; no allocations allowed) ----------------
__device__ float g_h[BT*DM];
__device__ float g_zxb[BT*ZXB];
__device__ float g_xBC[BT*XBCD];
__device__ float g_dt[BT*NH];
__device__ float g_dA[BT*NH];
__device__ float g_yp[2*BT*DI];
__device__ float g_y2[BT*DI];
__device__ float g_x2[BT*DM];
__device__ float g_qkv[BT*QKVD];
__device__ float g_qc[BT*DM];
__device__ float g_kc[BT*HDA];
__device__ float g_vc[BT*HDA];
__device__ float g_att[BT*DM];
__device__ float g_x3[BT*DM];
__device__ float g_xr[BT*DM];
__device__ float g_kv[BT*DM];
__device__ float g_wt[18251776];          // tf32-rounded TRANSPOSED weights [N][K]
__device__ float g_sk[2*BT*QKVD];         // split-K partial sums
__device__ __nv_bfloat16 g_xkb[BT*DM];    // xk in bf16
__device__ __nv_bfloat16 g_kfb[BT*FFND];  // kf in bf16
__device__ __nv_bfloat16 g_wkb[DM*FFND];  // W_key^T bf16 [N][K]
__device__ __nv_bfloat16 g_wvb[FFND*DM];  // W_val^T bf16 [N][K]

// tf32 weight offsets in g_wt
#define OW_IN    0
#define OW_OUT   4489216
#define OW_QKV   6586368
#define OW_CPROJ 7766016
#define OW_REC   8814592

// ---------------- helpers ----------------
__device__ __forceinline__ uint32_t f2tf32(float x) {
    uint32_t r; asm("cvt.rna.tf32.f32 %0, %1;" : "=r"(r) : "f"(x)); return r;
}
__device__ __forceinline__ float tf32r(float x) { return __uint_as_float(f2tf32(x)); }

__device__ __forceinline__ float block_sum(float v) {
    __shared__ float red[32];
    int lane = threadIdx.x & 31, w = threadIdx.x >> 5;
    #pragma unroll
    for (int o = 16; o; o >>= 1) v += __shfl_xor_sync(0xffffffffu, v, o);
    if (lane == 0) red[w] = v;
    __syncthreads();
    int nw = blockDim.x >> 5;
    float r = (threadIdx.x < nw) ? red[threadIdx.x] : 0.f;
    if (w == 0) {
        #pragma unroll
        for (int o = 16; o; o >>= 1) r += __shfl_xor_sync(0xffffffffu, r, o);
        if (lane == 0) red[0] = r;
    }
    __syncthreads();
    return red[0];
}

__global__ void rmsnorm_k(const float* __restrict__ x, float* __restrict__ o, float eps, int rnd) {
    int row = blockIdx.x;
    const float* xr = x + (size_t)row * DM;
    float ss = 0.f;
    for (int c = threadIdx.x; c < DM; c += blockDim.x) { float v = xr[c]; ss = fmaf(v, v, ss); }
    ss = block_sum(ss);
    float sc = rsqrtf(ss / (float)DM + eps);
    float* orow = o + (size_t)row * DM;
    if (rnd) for (int c = threadIdx.x; c < DM; c += blockDim.x) orow[c] = tf32r(xr[c] * sc);
    else     for (int c = threadIdx.x; c < DM; c += blockDim.x) orow[c] = xr[c] * sc;
}

// ---------------- fused rmsnorm + token-shift (channel mix); xk -> bf16, xr -> tf32 ----
__global__ void rmsshift_k(const float* __restrict__ x3,
                           const float* __restrict__ tmk, const float* __restrict__ tmr,
                           __nv_bfloat16* __restrict__ xk, float* __restrict__ xr) {
    int bt = blockIdx.x; int t = bt & 1023;
    const float* cur = x3 + (size_t)bt * DM;
    const float* prv = x3 + (size_t)(bt - 1) * DM;
    float sa = 0.f, sb = 0.f;
    for (int c = threadIdx.x; c < DM; c += blockDim.x) {
        float v = cur[c]; sa = fmaf(v, v, sa);
        float p = t ? prv[c] : 0.f; sb = fmaf(p, p, sb);
    }
    float ra = block_sum(sa);
    __syncthreads();
    float rb = block_sum(sb);
    float scc = rsqrtf(ra / (float)DM + 1e-6f);
    float scp = rsqrtf(rb / (float)DM + 1e-6f);
    for (int c = threadIdx.x; c < DM; c += blockDim.x) {
        float h = cur[c] * scc;
        float hp = t ? prv[c] * scp : 0.f;
        float dd = hp - h;
        xk[(size_t)bt * DM + c] = __float2bfloat16(fmaf(dd, tmk[c], h));
        xr[(size_t)bt * DM + c] = tf32r(fmaf(dd, tmr[c], h));
    }
}

// ---------------- tf32 weight round + transpose (5 weights, one launch) ----
struct WTab {
    const float* src[5];
    int off[5];
    int K[5], N[5];
    int tstart[6];
};
__global__ void cvtall_k(WTab wt) {
    __shared__ float t[32][33];
    int bidx = blockIdx.x;
    int w = 0;
    #pragma unroll
    for (int i = 1; i < 5; i++) if (bidx >= wt.tstart[i]) w = i;
    int tloc = bidx - wt.tstart[w];
    int K = wt.K[w], N = wt.N[w];
    int ntn = N >> 5;
    int k0 = (tloc / ntn) << 5, n0 = (tloc % ntn) << 5;
    const float* in = wt.src[w];
    float* out = g_wt + wt.off[w];
    int x = threadIdx.x, y = threadIdx.y;
    #pragma unroll
    for (int i = 0; i < 32; i += 8)
        t[y + i][x] = tf32r(in[(size_t)(k0 + y + i) * N + n0 + x]);
    __syncthreads();
    #pragma unroll
    for (int i = 0; i < 32; i += 8)
        out[(size_t)(n0 + y + i) * K + k0 + x] = t[x][y + i];
}

// ---------------- bf16 weight round + transpose ----------------
__global__ void cvtbf_k(const float* __restrict__ in, __nv_bfloat16* __restrict__ out, int K, int N) {
    __shared__ float t[32][33];
    int k0 = blockIdx.y * 32, n0 = blockIdx.x * 32;
    int x = threadIdx.x, y = threadIdx.y;
    #pragma unroll
    for (int i = 0; i < 32; i += 8)
        t[y + i][x] = in[(size_t)(k0 + y + i) * N + n0 + x];
    __syncthreads();
    #pragma unroll
    for (int i = 0; i < 32; i += 8)
        out[(size_t)(n0 + y + i) * K + k0 + x] = __float2bfloat16(t[x][y + i]);
}

// ================= shared GEMM macros =================
#define CP_ASYNC16(dst, src, sz) \
    asm volatile("cp.async.cg.shared.global [%0], [%1], 16, %2;" :: "r"(dst), "l"(src), "r"(sz) : "memory")
#define CP_COMMIT() asm volatile("cp.async.commit_group;" ::: "memory")
#define CP_WAIT_N(n) asm volatile("cp.async.wait_group %0;" :: "n"(n) : "memory")
#define MMA_TF32(d, a, b) \
    asm volatile("mma.sync.aligned.m16n8k8.row.col.f32.tf32.tf32.f32 " \
        "{%0,%1,%2,%3}, {%4,%5,%6,%7}, {%8,%9}, {%0,%1,%2,%3};" \
        : "+f"((d)[0]), "+f"((d)[1]), "+f"((d)[2]), "+f"((d)[3]) \
        : "r"((a)[0]), "r"((a)[1]), "r"((a)[2]), "r"((a)[3]), "r"((b)[0]), "r"((b)[1]))
#define MMA_BF16(d, a, b) \
    asm volatile("mma.sync.aligned.m16n8k16.row.col.f32.bf16.bf16.f32 " \
        "{%0,%1,%2,%3}, {%4,%5,%6,%7}, {%8,%9}, {%0,%1,%2,%3};" \
        : "+f"((d)[0]), "+f"((d)[1]), "+f"((d)[2]), "+f"((d)[3]) \
        : "r"((a)[0]), "r"((a)[1]), "r"((a)[2]), "r"((a)[3]), "r"((b)[0]), "r"((b)[1]))
#define LDMX4(r0, r1, r2, r3, a) \
    asm volatile("ldmatrix.sync.aligned.m8n8.x4.shared.b16 {%0,%1,%2,%3}, [%4];" \
        : "=r"(r0), "=r"(r1), "=r"(r2), "=r"(r3) : "r"(a))

// ================= tf32 GEMM (ldmatrix, 3-stage, optional split-K) =================
template<bool SPLITK>
__global__ void __launch_bounds__(256, 2) gemm_tc(const float* __restrict__ A, const float* __restrict__ Bt,
                                                  float* __restrict__ C, int M, int N, int K,
                                                  const float* __restrict__ res, const float* __restrict__ mul, int epi)
{
    extern __shared__ float gs[];
    float (*As)[36] = (float(*)[36])gs;
    float (*Bs)[36] = (float(*)[36])(gs + 3*128*36);
    int tid = threadIdx.x;
    int m0 = blockIdx.y * 128, n0 = blockIdx.x * 128;
    int kz = SPLITK ? blockIdx.z : 0;
    int Keff = SPLITK ? (K >> 1) : K;
    int kzoff = kz * Keff;
    int w = tid >> 5, lane = tid & 31;
    int wm = (w >> 2) * 64;
    int wn = (w & 3) * 32;

    float acc[4][4][4];
    #pragma unroll
    for (int mi = 0; mi < 4; mi++)
        #pragma unroll
        for (int ni = 0; ni < 4; ni++)
            #pragma unroll
            for (int e = 0; e < 4; e++) acc[mi][ni][e] = 0.f;

    const int NC = Keff >> 5;

    auto fill = [&](int buf, int k0) {
        #pragma unroll
        for (int i = 0; i < 4; i++) {
            int task = tid + i * 256;
            int r = task >> 3, q = (task & 7) * 4;
            const float* src = A + (size_t)(m0 + r) * K + k0 + q;
            uint32_t dst = (uint32_t)__cvta_generic_to_shared(&As[buf * 128 + r][q]);
            CP_ASYNC16(dst, src, 16);
        }
        #pragma unroll
        for (int i = 0; i < 4; i++) {
            int task = tid + i * 256;
            int r = task >> 3, q = (task & 7) * 4;
            int ok = (n0 + r) < N;
            const float* src = Bt + (size_t)(n0 + r) * K + k0 + q;
            uint32_t dst = (uint32_t)__cvta_generic_to_shared(&Bs[buf * 128 + r][q]);
            CP_ASYNC16(dst, src, ok ? 16 : 0);
        }
    };

    fill(0, kzoff);      CP_COMMIT();
    fill(1, kzoff + 32); CP_COMMIT();

    int g = lane >> 3, lr8 = lane & 7;
    int arow_l = wm + (g & 1) * 8 + lr8;
    int acol_l = (g >> 1) * 4;
    int brow_l = wn + (g >> 1) * 8 + lr8;
    int bcol_l = (g & 1) * 4;

    int buf = 0;
    for (int ct = 0; ct < NC; ct++) {
        CP_WAIT_N(1);
        __syncthreads();

        const float (*as)[36] = &As[buf * 128];
        const float (*bs)[36] = &Bs[buf * 128];
        #pragma unroll
        for (int ks = 0; ks < 4; ks++) {
            int kb = ks * 8;
            uint32_t af[4][4];
            #pragma unroll
            for (int mi = 0; mi < 4; mi++) {
                uint32_t a = (uint32_t)__cvta_generic_to_shared(&as[arow_l + mi * 16][acol_l + kb]);
                LDMX4(af[mi][0], af[mi][1], af[mi][2], af[mi][3], a);
            }
            uint32_t bf[4][2];
            #pragma unroll
            for (int p = 0; p < 2; p++) {
                uint32_t a = (uint32_t)__cvta_generic_to_shared(&bs[brow_l + p * 16][bcol_l + kb]);
                LDMX4(bf[2*p][0], bf[2*p][1], bf[2*p+1][0], bf[2*p+1][1], a);
            }
            #pragma unroll
            for (int mi = 0; mi < 4; mi++)
                #pragma unroll
                for (int ni = 0; ni < 4; ni++)
                    MMA_TF32(acc[mi][ni], af[mi], bf[ni]);
        }

        int nx = ct + 2;
        if (nx < NC) fill(nx % 3, kzoff + nx * 32);
        CP_COMMIT();
        if (++buf == 3) buf = 0;
    }

    float* Co = SPLITK ? (C + (size_t)kz * M * N) : C;
    #pragma unroll
    for (int mi = 0; mi < 4; mi++) {
        int r0 = m0 + wm + mi * 16 + (lane >> 2);
        #pragma unroll
        for (int ni = 0; ni < 4; ni++) {
            int c = n0 + wn + ni * 8 + (lane & 3) * 2;
            if (c < N) {
                #pragma unroll
                for (int half = 0; half < 2; half++) {
                    int r = r0 + half * 8;
                    size_t idx = (size_t)r * N + c;
                    float v0 = acc[mi][ni][half * 2 + 0];
                    float v1 = acc[mi][ni][half * 2 + 1];
                    if (!SPLITK) {
                        if (epi == 1) {
                            v0 += res[idx]; v1 += res[idx + 1];
                        } else if (epi == 3) {
                            v0 = res[idx]     + mul[idx]     / (1.f + expf(-v0));
                            v1 = res[idx + 1] + mul[idx + 1] / (1.f + expf(-v1));
                        }
                    }
                    Co[idx] = v0; Co[idx + 1] = v1;
                }
            }
        }
    }
}
#define GEMM_SMEM_S3 110592

// ================= bf16 GEMM (m16n8k16, ldmatrix, 3-stage, optional split-K) =========
// A[M,K], Bt[N,K] both bf16. epi==2: relu^2 -> bf16 out (Cb). else fp32 out (C).
template<bool SPLITK>
__global__ void __launch_bounds__(256, 2) gemm_bf(const __nv_bfloat16* __restrict__ A,
                                                  const __nv_bfloat16* __restrict__ Bt,
                                                  float* __restrict__ C, __nv_bfloat16* __restrict__ Cb,
                                                  int M, int N, int K, int epi)
{
    extern __shared__ __nv_bfloat16 gb[];
    __nv_bfloat16 (*As)[40] = (__nv_bfloat16(*)[40])gb;                 // [3*128][40]
    __nv_bfloat16 (*Bs)[40] = (__nv_bfloat16(*)[40])(gb + 3*128*40);
    int tid = threadIdx.x;
    int m0 = blockIdx.y * 128, n0 = blockIdx.x * 128;
    int kz = SPLITK ? blockIdx.z : 0;
    int Keff = SPLITK ? (K >> 1) : K;
    int kzoff = kz * Keff;
    int w = tid >> 5, lane = tid & 31;
    int wm = (w >> 2) * 64;
    int wn = (w & 3) * 32;

    float acc[4][4][4];
    #pragma unroll
    for (int mi = 0; mi < 4; mi++)
        #pragma unroll
        for (int ni = 0; ni < 4; ni++)
            #pragma unroll
            for (int e = 0; e < 4; e++) acc[mi][ni][e] = 0.f;

    const int NC = Keff >> 5;

    auto fill = [&](int buf, int k0) {
        #pragma unroll
        for (int i = 0; i < 2; i++) {
            int task = tid + i * 256;
            int r = task >> 2, q = (task & 3) * 8;
            const __nv_bfloat16* src = A + (size_t)(m0 + r) * K + k0 + q;
            uint32_t dst = (uint32_t)__cvta_generic_to_shared(&As[buf * 128 + r][q]);
            CP_ASYNC16(dst, src, 16);
        }
        #pragma unroll
        for (int i = 0; i < 2; i++) {
            int task = tid + i * 256;
            int r = task >> 2, q = (task & 3) * 8;
            int ok = (n0 + r) < N;
            const __nv_bfloat16* src = Bt + (size_t)(n0 + r) * K + k0 + q;
            uint32_t dst = (uint32_t)__cvta_generic_to_shared(&Bs[buf * 128 + r][q]);
            CP_ASYNC16(dst, src, ok ? 16 : 0);
        }
    };

    fill(0, kzoff);      CP_COMMIT();
    fill(1, kzoff + 32); CP_COMMIT();

    int g = lane >> 3, lr8 = lane & 7;

    int buf = 0;
    for (int ct = 0; ct < NC; ct++) {
        CP_WAIT_N(1);
        __syncthreads();

        const __nv_bfloat16 (*as)[40] = &As[buf * 128];
        const __nv_bfloat16 (*bs)[40] = &Bs[buf * 128];
        #pragma unroll
        for (int ks = 0; ks < 2; ks++) {
            int kb = ks * 16;
            uint32_t af[4][4];
            #pragma unroll
            for (int mi = 0; mi < 4; mi++) {
                int row = wm + mi * 16 + (g & 1) * 8 + lr8;
                int col = (g >> 1) * 8 + kb;
                uint32_t a = (uint32_t)__cvta_generic_to_shared(&as[row][col]);
                LDMX4(af[mi][0], af[mi][1], af[mi][2], af[mi][3], a);
            }
            uint32_t bf[4][2];
            #pragma unroll
            for (int p = 0; p < 2; p++) {
                int row = wn + p * 16 + (g >> 1) * 8 + lr8;
                int col = (g & 1) * 8 + kb;
                uint32_t a = (uint32_t)__cvta_generic_to_shared(&bs[row][col]);
                LDMX4(bf[2*p][0], bf[2*p][1], bf[2*p+1][0], bf[2*p+1][1], a);
            }
            #pragma unroll
            for (int mi = 0; mi < 4; mi++)
                #pragma unroll
                for (int ni = 0; ni < 4; ni++)
                    MMA_BF16(acc[mi][ni], af[mi], bf[ni]);
        }

        int nx = ct + 2;
        if (nx < NC) fill(nx % 3, kzoff + nx * 32);
        CP_COMMIT();
        if (++buf == 3) buf = 0;
    }

    float* Co = SPLITK ? (C + (size_t)kz * M * N) : C;
    #pragma unroll
    for (int mi = 0; mi < 4; mi++) {
        int r0 = m0 + wm + mi * 16 + (lane >> 2);
        #pragma unroll
        for (int ni = 0; ni < 4; ni++) {
            int c = n0 + wn + ni * 8 + (lane & 3) * 2;
            if (c < N) {
                #pragma unroll
                for (int half = 0; half < 2; half++) {
                    int r = r0 + half * 8;
                    size_t idx = (size_t)r * N + c;
                    float v0 = acc[mi][ni][half * 2 + 0];
                    float v1 = acc[mi][ni][half * 2 + 1];
                    if (epi == 2) {
                        v0 = fmaxf(v0, 0.f); v0 = v0 * v0;
                        v1 = fmaxf(v1, 0.f); v1 = v1 * v1;
                        __nv_bfloat162 bv;
                        bv.x = __float2bfloat16(v0);
                        bv.y = __float2bfloat16(v1);
                        *(__nv_bfloat162*)(Cb + idx) = bv;
                    } else {
                        Co[idx] = v0; Co[idx + 1] = v1;
                    }
                }
            }
        }
    }
}
#define GEMM_SMEM_BF 61440

// ---------------- split-K combine + fused epilogue ----------------
__global__ void combine_k(const float* __restrict__ p, float* __restrict__ C,
                          const float* __restrict__ res, const float* __restrict__ mul,
                          int epi, int MN) {
    int i = (blockIdx.x * blockDim.x + threadIdx.x) * 2;
    if (i >= MN) return;
    float2 a = *(const float2*)(p + i);
    float2 b = *(const float2*)(p + MN + i);
    float v0 = a.x + b.x, v1 = a.y + b.y;
    if (epi == 1) {
        v0 += res[i]; v1 += res[i + 1];
    } else if (epi == 3) {
        v0 = res[i]     + mul[i]     / (1.f + expf(-v0));
        v1 = res[i + 1] + mul[i + 1] / (1.f + expf(-v1));
    }
    *(float2*)(C + i) = make_float2(v0, v1);
}

// ---------------- xBC causal depthwise conv (K=4) + silu + fused dt/dA ----------------
#define CTB 8
__global__ void conv_silu_k(const float* __restrict__ cw, const float* __restrict__ cb,
                            const float* __restrict__ dt_bias, const float* __restrict__ A_log) {
    int blk = blockIdx.x;
    int cblk = blk % (XBCD / 256);
    int tb = blk / (XBCD / 256);
    int b = tb / (TT / CTB);
    int t0 = (tb % (TT / CTB)) * CTB;
    int c = cblk * 256 + threadIdx.x;

    float w0 = cw[c*4], w1 = cw[c*4+1], w2 = cw[c*4+2], w3 = cw[c*4+3], bb = cb[c];
    float xm3 = (t0 >= 3) ? g_zxb[(size_t)(b * TT + t0 - 3) * ZXB + DI + c] : 0.f;
    float xm2 = (t0 >= 2) ? g_zxb[(size_t)(b * TT + t0 - 2) * ZXB + DI + c] : 0.f;
    float xm1 = (t0 >= 1) ? g_zxb[(size_t)(b * TT + t0 - 1) * ZXB + DI + c] : 0.f;
    #pragma unroll
    for (int j = 0; j < CTB; j++) {
        float x0 = g_zxb[(size_t)(b * TT + t0 + j) * ZXB + DI + c];
        float acc = bb;
        acc = fmaf(w0, xm3, acc); acc = fmaf(w1, xm2, acc);
        acc = fmaf(w2, xm1, acc); acc = fmaf(w3, x0, acc);
        acc = acc / (1.f + expf(-acc));
        g_xBC[(size_t)(b * TT + t0 + j) * XBCD + c] = acc;
        xm3 = xm2; xm2 = xm1; xm1 = x0;
    }
    if (cblk == 0) {
        int h = threadIdx.x & 31, j = threadIdx.x >> 5;
        int bt = b * TT + t0 + j;
        float v = g_zxb[(size_t)bt * ZXB + 4352 + h] + dt_bias[h];
        float sp = (v > 20.f) ? v : log1pf(expf(v));
        g_dt[bt * NH + h] = sp;
        g_dA[bt * NH + h] = expf(sp * (-expf(A_log[h])));
    }
}

// ---------------- SSM scan ----------------
__global__ void scan_k() {
    int bid = blockIdx.x;
    int ns = bid & 1; int bh = bid >> 1; int b = bh >> 5; int h = bh & 31;
    int tid = threadIdx.x;
    int p = tid >> 3;
    int ng = tid & 7;
    __shared__ float sB[16 * 64], sC[16 * 64], sX[16 * 64], sS[16];
    float s[8];
    #pragma unroll
    for (int j = 0; j < 8; j++) s[j] = 0.f;
    int nb = ns * 64;

    for (int ct = 0; ct < TT / 16; ct++) {
        int t0 = ct * 16;
        #pragma unroll
        for (int l = 0; l < 2; l++) {
            int e = tid + l * 512; int tt = e >> 6; int n = e & 63;
            int base = b * TT + t0 + tt;
            sB[e] = g_xBC[(size_t)base * XBCD + DI + nb + n];
            sC[e] = g_xBC[(size_t)base * XBCD + DI + DS + nb + n];
            sX[e] = g_xBC[(size_t)base * XBCD + h * 64 + n] * g_dt[base * NH + h];
        }
        if (tid < 16) sS[tid] = g_dA[(b * TT + t0 + tid) * NH + h];
        __syncthreads();
        for (int tt = 0; tt < 16; tt++) {
            float da = sS[tt];
            float dtx = sX[tt * 64 + p];
            float bb[8], cc[8];
            *(float4*)&bb[0] = *(float4*)&sB[tt * 64 + ng * 8];
            *(float4*)&bb[4] = *(float4*)&sB[tt * 64 + ng * 8 + 4];
            *(float4*)&cc[0] = *(float4*)&sC[tt * 64 + ng * 8];
            *(float4*)&cc[4] = *(float4*)&sC[tt * 64 + ng * 8 + 4];
            float acc = 0.f;
            #pragma unroll
            for (int j = 0; j < 8; j++) {
                s[j] = fmaf(s[j], da, dtx * bb[j]);
                acc = fmaf(s[j], cc[j], acc);
            }
            acc += __shfl_xor_sync(0xffffffffu, acc, 1);
            acc += __shfl_xor_sync(0xffffffffu, acc, 2);
            acc += __shfl_xor_sync(0xffffffffu, acc, 4);
            if (ng == 0)
                g_yp[(size_t)ns * (BT * DI) + (size_t)(b * TT + t0 + tt) * DI + h * 64 + p] = acc;
        }
        __syncthreads();
    }
}

__global__ void gate_k(const float* __restrict__ Dm, const float* __restrict__ mnw) {
    int bt = blockIdx.x;
    float ss = 0.f;
    for (int c = threadIdx.x; c < DI; c += blockDim.x) {
        float v = g_yp[(size_t)bt * DI + c] + g_yp[(size_t)BT * DI + (size_t)bt * DI + c]
                + g_xBC[(size_t)bt * XBCD + c] * Dm[c >> 6];
        float z = g_zxb[(size_t)bt * ZXB + c];
        v *= z / (1.f + expf(-z));
        g_y2[(size_t)bt * DI + c] = v;
        ss = fmaf(v, v, ss);
    }
    ss = block_sum(ss);
    float sc = rsqrtf(ss / (float)DI + 1e-5f);
    for (int c = threadIdx.x; c < DI; c += blockDim.x)
        g_y2[(size_t)bt * DI + c] = tf32r(g_y2[(size_t)bt * DI + c] * sc * mnw[c]);
}

// ---------------- q/k/v causal depthwise conv (K=3), channel-slab blocking -----------
__global__ void convqkv_k(const float* __restrict__ qw, const float* __restrict__ qb,
                          const float* __restrict__ kw, const float* __restrict__ kb,
                          const float* __restrict__ vw, const float* __restrict__ vb) {
    int blk = blockIdx.x;
    int cblk = blk % 5;
    int tb = blk / 5;
    int b = tb / (TT / CTB);
    int t0 = (tb % (TT / CTB)) * CTB;
    int c = cblk * 256 + threadIdx.x;
    if (c >= QKVD) return;

    const float* w; const float* bias; int d;
    if (c < DM)            { d = c & 63;        w = qw; bias = qb; }
    else if (c < DM + 64)  { d = c - DM;        w = kw; bias = kb; }
    else                   { d = c - DM - 64;   w = vw; bias = vb; }
    float w0 = w[d*3], w1 = w[d*3+1], w2 = w[d*3+2], bb = bias[d];
    float xm2 = (t0 >= 2) ? g_qkv[(size_t)(b * TT + t0 - 2) * QKVD + c] : 0.f;
    float xm1 = (t0 >= 1) ? g_qkv[(size_t)(b * TT + t0 - 1) * QKVD + c] : 0.f;
    #pragma unroll
    for (int j = 0; j < CTB; j++) {
        int bt = b * TT + t0 + j;
        float x0 = g_qkv[(size_t)bt * QKVD + c];
        float acc = bb;
        acc = fmaf(w0, xm2, acc); acc = fmaf(w1, xm1, acc); acc = fmaf(w2, x0, acc);
        if (c < DM)           g_qc[(size_t)bt * DM + c] = acc;
        else if (c < DM + 64) g_kc[(size_t)bt * 64 + d] = acc;
        else                  g_vc[(size_t)bt * 64 + d] = acc;
        xm2 = xm1; xm1 = x0;
    }
}

// ---------------- fused causal attention (tf32 mma, online softmax) ----------------
#define ATTN_SMEM 69632
__global__ void __launch_bounds__(128) attn_k() {
    extern __shared__ float sm[];
    float* qs = sm;
    float* ks = sm + 4352;
    float* vT = sm + 8704;
    float* ps = sm + 13056;
    int bid = blockIdx.x;
    int qb = 15 - (bid & 15); int h = (bid >> 4) & 15; int b = bid >> 8;
    int tid = threadIdx.x;
    int w = tid >> 5, lane = tid & 31;
    int lr = lane >> 2, lc = lane & 3;

    {
        int r = tid >> 1, d0 = (tid & 1) * 32;
        const float* qp = &g_qc[(size_t)(b * TT + qb * 64 + r) * DM + h * 64 + d0];
        #pragma unroll
        for (int j = 0; j < 8; j++) {
            float4 v = *(const float4*)(qp + j * 4);
            *(float4*)&qs[r * 68 + d0 + j * 4] =
                make_float4(tf32r(v.x * 0.125f), tf32r(v.y * 0.125f),
                            tf32r(v.z * 0.125f), tf32r(v.w * 0.125f));
        }
    }

    float m[2] = {-1e30f, -1e30f}, l[2] = {0.f, 0.f};
    float o[8][4];
    #pragma unroll
    for (int ni = 0; ni < 8; ni++)
        #pragma unroll
        for (int e = 0; e < 4; e++) o[ni][e] = 0.f;

    for (int kb = 0; kb <= qb; kb++) {
        __syncthreads();
        {
            int r = tid >> 1, d0 = (tid & 1) * 32;
            const float* kp = &g_kc[(size_t)(b * TT + kb * 64 + r) * 64 + d0];
            const float* vp = &g_vc[(size_t)(b * TT + kb * 64 + r) * 64 + d0];
            #pragma unroll
            for (int j = 0; j < 8; j++) {
                float4 kv = *(const float4*)(kp + j * 4);
                *(float4*)&ks[r * 68 + d0 + j * 4] =
                    make_float4(tf32r(kv.x), tf32r(kv.y), tf32r(kv.z), tf32r(kv.w));
                float4 vv = *(const float4*)(vp + j * 4);
                int d = d0 + j * 4;
                vT[(d + 0) * 68 + r] = tf32r(vv.x); vT[(d + 1) * 68 + r] = tf32r(vv.y);
                vT[(d + 2) * 68 + r] = tf32r(vv.z); vT[(d + 3) * 68 + r] = tf32r(vv.w);
            }
        }
        __syncthreads();

        float sc[8][4];
        #pragma unroll
        for (int ni = 0; ni < 8; ni++)
            #pragma unroll
            for (int e = 0; e < 4; e++) sc[ni][e] = 0.f;
        #pragma unroll
        for (int ksx = 0; ksx < 8; ksx++) {
            int k8 = ksx * 8;
            int r = w * 16 + lr;
            uint32_t af[4];
            af[0] = __float_as_uint(qs[r * 68 + k8 + lc]);
            af[1] = __float_as_uint(qs[(r + 8) * 68 + k8 + lc]);
            af[2] = __float_as_uint(qs[r * 68 + k8 + lc + 4]);
            af[3] = __float_as_uint(qs[(r + 8) * 68 + k8 + lc + 4]);
            #pragma unroll
            for (int ni = 0; ni < 8; ni++) {
                int n = ni * 8 + lr;
                uint32_t bf[2];
                bf[0] = __float_as_uint(ks[n * 68 + k8 + lc]);
                bf[1] = __float_as_uint(ks[n * 68 + k8 + lc + 4]);
                MMA_TF32(sc[ni], af, bf);
            }
        }

        bool diag = (kb == qb);
        #pragma unroll
        for (int h2 = 0; h2 < 2; h2++) {
            int row = w * 16 + lr + h2 * 8;
            if (diag) {
                #pragma unroll
                for (int ni = 0; ni < 8; ni++) {
                    int c0 = ni * 8 + lc * 2;
                    if (c0 > row)     sc[ni][h2 * 2 + 0] = -1e30f;
                    if (c0 + 1 > row) sc[ni][h2 * 2 + 1] = -1e30f;
                }
            }
            float mx = -1e30f;
            #pragma unroll
            for (int ni = 0; ni < 8; ni++)
                mx = fmaxf(mx, fmaxf(sc[ni][h2 * 2], sc[ni][h2 * 2 + 1]));
            mx = fmaxf(mx, __shfl_xor_sync(0xffffffffu, mx, 1));
            mx = fmaxf(mx, __shfl_xor_sync(0xffffffffu, mx, 2));
            float mn = fmaxf(m[h2], mx);
            float alpha = __expf(m[h2] - mn);
            m[h2] = mn;
            float rs = 0.f;
            #pragma unroll
            for (int ni = 0; ni < 8; ni++) {
                float p0 = __expf(sc[ni][h2 * 2]     - mn);
                float p1 = __expf(sc[ni][h2 * 2 + 1] - mn);
                rs += p0 + p1;
                *(float2*)&ps[row * 68 + ni * 8 + lc * 2] = make_float2(tf32r(p0), tf32r(p1));
            }
            rs += __shfl_xor_sync(0xffffffffu, rs, 1);
            rs += __shfl_xor_sync(0xffffffffu, rs, 2);
            l[h2] = l[h2] * alpha + rs;
            #pragma unroll
            for (int ni = 0; ni < 8; ni++) {
                o[ni][h2 * 2]     *= alpha;
                o[ni][h2 * 2 + 1] *= alpha;
            }
        }
        __syncwarp();

        #pragma unroll
        for (int ksx = 0; ksx < 8; ksx++) {
            int k8 = ksx * 8;
            int r = w * 16 + lr;
            uint32_t af[4];
            af[0] = __float_as_uint(ps[r * 68 + k8 + lc]);
            af[1] = __float_as_uint(ps[(r + 8) * 68 + k8 + lc]);
            af[2] = __float_as_uint(ps[r * 68 + k8 + lc + 4]);
            af[3] = __float_as_uint(ps[(r + 8) * 68 + k8 + lc + 4]);
            #pragma unroll
            for (int ni = 0; ni < 8; ni++) {
                int n = ni * 8 + lr;
                uint32_t bf[2];
                bf[0] = __float_as_uint(vT[n * 68 + k8 + lc]);
                bf[1] = __float_as_uint(vT[n * 68 + k8 + lc + 4]);
                MMA_TF32(o[ni], af, bf);
            }
        }
    }

    #pragma unroll
    for (int h2 = 0; h2 < 2; h2++) {
        float inv = 1.f / l[h2];
        int r = qb * 64 + w * 16 + lr + h2 * 8;
        #pragma unroll
        for (int ni = 0; ni < 8; ni++) {
            float2 v = make_float2(tf32r(o[ni][h2 * 2] * inv), tf32r(o[ni][h2 * 2 + 1] * inv));
            *(float2*)&g_att[(size_t)(b * TT + r) * DM + h * 64 + ni * 8 + lc * 2] = v;
        }
    }
}

// ---------------- host launch ----------------
static void run_gemm(const float* A, const float* Wt, float* C, int M, int N, int K,
                     const float* res, const float* mul, int epi, float* skbuf) {
    if (N <= 1536) {
        dim3 grid((N + 127) / 128, M / 128, 2);
        gemm_tc<true><<<grid, 256, GEMM_SMEM_S3>>>(A, Wt, skbuf, M, N, K, nullptr, nullptr, 0);
        int MN = M * N;
        combine_k<<<(MN / 2 + 255) / 256, 256>>>(skbuf, C, res, mul, epi, MN);
    } else {
        dim3 grid((N + 127) / 128, M / 128);
        gemm_tc<false><<<grid, 256, GEMM_SMEM_S3>>>(A, Wt, C, M, N, K, res, mul, epi);
    }
}

extern "C" void kernel_launch(void* const* d_in, const int* in_sizes, int n_in,
                              void* d_out, int out_size) {
    const float* x       = (const float*)d_in[0];
    const float* W_in    = (const float*)d_in[1];
    const float* conv_w  = (const float*)d_in[2];
    const float* conv_b  = (const float*)d_in[3];
    const float* A_log   = (const float*)d_in[4];
    const float* Dm      = (const float*)d_in[5];
    const float* dt_bias = (const float*)d_in[6];
    const float* mnorm_w = (const float*)d_in[7];
    const float* W_out   = (const float*)d_in[8];
    const float* W_qkv   = (const float*)d_in[9];
    const float* W_cproj = (const float*)d_in[10];
    const float* qconv_w = (const float*)d_in[11];
    const float* qconv_b = (const float*)d_in[12];
    const float* kconv_w = (const float*)d_in[13];
    const float* kconv_b = (const float*)d_in[14];
    const float* vconv_w = (const float*)d_in[15];
    const float* vconv_b = (const float*)d_in[16];
    const float* tmk     = (const float*)d_in[17];
    const float* tmr     = (const float*)d_in[18];
    const float* W_key   = (const float*)d_in[19];
    const float* W_rec   = (const float*)d_in[20];
    const float* W_val   = (const float*)d_in[21];
    float* out = (float*)d_out;

    float *p_h, *p_zxb, *p_y2, *p_x2, *p_qkv, *p_att, *p_x3, *p_xr, *p_kv, *p_wt, *p_sk;
    __nv_bfloat16 *p_xkb, *p_kfb, *p_wkb, *p_wvb;
    cudaGetSymbolAddress((void**)&p_h, g_h);
    cudaGetSymbolAddress((void**)&p_zxb, g_zxb);
    cudaGetSymbolAddress((void**)&p_y2, g_y2);
    cudaGetSymbolAddress((void**)&p_x2, g_x2);
    cudaGetSymbolAddress((void**)&p_qkv, g_qkv);
    cudaGetSymbolAddress((void**)&p_att, g_att);
    cudaGetSymbolAddress((void**)&p_x3, g_x3);
    cudaGetSymbolAddress((void**)&p_xr, g_xr);
    cudaGetSymbolAddress((void**)&p_kv, g_kv);
    cudaGetSymbolAddress((void**)&p_wt, g_wt);
    cudaGetSymbolAddress((void**)&p_sk, g_sk);
    cudaGetSymbolAddress((void**)&p_xkb, g_xkb);
    cudaGetSymbolAddress((void**)&p_kfb, g_kfb);
    cudaGetSymbolAddress((void**)&p_wkb, g_wkb);
    cudaGetSymbolAddress((void**)&p_wvb, g_wvb);

    cudaFuncSetAttribute(attn_k, cudaFuncAttributeMaxDynamicSharedMemorySize, ATTN_SMEM);
    cudaFuncSetAttribute(gemm_tc<true>,  cudaFuncAttributeMaxDynamicSharedMemorySize, GEMM_SMEM_S3);
    cudaFuncSetAttribute(gemm_tc<false>, cudaFuncAttributeMaxDynamicSharedMemorySize, GEMM_SMEM_S3);
    cudaFuncSetAttribute(gemm_bf<true>,  cudaFuncAttributeMaxDynamicSharedMemorySize, GEMM_SMEM_BF);
    cudaFuncSetAttribute(gemm_bf<false>, cudaFuncAttributeMaxDynamicSharedMemorySize, GEMM_SMEM_BF);

    // ---- tf32 weight round + transpose (5 weights, one launch) ----
    {
        WTab wt;
        const float* srcs[5] = {W_in, W_out, W_qkv, W_cproj, W_rec};
        int offs[5] = {OW_IN, OW_OUT, OW_QKV, OW_CPROJ, OW_REC};
        int Ks[5]   = {DM, DI, DM, DM, DM};
        int Ns[5]   = {ZXB, DM, QKVD, DM, DM};
        int acc = 0;
        for (int i = 0; i < 5; i++) {
            wt.src[i] = srcs[i]; wt.off[i] = offs[i]; wt.K[i] = Ks[i]; wt.N[i] = Ns[i];
            wt.tstart[i] = acc;
            acc += (Ks[i] >> 5) * (Ns[i] >> 5);
        }
        wt.tstart[5] = acc;
        cvtall_k<<<acc, dim3(32, 8)>>>(wt);
    }
    // ---- bf16 weight round + transpose (FFN pair) ----
    cvtbf_k<<<dim3(FFND / 32, DM / 32), dim3(32, 8)>>>(W_key, p_wkb, DM, FFND);
    cvtbf_k<<<dim3(DM / 32, FFND / 32), dim3(32, 8)>>>(W_val, p_wvb, FFND, DM);

    // ---- Mamba2-style block ----
    rmsnorm_k<<<BT, 256>>>(x, p_h, 1e-6f, 1);
    run_gemm(p_h, p_wt + OW_IN, p_zxb, BT, ZXB, DM, nullptr, nullptr, 0, p_sk);
    conv_silu_k<<<(BT / CTB) * (XBCD / 256), 256>>>(conv_w, conv_b, dt_bias, A_log);
    scan_k<<<128, 512>>>();
    gate_k<<<BT, 256>>>(Dm, mnorm_w);
    run_gemm(p_y2, p_wt + OW_OUT, p_x2, BT, DM, DI, x, nullptr, 1, p_sk);

    // ---- attention block ----
    rmsnorm_k<<<BT, 256>>>(p_x2, p_h, 1e-6f, 1);
    run_gemm(p_h, p_wt + OW_QKV, p_qkv, BT, QKVD, DM, nullptr, nullptr, 0, p_sk);
    convqkv_k<<<(BT / CTB) * 5, 256>>>(qconv_w, qconv_b, kconv_w, kconv_b, vconv_w, vconv_b);
    attn_k<<<BSZ * NHA * (TT / 64), 128, ATTN_SMEM>>>();
    run_gemm(p_att, p_wt + OW_CPROJ, p_x3, BT, DM, DM, p_x2, nullptr, 1, p_sk);

    // ---- channel mix ----
    rmsshift_k<<<BT, 256>>>(p_x3, tmk, tmr, p_xkb, p_xr);
    // kf = relu^2(xk @ W_key) in bf16 (wide-N, no split)
    gemm_bf<false><<<dim3(FFND / 128, BT / 128), 256, GEMM_SMEM_BF>>>(
        p_xkb, p_wkb, nullptr, p_kfb, BT, FFND, DM, 2);
    // kv = kf @ W_val (split-K, fp32 partials + combine)
    {
        dim3 grid(DM / 128, BT / 128, 2);
        gemm_bf<true><<<grid, 256, GEMM_SMEM_BF>>>(p_kfb, p_wvb, p_sk, nullptr, BT, DM, FFND, 0);
        int MN = BT * DM;
        combine_k<<<(MN / 2 + 255) / 256, 256>>>(p_sk, p_kv, nullptr, nullptr, 0, MN);
    }
    run_gemm(p_xr, p_wt + OW_REC, out, BT, DM, DM, p_x3, p_kv, 3, p_sk);
}

// round 17
// speedup vs baseline: 1.2479x; 1.1319x over previous
#include <cuda_runtime.h>
#include <cuda_bf16.h>
#include <math.h>
#include <stdint.h>

#define BSZ 2
#define TT 1024
#define DM 1024
#define DI 2048
#define DS 128
#define NH 32
#define HDS 64
#define NHA 16
#define HDA 64
#define FFND 4096
#define ZXB 4384
#define XBCD 2304
#define QKVD 1152
#define BT (BSZ*TT)

// ---------------- scratch (device globals; no allocations allowed) ----------------
__device__ float g_h[BT*DM];
__device__ float g_zxb[BT*ZXB];
__device__ float g_xBC[BT*XBCD];
__device__ float g_dt[BT*NH];
__device__ float g_dA[BT*NH];
__device__ float g_yp[4*BT*DI];           // scan partials (n-split 4)
__device__ float g_y2[BT*DI];
__device__ float g_x2[BT*DM];
__device__ float g_qkv[BT*QKVD];
__device__ float g_qc[BT*DM];
__device__ float g_kc[BT*HDA];
__device__ float g_vc[BT*HDA];
__device__ float g_att[BT*DM];
__device__ float g_x3[BT*DM];
__device__ float g_xr[BT*DM];
__device__ float g_kv[BT*DM];
__device__ float g_wt[5373952];           // tf32-rounded TRANSPOSED weights [N][K]
__device__ float g_sk[2*BT*QKVD];         // split-K partial sums
__device__ __nv_bfloat16 g_xkb[BT*DM];    // xk in bf16
__device__ __nv_bfloat16 g_kfb[BT*FFND];  // kf in bf16
__device__ __nv_bfloat16 g_wkb[DM*FFND];  // W_key^T bf16 [N][K]
__device__ __nv_bfloat16 g_wvb[FFND*DM];  // W_val^T bf16 [N][K]

// tf32 weight offsets in g_wt
#define OW_IN_UNUSED 0
#define OW_OUT   0
#define OW_QKV   2097152
#define OW_CPROJ 3276800
#define OW_REC   4325376
// (W_in stays tf32 but large; stored in g_sk-sized scratch? No: keep dedicated)
__device__ float g_wtin[ZXB*DM];          // W_in^T tf32 [N][K]

// ---------------- helpers ----------------
__device__ __forceinline__ uint32_t f2tf32(float x) {
    uint32_t r; asm("cvt.rna.tf32.f32 %0, %1;" : "=r"(r) : "f"(x)); return r;
}
__device__ __forceinline__ float tf32r(float x) { return __uint_as_float(f2tf32(x)); }

__device__ __forceinline__ float block_sum(float v) {
    __shared__ float red[32];
    int lane = threadIdx.x & 31, w = threadIdx.x >> 5;
    #pragma unroll
    for (int o = 16; o; o >>= 1) v += __shfl_xor_sync(0xffffffffu, v, o);
    if (lane == 0) red[w] = v;
    __syncthreads();
    int nw = blockDim.x >> 5;
    float r = (threadIdx.x < nw) ? red[threadIdx.x] : 0.f;
    if (w == 0) {
        #pragma unroll
        for (int o = 16; o; o >>= 1) r += __shfl_xor_sync(0xffffffffu, r, o);
        if (lane == 0) red[0] = r;
    }
    __syncthreads();
    return red[0];
}

__global__ void rmsnorm_k(const float* __restrict__ x, float* __restrict__ o, float eps, int rnd) {
    int row = blockIdx.x;
    const float* xr = x + (size_t)row * DM;
    float ss = 0.f;
    for (int c = threadIdx.x; c < DM; c += blockDim.x) { float v = xr[c]; ss = fmaf(v, v, ss); }
    ss = block_sum(ss);
    float sc = rsqrtf(ss / (float)DM + eps);
    float* orow = o + (size_t)row * DM;
    if (rnd) for (int c = threadIdx.x; c < DM; c += blockDim.x) orow[c] = tf32r(xr[c] * sc);
    else     for (int c = threadIdx.x; c < DM; c += blockDim.x) orow[c] = xr[c] * sc;
}

// ---------------- fused rmsnorm + token-shift (channel mix); xk -> bf16, xr -> tf32 ----
__global__ void rmsshift_k(const float* __restrict__ x3,
                           const float* __restrict__ tmk, const float* __restrict__ tmr,
                           __nv_bfloat16* __restrict__ xk, float* __restrict__ xr) {
    int bt = blockIdx.x; int t = bt & 1023;
    const float* cur = x3 + (size_t)bt * DM;
    const float* prv = x3 + (size_t)(bt - 1) * DM;
    float sa = 0.f, sb = 0.f;
    for (int c = threadIdx.x; c < DM; c += blockDim.x) {
        float v = cur[c]; sa = fmaf(v, v, sa);
        float p = t ? prv[c] : 0.f; sb = fmaf(p, p, sb);
    }
    float ra = block_sum(sa);
    __syncthreads();
    float rb = block_sum(sb);
    float scc = rsqrtf(ra / (float)DM + 1e-6f);
    float scp = rsqrtf(rb / (float)DM + 1e-6f);
    for (int c = threadIdx.x; c < DM; c += blockDim.x) {
        float h = cur[c] * scc;
        float hp = t ? prv[c] * scp : 0.f;
        float dd = hp - h;
        xk[(size_t)bt * DM + c] = __float2bfloat16(fmaf(dd, tmk[c], h));
        xr[(size_t)bt * DM + c] = tf32r(fmaf(dd, tmr[c], h));
    }
}

// ---------------- tf32 weight round + transpose (5 weights incl W_in, one launch) ----
struct WTab {
    const float* src[5];
    float* dst[5];
    int K[5], N[5];
    int tstart[6];
};
__global__ void cvtall_k(WTab wt) {
    __shared__ float t[32][33];
    int bidx = blockIdx.x;
    int w = 0;
    #pragma unroll
    for (int i = 1; i < 5; i++) if (bidx >= wt.tstart[i]) w = i;
    int tloc = bidx - wt.tstart[w];
    int K = wt.K[w], N = wt.N[w];
    int ntn = N >> 5;
    int k0 = (tloc / ntn) << 5, n0 = (tloc % ntn) << 5;
    const float* in = wt.src[w];
    float* out = wt.dst[w];
    int x = threadIdx.x, y = threadIdx.y;
    #pragma unroll
    for (int i = 0; i < 32; i += 8)
        t[y + i][x] = tf32r(in[(size_t)(k0 + y + i) * N + n0 + x]);
    __syncthreads();
    #pragma unroll
    for (int i = 0; i < 32; i += 8)
        out[(size_t)(n0 + y + i) * K + k0 + x] = t[x][y + i];
}

// ---------------- bf16 weight round + transpose ----------------
__global__ void cvtbf_k(const float* __restrict__ in, __nv_bfloat16* __restrict__ out, int K, int N) {
    __shared__ float t[32][33];
    int k0 = blockIdx.y * 32, n0 = blockIdx.x * 32;
    int x = threadIdx.x, y = threadIdx.y;
    #pragma unroll
    for (int i = 0; i < 32; i += 8)
        t[y + i][x] = in[(size_t)(k0 + y + i) * N + n0 + x];
    __syncthreads();
    #pragma unroll
    for (int i = 0; i < 32; i += 8)
        out[(size_t)(n0 + y + i) * K + k0 + x] = __float2bfloat16(t[x][y + i]);
}

// ================= shared GEMM macros =================
#define CP_ASYNC16(dst, src, sz) \
    asm volatile("cp.async.cg.shared.global [%0], [%1], 16, %2;" :: "r"(dst), "l"(src), "r"(sz) : "memory")
#define CP_COMMIT() asm volatile("cp.async.commit_group;" ::: "memory")
#define CP_WAIT_N(n) asm volatile("cp.async.wait_group %0;" :: "n"(n) : "memory")
#define MMA_TF32(d, a, b) \
    asm volatile("mma.sync.aligned.m16n8k8.row.col.f32.tf32.tf32.f32 " \
        "{%0,%1,%2,%3}, {%4,%5,%6,%7}, {%8,%9}, {%0,%1,%2,%3};" \
        : "+f"((d)[0]), "+f"((d)[1]), "+f"((d)[2]), "+f"((d)[3]) \
        : "r"((a)[0]), "r"((a)[1]), "r"((a)[2]), "r"((a)[3]), "r"((b)[0]), "r"((b)[1]))
#define MMA_BF16(d, a, b) \
    asm volatile("mma.sync.aligned.m16n8k16.row.col.f32.bf16.bf16.f32 " \
        "{%0,%1,%2,%3}, {%4,%5,%6,%7}, {%8,%9}, {%0,%1,%2,%3};" \
        : "+f"((d)[0]), "+f"((d)[1]), "+f"((d)[2]), "+f"((d)[3]) \
        : "r"((a)[0]), "r"((a)[1]), "r"((a)[2]), "r"((a)[3]), "r"((b)[0]), "r"((b)[1]))
#define LDMX4(r0, r1, r2, r3, a) \
    asm volatile("ldmatrix.sync.aligned.m8n8.x4.shared.b16 {%0,%1,%2,%3}, [%4];" \
        : "=r"(r0), "=r"(r1), "=r"(r2), "=r"(r3) : "r"(a))

// ================= tf32 GEMM (ldmatrix, 3-stage, optional split-K) =================
template<bool SPLITK>
__global__ void __launch_bounds__(256, 2) gemm_tc(const float* __restrict__ A, const float* __restrict__ Bt,
                                                  float* __restrict__ C, int M, int N, int K,
                                                  const float* __restrict__ res, const float* __restrict__ mul, int epi)
{
    extern __shared__ float gs[];
    float (*As)[36] = (float(*)[36])gs;
    float (*Bs)[36] = (float(*)[36])(gs + 3*128*36);
    int tid = threadIdx.x;
    int m0 = blockIdx.y * 128, n0 = blockIdx.x * 128;
    int kz = SPLITK ? blockIdx.z : 0;
    int Keff = SPLITK ? (K >> 1) : K;
    int kzoff = kz * Keff;
    int w = tid >> 5, lane = tid & 31;
    int wm = (w >> 2) * 64;
    int wn = (w & 3) * 32;

    float acc[4][4][4];
    #pragma unroll
    for (int mi = 0; mi < 4; mi++)
        #pragma unroll
        for (int ni = 0; ni < 4; ni++)
            #pragma unroll
            for (int e = 0; e < 4; e++) acc[mi][ni][e] = 0.f;

    const int NC = Keff >> 5;

    auto fill = [&](int buf, int k0) {
        #pragma unroll
        for (int i = 0; i < 4; i++) {
            int task = tid + i * 256;
            int r = task >> 3, q = (task & 7) * 4;
            const float* src = A + (size_t)(m0 + r) * K + k0 + q;
            uint32_t dst = (uint32_t)__cvta_generic_to_shared(&As[buf * 128 + r][q]);
            CP_ASYNC16(dst, src, 16);
        }
        #pragma unroll
        for (int i = 0; i < 4; i++) {
            int task = tid + i * 256;
            int r = task >> 3, q = (task & 7) * 4;
            int ok = (n0 + r) < N;
            const float* src = Bt + (size_t)(n0 + r) * K + k0 + q;
            uint32_t dst = (uint32_t)__cvta_generic_to_shared(&Bs[buf * 128 + r][q]);
            CP_ASYNC16(dst, src, ok ? 16 : 0);
        }
    };

    fill(0, kzoff);      CP_COMMIT();
    fill(1, kzoff + 32); CP_COMMIT();

    int g = lane >> 3, lr8 = lane & 7;
    int arow_l = wm + (g & 1) * 8 + lr8;
    int acol_l = (g >> 1) * 4;
    int brow_l = wn + (g >> 1) * 8 + lr8;
    int bcol_l = (g & 1) * 4;

    int buf = 0;
    for (int ct = 0; ct < NC; ct++) {
        CP_WAIT_N(1);
        __syncthreads();

        const float (*as)[36] = &As[buf * 128];
        const float (*bs)[36] = &Bs[buf * 128];
        #pragma unroll
        for (int ks = 0; ks < 4; ks++) {
            int kb = ks * 8;
            uint32_t af[4][4];
            #pragma unroll
            for (int mi = 0; mi < 4; mi++) {
                uint32_t a = (uint32_t)__cvta_generic_to_shared(&as[arow_l + mi * 16][acol_l + kb]);
                LDMX4(af[mi][0], af[mi][1], af[mi][2], af[mi][3], a);
            }
            uint32_t bf[4][2];
            #pragma unroll
            for (int p = 0; p < 2; p++) {
                uint32_t a = (uint32_t)__cvta_generic_to_shared(&bs[brow_l + p * 16][bcol_l + kb]);
                LDMX4(bf[2*p][0], bf[2*p][1], bf[2*p+1][0], bf[2*p+1][1], a);
            }
            #pragma unroll
            for (int mi = 0; mi < 4; mi++)
                #pragma unroll
                for (int ni = 0; ni < 4; ni++)
                    MMA_TF32(acc[mi][ni], af[mi], bf[ni]);
        }

        int nx = ct + 2;
        if (nx < NC) fill(nx % 3, kzoff + nx * 32);
        CP_COMMIT();
        if (++buf == 3) buf = 0;
    }

    float* Co = SPLITK ? (C + (size_t)kz * M * N) : C;
    #pragma unroll
    for (int mi = 0; mi < 4; mi++) {
        int r0 = m0 + wm + mi * 16 + (lane >> 2);
        #pragma unroll
        for (int ni = 0; ni < 4; ni++) {
            int c = n0 + wn + ni * 8 + (lane & 3) * 2;
            if (c < N) {
                #pragma unroll
                for (int half = 0; half < 2; half++) {
                    int r = r0 + half * 8;
                    size_t idx = (size_t)r * N + c;
                    float v0 = acc[mi][ni][half * 2 + 0];
                    float v1 = acc[mi][ni][half * 2 + 1];
                    if (!SPLITK) {
                        if (epi == 1) {
                            v0 += res[idx]; v1 += res[idx + 1];
                        } else if (epi == 3) {
                            v0 = res[idx]     + mul[idx]     / (1.f + expf(-v0));
                            v1 = res[idx + 1] + mul[idx + 1] / (1.f + expf(-v1));
                        }
                    }
                    Co[idx] = v0; Co[idx + 1] = v1;
                }
            }
        }
    }
}
#define GEMM_SMEM_S3 110592

// ================= bf16 GEMM (m16n8k16, ldmatrix, 3-stage, optional split-K) =========
template<bool SPLITK>
__global__ void __launch_bounds__(256, 2) gemm_bf(const __nv_bfloat16* __restrict__ A,
                                                  const __nv_bfloat16* __restrict__ Bt,
                                                  float* __restrict__ C, __nv_bfloat16* __restrict__ Cb,
                                                  int M, int N, int K, int epi)
{
    extern __shared__ __nv_bfloat16 gb[];
    __nv_bfloat16 (*As)[40] = (__nv_bfloat16(*)[40])gb;
    __nv_bfloat16 (*Bs)[40] = (__nv_bfloat16(*)[40])(gb + 3*128*40);
    int tid = threadIdx.x;
    int m0 = blockIdx.y * 128, n0 = blockIdx.x * 128;
    int kz = SPLITK ? blockIdx.z : 0;
    int Keff = SPLITK ? (K >> 1) : K;
    int kzoff = kz * Keff;
    int w = tid >> 5, lane = tid & 31;
    int wm = (w >> 2) * 64;
    int wn = (w & 3) * 32;

    float acc[4][4][4];
    #pragma unroll
    for (int mi = 0; mi < 4; mi++)
        #pragma unroll
        for (int ni = 0; ni < 4; ni++)
            #pragma unroll
            for (int e = 0; e < 4; e++) acc[mi][ni][e] = 0.f;

    const int NC = Keff >> 5;

    auto fill = [&](int buf, int k0) {
        #pragma unroll
        for (int i = 0; i < 2; i++) {
            int task = tid + i * 256;
            int r = task >> 2, q = (task & 3) * 8;
            const __nv_bfloat16* src = A + (size_t)(m0 + r) * K + k0 + q;
            uint32_t dst = (uint32_t)__cvta_generic_to_shared(&As[buf * 128 + r][q]);
            CP_ASYNC16(dst, src, 16);
        }
        #pragma unroll
        for (int i = 0; i < 2; i++) {
            int task = tid + i * 256;
            int r = task >> 2, q = (task & 3) * 8;
            int ok = (n0 + r) < N;
            const __nv_bfloat16* src = Bt + (size_t)(n0 + r) * K + k0 + q;
            uint32_t dst = (uint32_t)__cvta_generic_to_shared(&Bs[buf * 128 + r][q]);
            CP_ASYNC16(dst, src, ok ? 16 : 0);
        }
    };

    fill(0, kzoff);      CP_COMMIT();
    fill(1, kzoff + 32); CP_COMMIT();

    int g = lane >> 3, lr8 = lane & 7;

    int buf = 0;
    for (int ct = 0; ct < NC; ct++) {
        CP_WAIT_N(1);
        __syncthreads();

        const __nv_bfloat16 (*as)[40] = &As[buf * 128];
        const __nv_bfloat16 (*bs)[40] = &Bs[buf * 128];
        #pragma unroll
        for (int ks = 0; ks < 2; ks++) {
            int kb = ks * 16;
            uint32_t af[4][4];
            #pragma unroll
            for (int mi = 0; mi < 4; mi++) {
                int row = wm + mi * 16 + (g & 1) * 8 + lr8;
                int col = (g >> 1) * 8 + kb;
                uint32_t a = (uint32_t)__cvta_generic_to_shared(&as[row][col]);
                LDMX4(af[mi][0], af[mi][1], af[mi][2], af[mi][3], a);
            }
            uint32_t bf[4][2];
            #pragma unroll
            for (int p = 0; p < 2; p++) {
                int row = wn + p * 16 + (g >> 1) * 8 + lr8;
                int col = (g & 1) * 8 + kb;
                uint32_t a = (uint32_t)__cvta_generic_to_shared(&bs[row][col]);
                LDMX4(bf[2*p][0], bf[2*p][1], bf[2*p+1][0], bf[2*p+1][1], a);
            }
            #pragma unroll
            for (int mi = 0; mi < 4; mi++)
                #pragma unroll
                for (int ni = 0; ni < 4; ni++)
                    MMA_BF16(acc[mi][ni], af[mi], bf[ni]);
        }

        int nx = ct + 2;
        if (nx < NC) fill(nx % 3, kzoff + nx * 32);
        CP_COMMIT();
        if (++buf == 3) buf = 0;
    }

    float* Co = SPLITK ? (C + (size_t)kz * M * N) : C;
    #pragma unroll
    for (int mi = 0; mi < 4; mi++) {
        int r0 = m0 + wm + mi * 16 + (lane >> 2);
        #pragma unroll
        for (int ni = 0; ni < 4; ni++) {
            int c = n0 + wn + ni * 8 + (lane & 3) * 2;
            if (c < N) {
                #pragma unroll
                for (int half = 0; half < 2; half++) {
                    int r = r0 + half * 8;
                    size_t idx = (size_t)r * N + c;
                    float v0 = acc[mi][ni][half * 2 + 0];
                    float v1 = acc[mi][ni][half * 2 + 1];
                    if (epi == 2) {
                        v0 = fmaxf(v0, 0.f); v0 = v0 * v0;
                        v1 = fmaxf(v1, 0.f); v1 = v1 * v1;
                        __nv_bfloat162 bv;
                        bv.x = __float2bfloat16(v0);
                        bv.y = __float2bfloat16(v1);
                        *(__nv_bfloat162*)(Cb + idx) = bv;
                    } else {
                        Co[idx] = v0; Co[idx + 1] = v1;
                    }
                }
            }
        }
    }
}
#define GEMM_SMEM_BF 61440

// ---------------- split-K combine + fused epilogue ----------------
__global__ void combine_k(const float* __restrict__ p, float* __restrict__ C,
                          const float* __restrict__ res, const float* __restrict__ mul,
                          int epi, int MN) {
    int i = (blockIdx.x * blockDim.x + threadIdx.x) * 2;
    if (i >= MN) return;
    float2 a = *(const float2*)(p + i);
    float2 b = *(const float2*)(p + MN + i);
    float v0 = a.x + b.x, v1 = a.y + b.y;
    if (epi == 1) {
        v0 += res[i]; v1 += res[i + 1];
    } else if (epi == 3) {
        v0 = res[i]     + mul[i]     / (1.f + expf(-v0));
        v1 = res[i + 1] + mul[i + 1] / (1.f + expf(-v1));
    }
    *(float2*)(C + i) = make_float2(v0, v1);
}

// ---------------- xBC causal depthwise conv (K=4) + silu + fused dt/dA ----------------
#define CTB 8
__global__ void conv_silu_k(const float* __restrict__ cw, const float* __restrict__ cb,
                            const float* __restrict__ dt_bias, const float* __restrict__ A_log) {
    int blk = blockIdx.x;
    int cblk = blk % (XBCD / 256);
    int tb = blk / (XBCD / 256);
    int b = tb / (TT / CTB);
    int t0 = (tb % (TT / CTB)) * CTB;
    int c = cblk * 256 + threadIdx.x;

    float w0 = cw[c*4], w1 = cw[c*4+1], w2 = cw[c*4+2], w3 = cw[c*4+3], bb = cb[c];
    float xm3 = (t0 >= 3) ? g_zxb[(size_t)(b * TT + t0 - 3) * ZXB + DI + c] : 0.f;
    float xm2 = (t0 >= 2) ? g_zxb[(size_t)(b * TT + t0 - 2) * ZXB + DI + c] : 0.f;
    float xm1 = (t0 >= 1) ? g_zxb[(size_t)(b * TT + t0 - 1) * ZXB + DI + c] : 0.f;
    #pragma unroll
    for (int j = 0; j < CTB; j++) {
        float x0 = g_zxb[(size_t)(b * TT + t0 + j) * ZXB + DI + c];
        float acc = bb;
        acc = fmaf(w0, xm3, acc); acc = fmaf(w1, xm2, acc);
        acc = fmaf(w2, xm1, acc); acc = fmaf(w3, x0, acc);
        acc = acc / (1.f + expf(-acc));
        g_xBC[(size_t)(b * TT + t0 + j) * XBCD + c] = acc;
        xm3 = xm2; xm2 = xm1; xm1 = x0;
    }
    if (cblk == 0) {
        int h = threadIdx.x & 31, j = threadIdx.x >> 5;
        int bt = b * TT + t0 + j;
        float v = g_zxb[(size_t)bt * ZXB + 4352 + h] + dt_bias[h];
        float sp = (v > 20.f) ? v : log1pf(expf(v));
        g_dt[bt * NH + h] = sp;
        g_dA[bt * NH + h] = expf(sp * (-expf(A_log[h])));
    }
}

// ---------------- SSM scan: 256 blocks = (b,h,n-split4), 512 threads ----------------
__global__ void scan_k() {
    int bid = blockIdx.x;
    int ns = bid & 3; int bh = bid >> 2; int b = bh >> 5; int h = bh & 31;
    int tid = threadIdx.x;
    int p = tid >> 3;        // 0..63
    int ng = tid & 7;        // 8 groups x 4 n = 32 n
    __shared__ float sB[16 * 32], sC[16 * 32], sX[16 * 64], sS[16];
    float s[4];
    #pragma unroll
    for (int j = 0; j < 4; j++) s[j] = 0.f;
    int nb = ns * 32;

    for (int ct = 0; ct < TT / 16; ct++) {
        int t0 = ct * 16;
        if (tid < 512) {
            int tt = tid >> 5; int n = tid & 31;
            int base = b * TT + t0 + tt;
            sB[tid] = g_xBC[(size_t)base * XBCD + DI + nb + n];
            sC[tid] = g_xBC[(size_t)base * XBCD + DI + DS + nb + n];
        }
        #pragma unroll
        for (int l = 0; l < 2; l++) {
            int e = tid + l * 512; int tt = e >> 6; int n = e & 63;
            int base = b * TT + t0 + tt;
            sX[e] = g_xBC[(size_t)base * XBCD + h * 64 + n] * g_dt[base * NH + h];
        }
        if (tid < 16) sS[tid] = g_dA[(b * TT + t0 + tid) * NH + h];
        __syncthreads();
        for (int tt = 0; tt < 16; tt++) {
            float da = sS[tt];
            float dtx = sX[tt * 64 + p];
            float bb[4], cc[4];
            *(float4*)&bb[0] = *(float4*)&sB[tt * 32 + ng * 4];
            *(float4*)&cc[0] = *(float4*)&sC[tt * 32 + ng * 4];
            float acc = 0.f;
            #pragma unroll
            for (int j = 0; j < 4; j++) {
                s[j] = fmaf(s[j], da, dtx * bb[j]);
                acc = fmaf(s[j], cc[j], acc);
            }
            acc += __shfl_xor_sync(0xffffffffu, acc, 1);
            acc += __shfl_xor_sync(0xffffffffu, acc, 2);
            acc += __shfl_xor_sync(0xffffffffu, acc, 4);
            if (ng == 0)
                g_yp[(size_t)ns * (BT * DI) + (size_t)(b * TT + t0 + tt) * DI + h * 64 + p] = acc;
        }
        __syncthreads();
    }
}

__global__ void gate_k(const float* __restrict__ Dm, const float* __restrict__ mnw) {
    int bt = blockIdx.x;
    float ss = 0.f;
    for (int c = threadIdx.x; c < DI; c += blockDim.x) {
        float v = (g_yp[(size_t)bt * DI + c] + g_yp[(size_t)(BT * DI) + (size_t)bt * DI + c])
                + (g_yp[2*(size_t)(BT * DI) + (size_t)bt * DI + c] + g_yp[3*(size_t)(BT * DI) + (size_t)bt * DI + c])
                + g_xBC[(size_t)bt * XBCD + c] * Dm[c >> 6];
        float z = g_zxb[(size_t)bt * ZXB + c];
        v *= z / (1.f + expf(-z));
        g_y2[(size_t)bt * DI + c] = v;
        ss = fmaf(v, v, ss);
    }
    ss = block_sum(ss);
    float sc = rsqrtf(ss / (float)DI + 1e-5f);
    for (int c = threadIdx.x; c < DI; c += blockDim.x)
        g_y2[(size_t)bt * DI + c] = tf32r(g_y2[(size_t)bt * DI + c] * sc * mnw[c]);
}

// ---------------- q/k/v causal depthwise conv (K=3), channel-slab blocking -----------
__global__ void convqkv_k(const float* __restrict__ qw, const float* __restrict__ qb,
                          const float* __restrict__ kw, const float* __restrict__ kb,
                          const float* __restrict__ vw, const float* __restrict__ vb) {
    int blk = blockIdx.x;
    int cblk = blk % 5;
    int tb = blk / 5;
    int b = tb / (TT / CTB);
    int t0 = (tb % (TT / CTB)) * CTB;
    int c = cblk * 256 + threadIdx.x;
    if (c >= QKVD) return;

    const float* w; const float* bias; int d;
    if (c < DM)            { d = c & 63;        w = qw; bias = qb; }
    else if (c < DM + 64)  { d = c - DM;        w = kw; bias = kb; }
    else                   { d = c - DM - 64;   w = vw; bias = vb; }
    float w0 = w[d*3], w1 = w[d*3+1], w2 = w[d*3+2], bb = bias[d];
    float xm2 = (t0 >= 2) ? g_qkv[(size_t)(b * TT + t0 - 2) * QKVD + c] : 0.f;
    float xm1 = (t0 >= 1) ? g_qkv[(size_t)(b * TT + t0 - 1) * QKVD + c] : 0.f;
    #pragma unroll
    for (int j = 0; j < CTB; j++) {
        int bt = b * TT + t0 + j;
        float x0 = g_qkv[(size_t)bt * QKVD + c];
        float acc = bb;
        acc = fmaf(w0, xm2, acc); acc = fmaf(w1, xm1, acc); acc = fmaf(w2, x0, acc);
        if (c < DM)           g_qc[(size_t)bt * DM + c] = acc;
        else if (c < DM + 64) g_kc[(size_t)bt * 64 + d] = acc;
        else                  g_vc[(size_t)bt * 64 + d] = acc;
        xm2 = xm1; xm1 = x0;
    }
}

// ---------------- fused causal attention (tf32 mma, online softmax) ----------------
#define ATTN_SMEM 69632
__global__ void __launch_bounds__(128) attn_k() {
    extern __shared__ float sm[];
    float* qs = sm;
    float* ks = sm + 4352;
    float* vT = sm + 8704;
    float* ps = sm + 13056;
    int bid = blockIdx.x;
    int qb = 15 - (bid & 15); int h = (bid >> 4) & 15; int b = bid >> 8;
    int tid = threadIdx.x;
    int w = tid >> 5, lane = tid & 31;
    int lr = lane >> 2, lc = lane & 3;

    {
        int r = tid >> 1, d0 = (tid & 1) * 32;
        const float* qp = &g_qc[(size_t)(b * TT + qb * 64 + r) * DM + h * 64 + d0];
        #pragma unroll
        for (int j = 0; j < 8; j++) {
            float4 v = *(const float4*)(qp + j * 4);
            *(float4*)&qs[r * 68 + d0 + j * 4] =
                make_float4(tf32r(v.x * 0.125f), tf32r(v.y * 0.125f),
                            tf32r(v.z * 0.125f), tf32r(v.w * 0.125f));
        }
    }

    float m[2] = {-1e30f, -1e30f}, l[2] = {0.f, 0.f};
    float o[8][4];
    #pragma unroll
    for (int ni = 0; ni < 8; ni++)
        #pragma unroll
        for (int e = 0; e < 4; e++) o[ni][e] = 0.f;

    for (int kb = 0; kb <= qb; kb++) {
        __syncthreads();
        {
            int r = tid >> 1, d0 = (tid & 1) * 32;
            const float* kp = &g_kc[(size_t)(b * TT + kb * 64 + r) * 64 + d0];
            const float* vp = &g_vc[(size_t)(b * TT + kb * 64 + r) * 64 + d0];
            #pragma unroll
            for (int j = 0; j < 8; j++) {
                float4 kv = *(const float4*)(kp + j * 4);
                *(float4*)&ks[r * 68 + d0 + j * 4] =
                    make_float4(tf32r(kv.x), tf32r(kv.y), tf32r(kv.z), tf32r(kv.w));
                float4 vv = *(const float4*)(vp + j * 4);
                int d = d0 + j * 4;
                vT[(d + 0) * 68 + r] = tf32r(vv.x); vT[(d + 1) * 68 + r] = tf32r(vv.y);
                vT[(d + 2) * 68 + r] = tf32r(vv.z); vT[(d + 3) * 68 + r] = tf32r(vv.w);
            }
        }
        __syncthreads();

        float sc[8][4];
        #pragma unroll
        for (int ni = 0; ni < 8; ni++)
            #pragma unroll
            for (int e = 0; e < 4; e++) sc[ni][e] = 0.f;
        #pragma unroll
        for (int ksx = 0; ksx < 8; ksx++) {
            int k8 = ksx * 8;
            int r = w * 16 + lr;
            uint32_t af[4];
            af[0] = __float_as_uint(qs[r * 68 + k8 + lc]);
            af[1] = __float_as_uint(qs[(r + 8) * 68 + k8 + lc]);
            af[2] = __float_as_uint(qs[r * 68 + k8 + lc + 4]);
            af[3] = __float_as_uint(qs[(r + 8) * 68 + k8 + lc + 4]);
            #pragma unroll
            for (int ni = 0; ni < 8; ni++) {
                int n = ni * 8 + lr;
                uint32_t bf[2];
                bf[0] = __float_as_uint(ks[n * 68 + k8 + lc]);
                bf[1] = __float_as_uint(ks[n * 68 + k8 + lc + 4]);
                MMA_TF32(sc[ni], af, bf);
            }
        }

        bool diag = (kb == qb);
        #pragma unroll
        for (int h2 = 0; h2 < 2; h2++) {
            int row = w * 16 + lr + h2 * 8;
            if (diag) {
                #pragma unroll
                for (int ni = 0; ni < 8; ni++) {
                    int c0 = ni * 8 + lc * 2;
                    if (c0 > row)     sc[ni][h2 * 2 + 0] = -1e30f;
                    if (c0 + 1 > row) sc[ni][h2 * 2 + 1] = -1e30f;
                }
            }
            float mx = -1e30f;
            #pragma unroll
            for (int ni = 0; ni < 8; ni++)
                mx = fmaxf(mx, fmaxf(sc[ni][h2 * 2], sc[ni][h2 * 2 + 1]));
            mx = fmaxf(mx, __shfl_xor_sync(0xffffffffu, mx, 1));
            mx = fmaxf(mx, __shfl_xor_sync(0xffffffffu, mx, 2));
            float mn = fmaxf(m[h2], mx);
            float alpha = __expf(m[h2] - mn);
            m[h2] = mn;
            float rs = 0.f;
            #pragma unroll
            for (int ni = 0; ni < 8; ni++) {
                float p0 = __expf(sc[ni][h2 * 2]     - mn);
                float p1 = __expf(sc[ni][h2 * 2 + 1] - mn);
                rs += p0 + p1;
                *(float2*)&ps[row * 68 + ni * 8 + lc * 2] = make_float2(tf32r(p0), tf32r(p1));
            }
            rs += __shfl_xor_sync(0xffffffffu, rs, 1);
            rs += __shfl_xor_sync(0xffffffffu, rs, 2);
            l[h2] = l[h2] * alpha + rs;
            #pragma unroll
            for (int ni = 0; ni < 8; ni++) {
                o[ni][h2 * 2]     *= alpha;
                o[ni][h2 * 2 + 1] *= alpha;
            }
        }
        __syncwarp();

        #pragma unroll
        for (int ksx = 0; ksx < 8; ksx++) {
            int k8 = ksx * 8;
            int r = w * 16 + lr;
            uint32_t af[4];
            af[0] = __float_as_uint(ps[r * 68 + k8 + lc]);
            af[1] = __float_as_uint(ps[(r + 8) * 68 + k8 + lc]);
            af[2] = __float_as_uint(ps[r * 68 + k8 + lc + 4]);
            af[3] = __float_as_uint(ps[(r + 8) * 68 + k8 + lc + 4]);
            #pragma unroll
            for (int ni = 0; ni < 8; ni++) {
                int n = ni * 8 + lr;
                uint32_t bf[2];
                bf[0] = __float_as_uint(vT[n * 68 + k8 + lc]);
                bf[1] = __float_as_uint(vT[n * 68 + k8 + lc + 4]);
                MMA_TF32(o[ni], af, bf);
            }
        }
    }

    #pragma unroll
    for (int h2 = 0; h2 < 2; h2++) {
        float inv = 1.f / l[h2];
        int r = qb * 64 + w * 16 + lr + h2 * 8;
        #pragma unroll
        for (int ni = 0; ni < 8; ni++) {
            float2 v = make_float2(tf32r(o[ni][h2 * 2] * inv), tf32r(o[ni][h2 * 2 + 1] * inv));
            *(float2*)&g_att[(size_t)(b * TT + r) * DM + h * 64 + ni * 8 + lc * 2] = v;
        }
    }
}

// ---------------- host launch ----------------
static void run_gemm(const float* A, const float* Wt, float* C, int M, int N, int K,
                     const float* res, const float* mul, int epi, float* skbuf) {
    if (N <= 1536) {
        dim3 grid((N + 127) / 128, M / 128, 2);
        gemm_tc<true><<<grid, 256, GEMM_SMEM_S3>>>(A, Wt, skbuf, M, N, K, nullptr, nullptr, 0);
        int MN = M * N;
        combine_k<<<(MN / 2 + 255) / 256, 256>>>(skbuf, C, res, mul, epi, MN);
    } else {
        dim3 grid((N + 127) / 128, M / 128);
        gemm_tc<false><<<grid, 256, GEMM_SMEM_S3>>>(A, Wt, C, M, N, K, res, mul, epi);
    }
}

extern "C" void kernel_launch(void* const* d_in, const int* in_sizes, int n_in,
                              void* d_out, int out_size) {
    const float* x       = (const float*)d_in[0];
    const float* W_in    = (const float*)d_in[1];
    const float* conv_w  = (const float*)d_in[2];
    const float* conv_b  = (const float*)d_in[3];
    const float* A_log   = (const float*)d_in[4];
    const float* Dm      = (const float*)d_in[5];
    const float* dt_bias = (const float*)d_in[6];
    const float* mnorm_w = (const float*)d_in[7];
    const float* W_out   = (const float*)d_in[8];
    const float* W_qkv   = (const float*)d_in[9];
    const float* W_cproj = (const float*)d_in[10];
    const float* qconv_w = (const float*)d_in[11];
    const float* qconv_b = (const float*)d_in[12];
    const float* kconv_w = (const float*)d_in[13];
    const float* kconv_b = (const float*)d_in[14];
    const float* vconv_w = (const float*)d_in[15];
    const float* vconv_b = (const float*)d_in[16];
    const float* tmk     = (const float*)d_in[17];
    const float* tmr     = (const float*)d_in[18];
    const float* W_key   = (const float*)d_in[19];
    const float* W_rec   = (const float*)d_in[20];
    const float* W_val   = (const float*)d_in[21];
    float* out = (float*)d_out;

    float *p_h, *p_zxb, *p_y2, *p_x2, *p_qkv, *p_att, *p_x3, *p_xr, *p_kv, *p_wt, *p_wtin, *p_sk;
    __nv_bfloat16 *p_xkb, *p_kfb, *p_wkb, *p_wvb;
    cudaGetSymbolAddress((void**)&p_h, g_h);
    cudaGetSymbolAddress((void**)&p_zxb, g_zxb);
    cudaGetSymbolAddress((void**)&p_y2, g_y2);
    cudaGetSymbolAddress((void**)&p_x2, g_x2);
    cudaGetSymbolAddress((void**)&p_qkv, g_qkv);
    cudaGetSymbolAddress((void**)&p_att, g_att);
    cudaGetSymbolAddress((void**)&p_x3, g_x3);
    cudaGetSymbolAddress((void**)&p_xr, g_xr);
    cudaGetSymbolAddress((void**)&p_kv, g_kv);
    cudaGetSymbolAddress((void**)&p_wt, g_wt);
    cudaGetSymbolAddress((void**)&p_wtin, g_wtin);
    cudaGetSymbolAddress((void**)&p_sk, g_sk);
    cudaGetSymbolAddress((void**)&p_xkb, g_xkb);
    cudaGetSymbolAddress((void**)&p_kfb, g_kfb);
    cudaGetSymbolAddress((void**)&p_wkb, g_wkb);
    cudaGetSymbolAddress((void**)&p_wvb, g_wvb);

    cudaFuncSetAttribute(attn_k, cudaFuncAttributeMaxDynamicSharedMemorySize, ATTN_SMEM);
    cudaFuncSetAttribute(gemm_tc<true>,  cudaFuncAttributeMaxDynamicSharedMemorySize, GEMM_SMEM_S3);
    cudaFuncSetAttribute(gemm_tc<false>, cudaFuncAttributeMaxDynamicSharedMemorySize, GEMM_SMEM_S3);
    cudaFuncSetAttribute(gemm_bf<true>,  cudaFuncAttributeMaxDynamicSharedMemorySize, GEMM_SMEM_BF);
    cudaFuncSetAttribute(gemm_bf<false>, cudaFuncAttributeMaxDynamicSharedMemorySize, GEMM_SMEM_BF);

    // ---- tf32 weight round + transpose (W_in + 4 others, one launch) ----
    {
        WTab wt;
        const float* srcs[5] = {W_in, W_out, W_qkv, W_cproj, W_rec};
        float* dsts[5] = {p_wtin, p_wt + OW_OUT, p_wt + OW_QKV, p_wt + OW_CPROJ, p_wt + OW_REC};
        int Ks[5]   = {DM, DI, DM, DM, DM};
        int Ns[5]   = {ZXB, DM, QKVD, DM, DM};
        int acc = 0;
        for (int i = 0; i < 5; i++) {
            wt.src[i] = srcs[i]; wt.dst[i] = dsts[i]; wt.K[i] = Ks[i]; wt.N[i] = Ns[i];
            wt.tstart[i] = acc;
            acc += (Ks[i] >> 5) * (Ns[i] >> 5);
        }
        wt.tstart[5] = acc;
        cvtall_k<<<acc, dim3(32, 8)>>>(wt);
    }
    // ---- bf16 weight round + transpose (FFN pair only) ----
    cvtbf_k<<<dim3(FFND / 32, DM / 32), dim3(32, 8)>>>(W_key, p_wkb, DM, FFND);
    cvtbf_k<<<dim3(DM / 32, FFND / 32), dim3(32, 8)>>>(W_val, p_wvb, FFND, DM);

    // ---- Mamba2-style block ----
    rmsnorm_k<<<BT, 256>>>(x, p_h, 1e-6f, 1);
    {
        dim3 grid((ZXB + 127) / 128, BT / 128);
        gemm_tc<false><<<grid, 256, GEMM_SMEM_S3>>>(p_h, p_wtin, p_zxb, BT, ZXB, DM, nullptr, nullptr, 0);
    }
    conv_silu_k<<<(BT / CTB) * (XBCD / 256), 256>>>(conv_w, conv_b, dt_bias, A_log);
    scan_k<<<256, 512>>>();
    gate_k<<<BT, 256>>>(Dm, mnorm_w);
    run_gemm(p_y2, p_wt + OW_OUT, p_x2, BT, DM, DI, x, nullptr, 1, p_sk);

    // ---- attention block ----
    rmsnorm_k<<<BT, 256>>>(p_x2, p_h, 1e-6f, 1);
    run_gemm(p_h, p_wt + OW_QKV, p_qkv, BT, QKVD, DM, nullptr, nullptr, 0, p_sk);
    convqkv_k<<<(BT / CTB) * 5, 256>>>(qconv_w, qconv_b, kconv_w, kconv_b, vconv_w, vconv_b);
    attn_k<<<BSZ * NHA * (TT / 64), 128, ATTN_SMEM>>>();
    run_gemm(p_att, p_wt + OW_CPROJ, p_x3, BT, DM, DM, p_x2, nullptr, 1, p_sk);

    // ---- channel mix ----
    rmsshift_k<<<BT, 256>>>(p_x3, tmk, tmr, p_xkb, p_xr);
    gemm_bf<false><<<dim3(FFND / 128, BT / 128), 256, GEMM_SMEM_BF>>>(
        p_xkb, p_wkb, nullptr, p_kfb, BT, FFND, DM, 2);
    {
        dim3 grid(DM / 128, BT / 128, 2);
        gemm_bf<true><<<grid, 256, GEMM_SMEM_BF>>>(p_kfb, p_wvb, p_sk, nullptr, BT, DM, FFND, 0);
        int MN = BT * DM;
        combine_k<<<(MN / 2 + 255) / 256, 256>>>(p_sk, p_kv, nullptr, nullptr, 0, MN);
    }
    run_gemm(p_xr, p_wt + OW_REC, out, BT, DM, DM, p_x3, p_kv, 3, p_sk);
}